// round 1
// baseline (speedup 1.0000x reference)
#include <cuda_runtime.h>
#include <math.h>

// ---------------------------------------------------------------------------
// Problem dims: N=8, C=64, COUT=128, T=V=256, S=3, IC=32, P=T*V=65536
// ---------------------------------------------------------------------------
#define PP 65536

// ------------------------- packed parameters -------------------------------
__device__ float g_Wab[192 * 64];       // rows: [a0(32) b0(32) a1 b1 a2 b2] x C=64
__device__ float g_Bab[192];
__device__ float g_Wcrt[256 * 64];      // rows 0-127 cres_w, 128-255 rt_w
__device__ float g_Bcrt[256];
__device__ float g_Wd[128 * 192];       // [o][i*64+c] = wd[i][o][c]
__device__ float g_Bd[128];             // sum_i bd[i][o]
__device__ float g_WtT[1152 * 128];     // [k=(c*9+k9)][o] transposed tcn weights
__device__ float g_bnp[1024];           // 8 x 128: sg,hg, sc,hc, st,ht2, sr,hr

// ------------------------- scratch buffers ---------------------------------
__device__ float g_ab[100663296];       // [n][192][65536]       402 MB
__device__ float g_adapt[1572864];      // [i*8+n][t][s]         6.3 MB (scores -> adapt in place)
__device__ float g_xa[100663296];       // [(i*8+n)*64+c][v*256+s] 402 MB
__device__ float g_y[67108864];         // [n][128][65536]       268 MB
__device__ float g_crt[134217728];      // [n][256][65536]       536 MB (cres | rt)
__device__ float g_gcn[67108864];       // [n][128][65536]       268 MB

// ---------------------------------------------------------------------------
// pack kernel: reorganize weights, fold BN affine params
// ---------------------------------------------------------------------------
__global__ void pack_kernel(const float* __restrict__ wa, const float* __restrict__ ba,
                            const float* __restrict__ wb, const float* __restrict__ bb,
                            const float* __restrict__ wd, const float* __restrict__ bd,
                            const float* __restrict__ cres_w, const float* __restrict__ cres_b,
                            const float* __restrict__ rt_w, const float* __restrict__ rt_b,
                            const float* __restrict__ gcn_bn, const float* __restrict__ cres_bn,
                            const float* __restrict__ tcn_bn, const float* __restrict__ rt_bn,
                            const float* __restrict__ tcn_w, const float* __restrict__ tcn_b)
{
    int tid = blockIdx.x * blockDim.x + threadIdx.x;
    int nth = gridDim.x * blockDim.x;
    for (int idx = tid; idx < 192 * 64; idx += nth) {
        int o = idx >> 6, c = idx & 63;
        int i = o >> 6, sub = o & 63;
        g_Wab[idx] = (sub < 32) ? wa[(i * 32 + sub) * 64 + c]
                                : wb[(i * 32 + sub - 32) * 64 + c];
    }
    for (int o = tid; o < 192; o += nth) {
        int i = o >> 6, sub = o & 63;
        g_Bab[o] = (sub < 32) ? ba[i * 32 + sub] : bb[i * 32 + sub - 32];
    }
    for (int idx = tid; idx < 256 * 64; idx += nth) {
        int o = idx >> 6, c = idx & 63;
        g_Wcrt[idx] = (o < 128) ? cres_w[o * 64 + c] : rt_w[(o - 128) * 64 + c];
    }
    for (int o = tid; o < 256; o += nth)
        g_Bcrt[o] = (o < 128) ? cres_b[o] : rt_b[o - 128];
    for (int idx = tid; idx < 128 * 192; idx += nth) {
        int o = idx / 192, k = idx - o * 192;
        int i = k >> 6, c = k & 63;
        g_Wd[idx] = wd[(i * 128 + o) * 64 + c];
    }
    for (int o = tid; o < 128; o += nth)
        g_Bd[o] = bd[o] + bd[128 + o] + bd[256 + o];
    for (int idx = tid; idx < 1152 * 128; idx += nth) {
        int kk = idx >> 7, o = idx & 127;
        g_WtT[idx] = tcn_w[o * 1152 + kk];
    }
    for (int o = tid; o < 128; o += nth) {
        float g, b, m, v, s;
        g = gcn_bn[o]; b = gcn_bn[128 + o]; m = gcn_bn[256 + o]; v = gcn_bn[384 + o];
        s = g * rsqrtf(v + 1e-5f);
        g_bnp[o] = s; g_bnp[128 + o] = b - m * s;
        g = cres_bn[o]; b = cres_bn[128 + o]; m = cres_bn[256 + o]; v = cres_bn[384 + o];
        s = g * rsqrtf(v + 1e-5f);
        g_bnp[256 + o] = s; g_bnp[384 + o] = b - m * s;
        g = tcn_bn[o]; b = tcn_bn[128 + o]; m = tcn_bn[256 + o]; v = tcn_bn[384 + o];
        s = g * rsqrtf(v + 1e-5f);
        g_bnp[512 + o] = s; g_bnp[640 + o] = (tcn_b[o] - m) * s + b;   // tcn_b folded
        g = rt_bn[o]; b = rt_bn[128 + o]; m = rt_bn[256 + o]; v = rt_bn[384 + o];
        s = g * rsqrtf(v + 1e-5f);
        g_bnp[768 + o] = s; g_bnp[896 + o] = b - m * s;
    }
}

// ---------------------------------------------------------------------------
// conv1x1: out[n][o][p] = sum_c W[o][c] * x[n][c][p] + bias[o].  K=64.
// MODE 0: ab (M=192)   MODE 1: cres|rt (M=256)
// 64x64 tile, 256 threads, 4x4 frag.
// ---------------------------------------------------------------------------
template <int MODE>
__global__ __launch_bounds__(256) void conv1x1_kernel(const float* __restrict__ x)
{
    const int M = MODE ? 256 : 192;
    const float* __restrict__ W    = MODE ? g_Wcrt : g_Wab;
    const float* __restrict__ bias = MODE ? g_Bcrt : g_Bab;
    float* __restrict__ out        = MODE ? g_crt  : g_ab;

    int pBlk = blockIdx.x << 6;
    int oBlk = blockIdx.y << 6;
    int n    = blockIdx.z;
    __shared__ float As[16][68];
    __shared__ float Bs[16][68];
    int tid = threadIdx.x;
    int tx = tid & 15, ty = tid >> 4;
    int aRow = tid >> 2, kq = tid & 3;
    const float* xn = x + (size_t)n * 64 * PP;
    float acc[4][4] = {};

#pragma unroll
    for (int k0 = 0; k0 < 64; k0 += 16) {
        float4 av = *(const float4*)(W + (oBlk + aRow) * 64 + k0 + (kq << 2));
        As[(kq << 2) + 0][aRow] = av.x;
        As[(kq << 2) + 1][aRow] = av.y;
        As[(kq << 2) + 2][aRow] = av.z;
        As[(kq << 2) + 3][aRow] = av.w;
        *(float4*)&Bs[ty][tx << 2] =
            *(const float4*)(xn + (size_t)(k0 + ty) * PP + pBlk + (tx << 2));
        __syncthreads();
#pragma unroll
        for (int kk = 0; kk < 16; kk++) {
            float4 aF = *(const float4*)&As[kk][ty << 2];
            float4 bF = *(const float4*)&Bs[kk][tx << 2];
            float a_[4] = {aF.x, aF.y, aF.z, aF.w};
            float b_[4] = {bF.x, bF.y, bF.z, bF.w};
#pragma unroll
            for (int i = 0; i < 4; i++)
#pragma unroll
                for (int j = 0; j < 4; j++)
                    acc[i][j] += a_[i] * b_[j];
        }
        __syncthreads();
    }
    int oB = oBlk + (ty << 2), pB = pBlk + (tx << 2);
#pragma unroll
    for (int i = 0; i < 4; i++) {
        float bi = bias[oB + i];
        float4 r;
        r.x = acc[i][0] + bi; r.y = acc[i][1] + bi;
        r.z = acc[i][2] + bi; r.w = acc[i][3] + bi;
        *(float4*)(out + ((size_t)n * M + oB + i) * PP + pB) = r;
    }
}

// ---------------------------------------------------------------------------
// scores: scores[b][t][s] = (1/256) * sum_{c<32,v} a[b,c,t,v]*b[b,c,s,v]
// b = i*8+n.  K = 32*256. Written into g_adapt (softmax later, in place).
// ---------------------------------------------------------------------------
__global__ __launch_bounds__(256) void scores_kernel()
{
    int b = blockIdx.z;
    int i = b >> 3, n = b & 7;
    int sBlk = blockIdx.x << 6, tBlk = blockIdx.y << 6;
    const float* aBase = g_ab + ((size_t)n * 192 + i * 64) * PP;
    const float* bBase = aBase + (size_t)32 * PP;
    __shared__ float As[16][68];
    __shared__ float Bs[16][68];
    int tid = threadIdx.x;
    int tx = tid & 15, ty = tid >> 4;
    int r_ = tid >> 2, kq = tid & 3;
    float acc[4][4] = {};

    for (int c = 0; c < 32; c++) {
        const float* ac = aBase + (size_t)c * PP;
        const float* bc = bBase + (size_t)c * PP;
        for (int v0 = 0; v0 < 256; v0 += 16) {
            float4 av = *(const float4*)(ac + (tBlk + r_) * 256 + v0 + (kq << 2));
            As[(kq << 2) + 0][r_] = av.x;
            As[(kq << 2) + 1][r_] = av.y;
            As[(kq << 2) + 2][r_] = av.z;
            As[(kq << 2) + 3][r_] = av.w;
            float4 bv = *(const float4*)(bc + (sBlk + r_) * 256 + v0 + (kq << 2));
            Bs[(kq << 2) + 0][r_] = bv.x;
            Bs[(kq << 2) + 1][r_] = bv.y;
            Bs[(kq << 2) + 2][r_] = bv.z;
            Bs[(kq << 2) + 3][r_] = bv.w;
            __syncthreads();
#pragma unroll
            for (int kk = 0; kk < 16; kk++) {
                float4 aF = *(const float4*)&As[kk][ty << 2];
                float4 bF = *(const float4*)&Bs[kk][tx << 2];
                float a_[4] = {aF.x, aF.y, aF.z, aF.w};
                float b_[4] = {bF.x, bF.y, bF.z, bF.w};
#pragma unroll
                for (int ii = 0; ii < 4; ii++)
#pragma unroll
                    for (int jj = 0; jj < 4; jj++)
                        acc[ii][jj] += a_[ii] * b_[jj];
            }
            __syncthreads();
        }
    }
    float* scp = g_adapt + (size_t)b * PP;
    const float sc = 1.0f / 256.0f;
#pragma unroll
    for (int ii = 0; ii < 4; ii++) {
        float4 r;
        r.x = acc[ii][0] * sc; r.y = acc[ii][1] * sc;
        r.z = acc[ii][2] * sc; r.w = acc[ii][3] * sc;
        *(float4*)(scp + (tBlk + (ty << 2) + ii) * 256 + sBlk + (tx << 2)) = r;
    }
}

// ---------------------------------------------------------------------------
// softmax over t (dim -2) per column s, then adapt = mat_adj + adj_w + att.
// In place on g_adapt. One block per b=i*8+n, thread = column s.
// ---------------------------------------------------------------------------
__global__ __launch_bounds__(256) void softmax_kernel(const float* __restrict__ mat_adj,
                                                      const float* __restrict__ adj_w)
{
    int b = blockIdx.x;
    int i = b >> 3;
    float* sc = g_adapt + (size_t)b * PP;
    int s = threadIdx.x;
    float m = -1e30f;
    for (int t = 0; t < 256; t++) m = fmaxf(m, sc[t * 256 + s]);
    float sum = 0.f;
    for (int t = 0; t < 256; t++) sum += expf(sc[t * 256 + s] - m);
    float inv = 1.f / sum;
    const float* A1 = mat_adj + (size_t)i * PP;
    const float* A2 = adj_w + (size_t)i * PP;
    for (int t = 0; t < 256; t++) {
        int idx = t * 256 + s;
        sc[idx] = A1[idx] + A2[idx] + expf(sc[idx] - m) * inv;
    }
}

// ---------------------------------------------------------------------------
// xa[b2][v][s] = sum_t x[n,c,t,v] * adapt[bn,t,s];  b2 = bn*64+c, bn = i*8+n
// K = 256 (t). Both operands are k-major rows -> direct tile loads.
// ---------------------------------------------------------------------------
__global__ __launch_bounds__(256) void xa_kernel(const float* __restrict__ x)
{
    int b2 = blockIdx.z;
    int c = b2 & 63, bn = b2 >> 6;
    int n = bn & 7;
    int sBlk = blockIdx.x << 6, vBlk = blockIdx.y << 6;
    const float* xb = x + ((size_t)n * 64 + c) * PP;
    const float* ad = g_adapt + (size_t)bn * PP;
    __shared__ float As[16][68];
    __shared__ float Bs[16][68];
    int tid = threadIdx.x;
    int tx = tid & 15, ty = tid >> 4;
    float acc[4][4] = {};

    for (int k0 = 0; k0 < 256; k0 += 16) {
        *(float4*)&As[ty][tx << 2] =
            *(const float4*)(xb + (k0 + ty) * 256 + vBlk + (tx << 2));
        *(float4*)&Bs[ty][tx << 2] =
            *(const float4*)(ad + (k0 + ty) * 256 + sBlk + (tx << 2));
        __syncthreads();
#pragma unroll
        for (int kk = 0; kk < 16; kk++) {
            float4 aF = *(const float4*)&As[kk][ty << 2];
            float4 bF = *(const float4*)&Bs[kk][tx << 2];
            float a_[4] = {aF.x, aF.y, aF.z, aF.w};
            float b_[4] = {bF.x, bF.y, bF.z, bF.w};
#pragma unroll
            for (int ii = 0; ii < 4; ii++)
#pragma unroll
                for (int jj = 0; jj < 4; jj++)
                    acc[ii][jj] += a_[ii] * b_[jj];
        }
        __syncthreads();
    }
    float* op = g_xa + (size_t)b2 * PP;
#pragma unroll
    for (int ii = 0; ii < 4; ii++) {
        float4 r;
        r.x = acc[ii][0]; r.y = acc[ii][1]; r.z = acc[ii][2]; r.w = acc[ii][3];
        *(float4*)(op + (vBlk + (ty << 2) + ii) * 256 + sBlk + (tx << 2)) = r;
    }
}

// ---------------------------------------------------------------------------
// y[n][o][p] = sum_{k=(i,c)} Wd[o][k] * xa[(i*8+n)*64+c][p] + Bd[o].  M=128, K=192
// ---------------------------------------------------------------------------
__global__ __launch_bounds__(256) void ygemm_kernel()
{
    int pBlk = blockIdx.x << 6;
    int oBlk = blockIdx.y << 6;
    int n    = blockIdx.z;
    __shared__ float As[16][68];
    __shared__ float Bs[16][68];
    int tid = threadIdx.x;
    int tx = tid & 15, ty = tid >> 4;
    int aRow = tid >> 2, kq = tid & 3;
    float acc[4][4] = {};

    for (int k0 = 0; k0 < 192; k0 += 16) {
        float4 av = *(const float4*)(g_Wd + (oBlk + aRow) * 192 + k0 + (kq << 2));
        As[(kq << 2) + 0][aRow] = av.x;
        As[(kq << 2) + 1][aRow] = av.y;
        As[(kq << 2) + 2][aRow] = av.z;
        As[(kq << 2) + 3][aRow] = av.w;
        int k = k0 + ty;
        int i = k >> 6, cc = k & 63;
        *(float4*)&Bs[ty][tx << 2] =
            *(const float4*)(g_xa + (size_t)((i << 9) + (n << 6) + cc) * PP + pBlk + (tx << 2));
        __syncthreads();
#pragma unroll
        for (int kk = 0; kk < 16; kk++) {
            float4 aF = *(const float4*)&As[kk][ty << 2];
            float4 bF = *(const float4*)&Bs[kk][tx << 2];
            float a_[4] = {aF.x, aF.y, aF.z, aF.w};
            float b_[4] = {bF.x, bF.y, bF.z, bF.w};
#pragma unroll
            for (int ii = 0; ii < 4; ii++)
#pragma unroll
                for (int jj = 0; jj < 4; jj++)
                    acc[ii][jj] += a_[ii] * b_[jj];
        }
        __syncthreads();
    }
    int oB = oBlk + (ty << 2), pB = pBlk + (tx << 2);
#pragma unroll
    for (int ii = 0; ii < 4; ii++) {
        float bi = g_Bd[oB + ii];
        float4 r;
        r.x = acc[ii][0] + bi; r.y = acc[ii][1] + bi;
        r.z = acc[ii][2] + bi; r.w = acc[ii][3] + bi;
        *(float4*)(g_y + ((size_t)(n * 128) + oB + ii) * PP + pB) = r;
    }
}

// ---------------------------------------------------------------------------
// gcn = relu(bn_g(y) + bn_c(cres))   elementwise, raw-index add (T==V)
// ---------------------------------------------------------------------------
__global__ __launch_bounds__(256) void gcn_kernel()
{
    size_t i4 = (size_t)blockIdx.x * 256 + threadIdx.x;   // 16,777,216 float4s
    size_t e = i4 << 2;
    int no = (int)(e >> 16);
    int o = no & 127, n = no >> 7;
    float sg = g_bnp[o],       hg = g_bnp[128 + o];
    float sc = g_bnp[256 + o], hc = g_bnp[384 + o];
    float4 yv = *(const float4*)(g_y + e);
    float4 cv = *(const float4*)(g_crt + (((size_t)(n * 256 + o)) << 16) + (e & 65535));
    float4 g;
    g.x = fmaxf(yv.x * sg + hg + cv.x * sc + hc, 0.f);
    g.y = fmaxf(yv.y * sg + hg + cv.y * sc + hc, 0.f);
    g.z = fmaxf(yv.z * sg + hg + cv.z * sc + hc, 0.f);
    g.w = fmaxf(yv.w * sg + hg + cv.w * sc + hc, 0.f);
    *(float4*)(g_gcn + e) = g;
}

// ---------------------------------------------------------------------------
// TCN implicit GEMM: t[n,o,h,w] = sum_{c,k9} W[o,c,k9]*gcn[n,c,h+k9-4,w]
// fused epilogue: out = relu(bn_t(t + tcn_b) + bn_r(rt))
// 128(o) x 128(w) tile per block at fixed (n,h). K = 1152, chunk 8.
// 8x8 frag in split-quad layout (o in {ty*4+i, 64+ty*4+i}, w likewise).
// ---------------------------------------------------------------------------
__global__ __launch_bounds__(256) void tcn_kernel(const float* __restrict__ crt_unused,
                                                  float* __restrict__ out)
{
    int wBlk = blockIdx.x << 7;
    int h    = blockIdx.y;
    int n    = blockIdx.z;
    __shared__ float As[8][132];
    __shared__ float Bs[8][132];
    int tid = threadIdx.x;
    int tx = tid & 15, ty = tid >> 4;
    int lk = tid >> 5, lq = tid & 31;
    const float* gn = g_gcn + (size_t)n * 128 * PP;
    float acc[8][8] = {};

    for (int k0 = 0; k0 < 1152; k0 += 8) {
        int kg = k0 + lk;
        *(float4*)&As[lk][lq << 2] = *(const float4*)(g_WtT + (size_t)kg * 128 + (lq << 2));
        int c  = kg / 9;
        int k9 = kg - c * 9;
        int hs = h + k9 - 4;
        float4 bv = make_float4(0.f, 0.f, 0.f, 0.f);
        if ((unsigned)hs < 256u)
            bv = *(const float4*)(gn + ((size_t)c * 256 + hs) * 256 + wBlk + (lq << 2));
        *(float4*)&Bs[lk][lq << 2] = bv;
        __syncthreads();
#pragma unroll
        for (int kk = 0; kk < 8; kk++) {
            float4 a0 = *(const float4*)&As[kk][ty << 2];
            float4 a1 = *(const float4*)&As[kk][64 + (ty << 2)];
            float4 b0 = *(const float4*)&Bs[kk][tx << 2];
            float4 b1 = *(const float4*)&Bs[kk][64 + (tx << 2)];
            float a_[8] = {a0.x, a0.y, a0.z, a0.w, a1.x, a1.y, a1.z, a1.w};
            float b_[8] = {b0.x, b0.y, b0.z, b0.w, b1.x, b1.y, b1.z, b1.w};
#pragma unroll
            for (int i = 0; i < 8; i++)
#pragma unroll
                for (int j = 0; j < 8; j++)
                    acc[i][j] += a_[i] * b_[j];
        }
        __syncthreads();
    }

    // epilogue: relu(acc*st + ht2 + rt*sr + hr)
#pragma unroll
    for (int io = 0; io < 8; io++) {
        int o = ((io >> 2) << 6) + (ty << 2) + (io & 3);
        float stt = g_bnp[512 + o], htt = g_bnp[640 + o];
        float srr = g_bnp[768 + o], hrr = g_bnp[896 + o];
        size_t ob = ((size_t)(n * 128 + o) * 256 + h) * 256 + wBlk;
        size_t rb = ((size_t)(n * 256 + 128 + o) * 256 + h) * 256 + wBlk;
#pragma unroll
        for (int jq = 0; jq < 2; jq++) {
            int w = (jq << 6) + (tx << 2);
            float4 rv = *(const float4*)(g_crt + rb + w);
            float4 ov;
            ov.x = fmaxf(acc[io][jq * 4 + 0] * stt + htt + rv.x * srr + hrr, 0.f);
            ov.y = fmaxf(acc[io][jq * 4 + 1] * stt + htt + rv.y * srr + hrr, 0.f);
            ov.z = fmaxf(acc[io][jq * 4 + 2] * stt + htt + rv.z * srr + hrr, 0.f);
            ov.w = fmaxf(acc[io][jq * 4 + 3] * stt + htt + rv.w * srr + hrr, 0.f);
            *(float4*)(out + ob + w) = ov;
        }
    }
}

// ---------------------------------------------------------------------------
extern "C" void kernel_launch(void* const* d_in, const int* in_sizes, int n_in,
                              void* d_out, int out_size)
{
    const float* x       = (const float*)d_in[0];
    const float* mat_adj = (const float*)d_in[1];
    const float* adj_w   = (const float*)d_in[2];
    const float* wa      = (const float*)d_in[3];
    const float* ba      = (const float*)d_in[4];
    const float* wb      = (const float*)d_in[5];
    const float* bb      = (const float*)d_in[6];
    const float* wd      = (const float*)d_in[7];
    const float* bd      = (const float*)d_in[8];
    const float* gcn_bn  = (const float*)d_in[9];
    const float* cres_w  = (const float*)d_in[10];
    const float* cres_b  = (const float*)d_in[11];
    const float* cres_bn = (const float*)d_in[12];
    const float* tcn_w   = (const float*)d_in[13];
    const float* tcn_b   = (const float*)d_in[14];
    const float* tcn_bn  = (const float*)d_in[15];
    const float* rt_w    = (const float*)d_in[16];
    const float* rt_b    = (const float*)d_in[17];
    const float* rt_bn   = (const float*)d_in[18];
    float* out = (float*)d_out;

    pack_kernel<<<128, 256>>>(wa, ba, wb, bb, wd, bd, cres_w, cres_b,
                              rt_w, rt_b, gcn_bn, cres_bn, tcn_bn, rt_bn,
                              tcn_w, tcn_b);
    conv1x1_kernel<0><<<dim3(1024, 3, 8), 256>>>(x);   // a|b embeds
    conv1x1_kernel<1><<<dim3(1024, 4, 8), 256>>>(x);   // cres | rt
    scores_kernel<<<dim3(4, 4, 24), 256>>>();
    softmax_kernel<<<24, 256>>>(mat_adj, adj_w);
    xa_kernel<<<dim3(4, 4, 1536), 256>>>(x);
    ygemm_kernel<<<dim3(1024, 2, 8), 256>>>();
    gcn_kernel<<<65536, 256>>>();
    tcn_kernel<<<dim3(2, 256, 8), 256>>>(nullptr, out);
}

// round 2
// speedup vs baseline: 1.8222x; 1.8222x over previous
#include <cuda_runtime.h>
#include <math.h>

// ---------------------------------------------------------------------------
// Problem dims: N=8, C=64, COUT=128, T=V=256, S=3, IC=32, P=T*V=65536
// ---------------------------------------------------------------------------
#define PP 65536

typedef unsigned long long u64;

__device__ __forceinline__ void ffma2(u64& d, u64 a, u64 b) {
    asm("fma.rn.f32x2 %0, %1, %2, %3;" : "=l"(d) : "l"(a), "l"(b), "l"(d));
}
__device__ __forceinline__ u64 bcast2(float x) {
    u64 r;
    asm("mov.b64 %0, {%1, %1};" : "=l"(r) : "r"(__float_as_uint(x)));
    return r;
}
__device__ __forceinline__ float2 unpk(u64 v) {
    unsigned a, b;
    asm("mov.b64 {%0, %1}, %2;" : "=r"(a), "=r"(b) : "l"(v));
    return make_float2(__uint_as_float(a), __uint_as_float(b));
}

// ------------------------- packed parameters -------------------------------
__device__ float g_Wab[192 * 64];       // rows: [a0(32) b0(32) a1 b1 a2 b2] x C=64
__device__ float g_Bab[192];
__device__ float g_Wcrt[256 * 64];      // rows 0-127 cres_w, 128-255 rt_w
__device__ float g_Bcrt[256];
__device__ float g_Wd[128 * 192];       // [o][i*64+c] = wd[i][o][c]
__device__ float g_Bd[128];             // sum_i bd[i][o]
__device__ float g_WtT[1152 * 128];     // [k=(c*9+k9)][o] transposed tcn weights
__device__ float g_bnp[1024];           // 8 x 128: sg,hg, sc,hc, st,ht2, sr,hr

// ------------------------- scratch buffers ---------------------------------
__device__ float g_ab[100663296];       // [n][192][65536]
__device__ float g_adapt[1572864];      // [i*8+n][t][s]
__device__ float g_xa[100663296];       // [(i*8+n)*64+c][v*256+s]
__device__ float g_y[67108864];         // [n][128][65536]
__device__ float g_crt[134217728];      // [n][256][65536]  (cres | rt)
__device__ float g_gcn[67108864];       // [n][128][65536]

// ---------------------------------------------------------------------------
// pack kernel: reorganize weights, fold BN affine params
// ---------------------------------------------------------------------------
__global__ void pack_kernel(const float* __restrict__ wa, const float* __restrict__ ba,
                            const float* __restrict__ wb, const float* __restrict__ bb,
                            const float* __restrict__ wd, const float* __restrict__ bd,
                            const float* __restrict__ cres_w, const float* __restrict__ cres_b,
                            const float* __restrict__ rt_w, const float* __restrict__ rt_b,
                            const float* __restrict__ gcn_bn, const float* __restrict__ cres_bn,
                            const float* __restrict__ tcn_bn, const float* __restrict__ rt_bn,
                            const float* __restrict__ tcn_w, const float* __restrict__ tcn_b)
{
    int tid = blockIdx.x * blockDim.x + threadIdx.x;
    int nth = gridDim.x * blockDim.x;
    for (int idx = tid; idx < 192 * 64; idx += nth) {
        int o = idx >> 6, c = idx & 63;
        int i = o >> 6, sub = o & 63;
        g_Wab[idx] = (sub < 32) ? wa[(i * 32 + sub) * 64 + c]
                                : wb[(i * 32 + sub - 32) * 64 + c];
    }
    for (int o = tid; o < 192; o += nth) {
        int i = o >> 6, sub = o & 63;
        g_Bab[o] = (sub < 32) ? ba[i * 32 + sub] : bb[i * 32 + sub - 32];
    }
    for (int idx = tid; idx < 256 * 64; idx += nth) {
        int o = idx >> 6, c = idx & 63;
        g_Wcrt[idx] = (o < 128) ? cres_w[o * 64 + c] : rt_w[(o - 128) * 64 + c];
    }
    for (int o = tid; o < 256; o += nth)
        g_Bcrt[o] = (o < 128) ? cres_b[o] : rt_b[o - 128];
    for (int idx = tid; idx < 128 * 192; idx += nth) {
        int o = idx / 192, k = idx - o * 192;
        int i = k >> 6, c = k & 63;
        g_Wd[idx] = wd[(i * 128 + o) * 64 + c];
    }
    for (int o = tid; o < 128; o += nth)
        g_Bd[o] = bd[o] + bd[128 + o] + bd[256 + o];
    for (int idx = tid; idx < 1152 * 128; idx += nth) {
        int kk = idx >> 7, o = idx & 127;
        g_WtT[idx] = tcn_w[o * 1152 + kk];
    }
    for (int o = tid; o < 128; o += nth) {
        float g, b, m, v, s;
        g = gcn_bn[o]; b = gcn_bn[128 + o]; m = gcn_bn[256 + o]; v = gcn_bn[384 + o];
        s = g * rsqrtf(v + 1e-5f);
        g_bnp[o] = s; g_bnp[128 + o] = b - m * s;
        g = cres_bn[o]; b = cres_bn[128 + o]; m = cres_bn[256 + o]; v = cres_bn[384 + o];
        s = g * rsqrtf(v + 1e-5f);
        g_bnp[256 + o] = s; g_bnp[384 + o] = b - m * s;
        g = tcn_bn[o]; b = tcn_bn[128 + o]; m = tcn_bn[256 + o]; v = tcn_bn[384 + o];
        s = g * rsqrtf(v + 1e-5f);
        g_bnp[512 + o] = s; g_bnp[640 + o] = (tcn_b[o] - m) * s + b;   // tcn_b folded
        g = rt_bn[o]; b = rt_bn[128 + o]; m = rt_bn[256 + o]; v = rt_bn[384 + o];
        s = g * rsqrtf(v + 1e-5f);
        g_bnp[768 + o] = s; g_bnp[896 + o] = b - m * s;
    }
}

// 4x4 fragment inner step (packed f32x2): acc2[4][2]
#define FRAG44_STEP(kk)                                                          \
    {                                                                            \
        float4 aF = *(const float4*)&As[kk][ty << 2];                            \
        ulonglong2 bq = *(const ulonglong2*)&Bs[kk][tx << 2];                    \
        u64 a0 = bcast2(aF.x), a1 = bcast2(aF.y);                                \
        u64 a2 = bcast2(aF.z), a3 = bcast2(aF.w);                                \
        ffma2(acc2[0][0], a0, bq.x); ffma2(acc2[0][1], a0, bq.y);                \
        ffma2(acc2[1][0], a1, bq.x); ffma2(acc2[1][1], a1, bq.y);                \
        ffma2(acc2[2][0], a2, bq.x); ffma2(acc2[2][1], a2, bq.y);                \
        ffma2(acc2[3][0], a3, bq.x); ffma2(acc2[3][1], a3, bq.y);                \
    }

// ---------------------------------------------------------------------------
// conv1x1: out[n][o][p] = sum_c W[o][c] * x[n][c][p] + bias[o].  K=64.
// MODE 0: ab (M=192)   MODE 1: cres|rt (M=256)
// ---------------------------------------------------------------------------
template <int MODE>
__global__ __launch_bounds__(256) void conv1x1_kernel(const float* __restrict__ x)
{
    const int M = MODE ? 256 : 192;
    const float* __restrict__ W    = MODE ? g_Wcrt : g_Wab;
    const float* __restrict__ bias = MODE ? g_Bcrt : g_Bab;
    float* __restrict__ out        = MODE ? g_crt  : g_ab;

    int pBlk = blockIdx.x << 6;
    int oBlk = blockIdx.y << 6;
    int n    = blockIdx.z;
    __shared__ float As[16][68];
    __shared__ float Bs[16][68];
    int tid = threadIdx.x;
    int tx = tid & 15, ty = tid >> 4;
    int aRow = tid >> 2, kq = tid & 3;
    const float* xn = x + (size_t)n * 64 * PP;
    u64 acc2[4][2];
    const u64 z = 0;
#pragma unroll
    for (int i = 0; i < 4; i++) { acc2[i][0] = z; acc2[i][1] = z; }

#pragma unroll
    for (int k0 = 0; k0 < 64; k0 += 16) {
        float4 av = *(const float4*)(W + (oBlk + aRow) * 64 + k0 + (kq << 2));
        As[(kq << 2) + 0][aRow] = av.x;
        As[(kq << 2) + 1][aRow] = av.y;
        As[(kq << 2) + 2][aRow] = av.z;
        As[(kq << 2) + 3][aRow] = av.w;
        *(float4*)&Bs[ty][tx << 2] =
            *(const float4*)(xn + (size_t)(k0 + ty) * PP + pBlk + (tx << 2));
        __syncthreads();
#pragma unroll
        for (int kk = 0; kk < 16; kk++) FRAG44_STEP(kk)
        __syncthreads();
    }
    int oB = oBlk + (ty << 2), pB = pBlk + (tx << 2);
#pragma unroll
    for (int i = 0; i < 4; i++) {
        float bi = bias[oB + i];
        float2 p0 = unpk(acc2[i][0]), p1 = unpk(acc2[i][1]);
        float4 r;
        r.x = p0.x + bi; r.y = p0.y + bi;
        r.z = p1.x + bi; r.w = p1.y + bi;
        *(float4*)(out + ((size_t)n * M + oB + i) * PP + pB) = r;
    }
}

// ---------------------------------------------------------------------------
// scores: scores[b][t][s] = (1/256) * sum_{c<32,v} a[b,c,t,v]*b[b,c,s,v]
// ---------------------------------------------------------------------------
__global__ __launch_bounds__(256) void scores_kernel()
{
    int b = blockIdx.z;
    int i = b >> 3, n = b & 7;
    int sBlk = blockIdx.x << 6, tBlk = blockIdx.y << 6;
    const float* aBase = g_ab + ((size_t)n * 192 + i * 64) * PP;
    const float* bBase = aBase + (size_t)32 * PP;
    __shared__ float As[16][68];
    __shared__ float Bs[16][68];
    int tid = threadIdx.x;
    int tx = tid & 15, ty = tid >> 4;
    int r_ = tid >> 2, kq = tid & 3;
    u64 acc2[4][2];
#pragma unroll
    for (int ii = 0; ii < 4; ii++) { acc2[ii][0] = 0ull; acc2[ii][1] = 0ull; }

    for (int c = 0; c < 32; c++) {
        const float* ac = aBase + (size_t)c * PP;
        const float* bc = bBase + (size_t)c * PP;
#pragma unroll 4
        for (int v0 = 0; v0 < 256; v0 += 16) {
            float4 av = *(const float4*)(ac + (tBlk + r_) * 256 + v0 + (kq << 2));
            As[(kq << 2) + 0][r_] = av.x;
            As[(kq << 2) + 1][r_] = av.y;
            As[(kq << 2) + 2][r_] = av.z;
            As[(kq << 2) + 3][r_] = av.w;
            float4 bv = *(const float4*)(bc + (sBlk + r_) * 256 + v0 + (kq << 2));
            Bs[(kq << 2) + 0][r_] = bv.x;
            Bs[(kq << 2) + 1][r_] = bv.y;
            Bs[(kq << 2) + 2][r_] = bv.z;
            Bs[(kq << 2) + 3][r_] = bv.w;
            __syncthreads();
#pragma unroll
            for (int kk = 0; kk < 16; kk++) FRAG44_STEP(kk)
            __syncthreads();
        }
    }
    float* scp = g_adapt + (size_t)b * PP;
    const float sc = 1.0f / 256.0f;
#pragma unroll
    for (int ii = 0; ii < 4; ii++) {
        float2 p0 = unpk(acc2[ii][0]), p1 = unpk(acc2[ii][1]);
        float4 r;
        r.x = p0.x * sc; r.y = p0.y * sc;
        r.z = p1.x * sc; r.w = p1.y * sc;
        *(float4*)(scp + (tBlk + (ty << 2) + ii) * 256 + sBlk + (tx << 2)) = r;
    }
}

// ---------------------------------------------------------------------------
// softmax over t (dim -2) per column s, then adapt = mat_adj + adj_w + att.
// ---------------------------------------------------------------------------
__global__ __launch_bounds__(256) void softmax_kernel(const float* __restrict__ mat_adj,
                                                      const float* __restrict__ adj_w)
{
    int b = blockIdx.x;
    int i = b >> 3;
    float* sc = g_adapt + (size_t)b * PP;
    int s = threadIdx.x;
    float m = -1e30f;
    for (int t = 0; t < 256; t++) m = fmaxf(m, sc[t * 256 + s]);
    float sum = 0.f;
    for (int t = 0; t < 256; t++) sum += expf(sc[t * 256 + s] - m);
    float inv = 1.f / sum;
    const float* A1 = mat_adj + (size_t)i * PP;
    const float* A2 = adj_w + (size_t)i * PP;
    for (int t = 0; t < 256; t++) {
        int idx = t * 256 + s;
        sc[idx] = A1[idx] + A2[idx] + expf(sc[idx] - m) * inv;
    }
}

// ---------------------------------------------------------------------------
// xa[b2][v][s] = sum_t x[n,c,t,v] * adapt[bn,t,s];  b2 = bn*64+c, bn = i*8+n
// ---------------------------------------------------------------------------
__global__ __launch_bounds__(256) void xa_kernel(const float* __restrict__ x)
{
    int b2 = blockIdx.z;
    int c = b2 & 63, bn = b2 >> 6;
    int n = bn & 7;
    int sBlk = blockIdx.x << 6, vBlk = blockIdx.y << 6;
    const float* xb = x + ((size_t)n * 64 + c) * PP;
    const float* ad = g_adapt + (size_t)bn * PP;
    __shared__ float As[16][68];
    __shared__ float Bs[16][68];
    int tid = threadIdx.x;
    int tx = tid & 15, ty = tid >> 4;
    u64 acc2[4][2];
#pragma unroll
    for (int ii = 0; ii < 4; ii++) { acc2[ii][0] = 0ull; acc2[ii][1] = 0ull; }

#pragma unroll 4
    for (int k0 = 0; k0 < 256; k0 += 16) {
        *(float4*)&As[ty][tx << 2] =
            *(const float4*)(xb + (k0 + ty) * 256 + vBlk + (tx << 2));
        *(float4*)&Bs[ty][tx << 2] =
            *(const float4*)(ad + (k0 + ty) * 256 + sBlk + (tx << 2));
        __syncthreads();
#pragma unroll
        for (int kk = 0; kk < 16; kk++) FRAG44_STEP(kk)
        __syncthreads();
    }
    float* op = g_xa + (size_t)b2 * PP;
#pragma unroll
    for (int ii = 0; ii < 4; ii++) {
        float2 p0 = unpk(acc2[ii][0]), p1 = unpk(acc2[ii][1]);
        float4 r;
        r.x = p0.x; r.y = p0.y; r.z = p1.x; r.w = p1.y;
        *(float4*)(op + (vBlk + (ty << 2) + ii) * 256 + sBlk + (tx << 2)) = r;
    }
}

// ---------------------------------------------------------------------------
// y[n][o][p] = sum_{k=(i,c)} Wd[o][k] * xa[(i*8+n)*64+c][p] + Bd[o].  M=128, K=192
// ---------------------------------------------------------------------------
__global__ __launch_bounds__(256) void ygemm_kernel()
{
    int pBlk = blockIdx.x << 6;
    int oBlk = blockIdx.y << 6;
    int n    = blockIdx.z;
    __shared__ float As[16][68];
    __shared__ float Bs[16][68];
    int tid = threadIdx.x;
    int tx = tid & 15, ty = tid >> 4;
    int aRow = tid >> 2, kq = tid & 3;
    u64 acc2[4][2];
#pragma unroll
    for (int ii = 0; ii < 4; ii++) { acc2[ii][0] = 0ull; acc2[ii][1] = 0ull; }

#pragma unroll
    for (int k0 = 0; k0 < 192; k0 += 16) {
        float4 av = *(const float4*)(g_Wd + (oBlk + aRow) * 192 + k0 + (kq << 2));
        As[(kq << 2) + 0][aRow] = av.x;
        As[(kq << 2) + 1][aRow] = av.y;
        As[(kq << 2) + 2][aRow] = av.z;
        As[(kq << 2) + 3][aRow] = av.w;
        int k = k0 + ty;
        int i = k >> 6, cc = k & 63;
        *(float4*)&Bs[ty][tx << 2] =
            *(const float4*)(g_xa + (size_t)((i << 9) + (n << 6) + cc) * PP + pBlk + (tx << 2));
        __syncthreads();
#pragma unroll
        for (int kk = 0; kk < 16; kk++) FRAG44_STEP(kk)
        __syncthreads();
    }
    int oB = oBlk + (ty << 2), pB = pBlk + (tx << 2);
#pragma unroll
    for (int ii = 0; ii < 4; ii++) {
        float bi = g_Bd[oB + ii];
        float2 p0 = unpk(acc2[ii][0]), p1 = unpk(acc2[ii][1]);
        float4 r;
        r.x = p0.x + bi; r.y = p0.y + bi;
        r.z = p1.x + bi; r.w = p1.y + bi;
        *(float4*)(g_y + ((size_t)(n * 128) + oB + ii) * PP + pB) = r;
    }
}

// ---------------------------------------------------------------------------
// gcn = relu(bn_g(y) + bn_c(cres))   elementwise, raw-index add (T==V)
// ---------------------------------------------------------------------------
__global__ __launch_bounds__(256) void gcn_kernel()
{
    size_t i4 = (size_t)blockIdx.x * 256 + threadIdx.x;
    size_t e = i4 << 2;
    int no = (int)(e >> 16);
    int o = no & 127, n = no >> 7;
    float sg = g_bnp[o],       hg = g_bnp[128 + o];
    float sc = g_bnp[256 + o], hc = g_bnp[384 + o];
    float4 yv = *(const float4*)(g_y + e);
    float4 cv = *(const float4*)(g_crt + (((size_t)(n * 256 + o)) << 16) + (e & 65535));
    float4 g;
    g.x = fmaxf(yv.x * sg + hg + cv.x * sc + hc, 0.f);
    g.y = fmaxf(yv.y * sg + hg + cv.y * sc + hc, 0.f);
    g.z = fmaxf(yv.z * sg + hg + cv.z * sc + hc, 0.f);
    g.w = fmaxf(yv.w * sg + hg + cv.w * sc + hc, 0.f);
    *(float4*)(g_gcn + e) = g;
}

// ---------------------------------------------------------------------------
// TCN implicit GEMM + fused epilogue. 128(o) x 128(w) tile, K=1152, chunk 16.
// acc2[8][4] packed pairs along w.
// ---------------------------------------------------------------------------
__global__ __launch_bounds__(256) void tcn_kernel(float* __restrict__ out)
{
    int wBlk = blockIdx.x << 7;
    int h    = blockIdx.y;
    int n    = blockIdx.z;
    __shared__ float As[16][132];
    __shared__ float Bs[16][132];
    int tid = threadIdx.x;
    int tx = tid & 15, ty = tid >> 4;
    int lk = tid >> 5, lq = tid & 31;
    const float* gn = g_gcn + (size_t)n * 128 * PP;
    u64 acc2[8][4];
#pragma unroll
    for (int i = 0; i < 8; i++)
#pragma unroll
        for (int j = 0; j < 4; j++) acc2[i][j] = 0ull;

    for (int k0 = 0; k0 < 1152; k0 += 16) {
#pragma unroll
        for (int rr = 0; rr < 2; rr++) {
            int row = lk + (rr << 3);
            int kg = k0 + row;
            *(float4*)&As[row][lq << 2] =
                *(const float4*)(g_WtT + (size_t)kg * 128 + (lq << 2));
            int c  = kg / 9;
            int k9 = kg - c * 9;
            int hs = h + k9 - 4;
            float4 bv = make_float4(0.f, 0.f, 0.f, 0.f);
            if ((unsigned)hs < 256u)
                bv = *(const float4*)(gn + ((size_t)c * 256 + hs) * 256 + wBlk + (lq << 2));
            *(float4*)&Bs[row][lq << 2] = bv;
        }
        __syncthreads();
#pragma unroll
        for (int kk = 0; kk < 16; kk++) {
            float4 a0 = *(const float4*)&As[kk][ty << 2];
            float4 a1 = *(const float4*)&As[kk][64 + (ty << 2)];
            ulonglong2 b0 = *(const ulonglong2*)&Bs[kk][tx << 2];
            ulonglong2 b1 = *(const ulonglong2*)&Bs[kk][64 + (tx << 2)];
            u64 ap[8] = {bcast2(a0.x), bcast2(a0.y), bcast2(a0.z), bcast2(a0.w),
                         bcast2(a1.x), bcast2(a1.y), bcast2(a1.z), bcast2(a1.w)};
            u64 bp[4] = {b0.x, b0.y, b1.x, b1.y};
#pragma unroll
            for (int i = 0; i < 8; i++)
#pragma unroll
                for (int j = 0; j < 4; j++)
                    ffma2(acc2[i][j], ap[i], bp[j]);
        }
        __syncthreads();
    }

    // epilogue: relu(acc*st + ht2 + rt*sr + hr)
#pragma unroll
    for (int io = 0; io < 8; io++) {
        int o = ((io >> 2) << 6) + (ty << 2) + (io & 3);
        float stt = g_bnp[512 + o], htt = g_bnp[640 + o];
        float srr = g_bnp[768 + o], hrr = g_bnp[896 + o];
        size_t ob = ((size_t)(n * 128 + o) * 256 + h) * 256 + wBlk;
        size_t rb = ((size_t)(n * 256 + 128 + o) * 256 + h) * 256 + wBlk;
#pragma unroll
        for (int jq = 0; jq < 2; jq++) {
            int w = (jq << 6) + (tx << 2);
            float4 rv = *(const float4*)(g_crt + rb + w);
            float2 p0 = unpk(acc2[io][jq * 2 + 0]);
            float2 p1 = unpk(acc2[io][jq * 2 + 1]);
            float4 ov;
            ov.x = fmaxf(p0.x * stt + htt + rv.x * srr + hrr, 0.f);
            ov.y = fmaxf(p0.y * stt + htt + rv.y * srr + hrr, 0.f);
            ov.z = fmaxf(p1.x * stt + htt + rv.z * srr + hrr, 0.f);
            ov.w = fmaxf(p1.y * stt + htt + rv.w * srr + hrr, 0.f);
            *(float4*)(out + ob + w) = ov;
        }
    }
}

// ---------------------------------------------------------------------------
extern "C" void kernel_launch(void* const* d_in, const int* in_sizes, int n_in,
                              void* d_out, int out_size)
{
    const float* x       = (const float*)d_in[0];
    const float* mat_adj = (const float*)d_in[1];
    const float* adj_w   = (const float*)d_in[2];
    const float* wa      = (const float*)d_in[3];
    const float* ba      = (const float*)d_in[4];
    const float* wb      = (const float*)d_in[5];
    const float* bb      = (const float*)d_in[6];
    const float* wd      = (const float*)d_in[7];
    const float* bd      = (const float*)d_in[8];
    const float* gcn_bn  = (const float*)d_in[9];
    const float* cres_w  = (const float*)d_in[10];
    const float* cres_b  = (const float*)d_in[11];
    const float* cres_bn = (const float*)d_in[12];
    const float* tcn_w   = (const float*)d_in[13];
    const float* tcn_b   = (const float*)d_in[14];
    const float* tcn_bn  = (const float*)d_in[15];
    const float* rt_w    = (const float*)d_in[16];
    const float* rt_b    = (const float*)d_in[17];
    const float* rt_bn   = (const float*)d_in[18];
    float* out = (float*)d_out;

    pack_kernel<<<128, 256>>>(wa, ba, wb, bb, wd, bd, cres_w, cres_b,
                              rt_w, rt_b, gcn_bn, cres_bn, tcn_bn, rt_bn,
                              tcn_w, tcn_b);
    conv1x1_kernel<0><<<dim3(1024, 3, 8), 256>>>(x);   // a|b embeds
    conv1x1_kernel<1><<<dim3(1024, 4, 8), 256>>>(x);   // cres | rt
    scores_kernel<<<dim3(4, 4, 24), 256>>>();
    softmax_kernel<<<24, 256>>>(mat_adj, adj_w);
    xa_kernel<<<dim3(4, 4, 1536), 256>>>(x);
    ygemm_kernel<<<dim3(1024, 2, 8), 256>>>();
    gcn_kernel<<<65536, 256>>>();
    tcn_kernel<<<dim3(2, 256, 8), 256>>>(out);
}

// round 3
// speedup vs baseline: 2.1248x; 1.1661x over previous
#include <cuda_runtime.h>
#include <math.h>

// ---------------------------------------------------------------------------
// Problem dims: N=8, C=64, COUT=128, T=V=256, S=3, IC=32, P=T*V=65536
// ---------------------------------------------------------------------------
#define PP 65536

typedef unsigned long long u64;

__device__ __forceinline__ void ffma2(u64& d, u64 a, u64 b) {
    asm("fma.rn.f32x2 %0, %1, %2, %3;" : "=l"(d) : "l"(a), "l"(b), "l"(d));
}
__device__ __forceinline__ u64 bcast2(float x) {
    u64 r;
    asm("mov.b64 %0, {%1, %1};" : "=l"(r) : "r"(__float_as_uint(x)));
    return r;
}
__device__ __forceinline__ float2 unpk(u64 v) {
    unsigned a, b;
    asm("mov.b64 {%0, %1}, %2;" : "=r"(a), "=r"(b) : "l"(v));
    return make_float2(__uint_as_float(a), __uint_as_float(b));
}

// ------------------------- packed parameters -------------------------------
__device__ float g_Wab[256 * 64];       // rows 0-191: [a0 b0 a1 b1 a2 b2], 192-255 zero pad
__device__ float g_Bab[256];
__device__ float g_Wcrt[256 * 64];      // rows 0-127 cres_w, 128-255 rt_w
__device__ float g_Bcrt[256];
__device__ float g_Wd[128 * 192];       // [o][i*64+c] = wd[i][o][c]
__device__ float g_Bd[128];
__device__ float g_WtT[1152 * 128];     // [k=(c*9+k9)][o] transposed tcn weights
__device__ float g_bnp[1024];           // 8 x 128: sg,hg, sc,hc, st,ht2, sr,hr

// ------------------------- scratch buffers ---------------------------------
__device__ float g_ab[134217728];       // [n][256][65536]  (rows 192-255 pad)
__device__ float g_adapt[1572864];      // [i*8+n][t][s]
__device__ float g_xa[100663296];       // [(i*8+n)*64+c][v*256+s]; head reused as scores split-k scratch
__device__ float g_y[67108864];         // [n][128][65536]
__device__ float g_crt[134217728];      // [n][256][65536]  (cres | rt)
__device__ float g_gcn[67108864];       // [n][128][65536]

// ---------------------------------------------------------------------------
__global__ void pack_kernel(const float* __restrict__ wa, const float* __restrict__ ba,
                            const float* __restrict__ wb, const float* __restrict__ bb,
                            const float* __restrict__ wd, const float* __restrict__ bd,
                            const float* __restrict__ cres_w, const float* __restrict__ cres_b,
                            const float* __restrict__ rt_w, const float* __restrict__ rt_b,
                            const float* __restrict__ gcn_bn, const float* __restrict__ cres_bn,
                            const float* __restrict__ tcn_bn, const float* __restrict__ rt_bn,
                            const float* __restrict__ tcn_w, const float* __restrict__ tcn_b)
{
    int tid = blockIdx.x * blockDim.x + threadIdx.x;
    int nth = gridDim.x * blockDim.x;
    for (int idx = tid; idx < 256 * 64; idx += nth) {
        int o = idx >> 6, c = idx & 63;
        int i = o >> 6, sub = o & 63;
        float v = 0.f;
        if (o < 192) v = (sub < 32) ? wa[(i * 32 + sub) * 64 + c]
                                    : wb[(i * 32 + sub - 32) * 64 + c];
        g_Wab[idx] = v;
    }
    for (int o = tid; o < 256; o += nth) {
        int i = o >> 6, sub = o & 63;
        float v = 0.f;
        if (o < 192) v = (sub < 32) ? ba[i * 32 + sub] : bb[i * 32 + sub - 32];
        g_Bab[o] = v;
    }
    for (int idx = tid; idx < 256 * 64; idx += nth) {
        int o = idx >> 6, c = idx & 63;
        g_Wcrt[idx] = (o < 128) ? cres_w[o * 64 + c] : rt_w[(o - 128) * 64 + c];
    }
    for (int o = tid; o < 256; o += nth)
        g_Bcrt[o] = (o < 128) ? cres_b[o] : rt_b[o - 128];
    for (int idx = tid; idx < 128 * 192; idx += nth) {
        int o = idx / 192, k = idx - o * 192;
        int i = k >> 6, c = k & 63;
        g_Wd[idx] = wd[(i * 128 + o) * 64 + c];
    }
    for (int o = tid; o < 128; o += nth)
        g_Bd[o] = bd[o] + bd[128 + o] + bd[256 + o];
    for (int idx = tid; idx < 1152 * 128; idx += nth) {
        int kk = idx >> 7, o = idx & 127;
        g_WtT[idx] = tcn_w[o * 1152 + kk];
    }
    for (int o = tid; o < 128; o += nth) {
        float g, b, m, v, s;
        g = gcn_bn[o]; b = gcn_bn[128 + o]; m = gcn_bn[256 + o]; v = gcn_bn[384 + o];
        s = g * rsqrtf(v + 1e-5f);
        g_bnp[o] = s; g_bnp[128 + o] = b - m * s;
        g = cres_bn[o]; b = cres_bn[128 + o]; m = cres_bn[256 + o]; v = cres_bn[384 + o];
        s = g * rsqrtf(v + 1e-5f);
        g_bnp[256 + o] = s; g_bnp[384 + o] = b - m * s;
        g = tcn_bn[o]; b = tcn_bn[128 + o]; m = tcn_bn[256 + o]; v = tcn_bn[384 + o];
        s = g * rsqrtf(v + 1e-5f);
        g_bnp[512 + o] = s; g_bnp[640 + o] = (tcn_b[o] - m) * s + b;
        g = rt_bn[o]; b = rt_bn[128 + o]; m = rt_bn[256 + o]; v = rt_bn[384 + o];
        s = g * rsqrtf(v + 1e-5f);
        g_bnp[768 + o] = s; g_bnp[896 + o] = b - m * s;
    }
}

// 8x8 fragment step on 128-wide tile, split-quad layout.
#define FRAG88(As_, Bs_, kk)                                                     \
    {                                                                            \
        float4 a0 = *(const float4*)&As_[kk][ty << 2];                           \
        float4 a1 = *(const float4*)&As_[kk][64 + (ty << 2)];                    \
        ulonglong2 b0 = *(const ulonglong2*)&Bs_[kk][tx << 2];                   \
        ulonglong2 b1 = *(const ulonglong2*)&Bs_[kk][64 + (tx << 2)];            \
        u64 ap[8] = {bcast2(a0.x), bcast2(a0.y), bcast2(a0.z), bcast2(a0.w),     \
                     bcast2(a1.x), bcast2(a1.y), bcast2(a1.z), bcast2(a1.w)};    \
        u64 bp[4] = {b0.x, b0.y, b1.x, b1.y};                                    \
        _Pragma("unroll")                                                        \
        for (int _i = 0; _i < 8; _i++)                                           \
            _Pragma("unroll")                                                    \
            for (int _j = 0; _j < 4; _j++)                                       \
                ffma2(acc2[_i][_j], ap[_i], bp[_j]);                             \
    }

#define ZERO_ACC()                                                               \
    u64 acc2[8][4];                                                              \
    _Pragma("unroll") for (int _i = 0; _i < 8; _i++)                             \
        _Pragma("unroll") for (int _j = 0; _j < 4; _j++) acc2[_i][_j] = 0ull;

// Transposed A fill: 16 k x 128 m from row-major rows of length `ld`.
#define FILL_A_T(rowptr_expr, k0)                                                \
    _Pragma("unroll")                                                            \
    for (int rr = 0; rr < 2; rr++) {                                             \
        int m_ = (tid >> 2) + (rr << 6);                                         \
        int kq_ = tid & 3;                                                       \
        float4 av = *(const float4*)((rowptr_expr) + (k0) + (kq_ << 2));         \
        As[(kq_ << 2) + 0][m_] = av.x;                                           \
        As[(kq_ << 2) + 1][m_] = av.y;                                           \
        As[(kq_ << 2) + 2][m_] = av.z;                                           \
        As[(kq_ << 2) + 3][m_] = av.w;                                           \
    }

// ---------------------------------------------------------------------------
// conv1x1: out[n][o][p] = sum_c W[o][c] * x[n][c][p] + bias[o].  K=64, M=256.
// 128(o) x 128(p) tiles, 8x8 frag.
// ---------------------------------------------------------------------------
template <int MODE>
__global__ __launch_bounds__(256, 2) void conv1x1_kernel(const float* __restrict__ x)
{
    const float* __restrict__ W    = MODE ? g_Wcrt : g_Wab;
    const float* __restrict__ bias = MODE ? g_Bcrt : g_Bab;
    float* __restrict__ out        = MODE ? g_crt  : g_ab;

    int pBlk = blockIdx.x << 7;
    int oBlk = blockIdx.y << 7;
    int n    = blockIdx.z;
    __shared__ __align__(16) float As[16][132];
    __shared__ __align__(16) float Bs[16][132];
    int tid = threadIdx.x;
    int tx = tid & 15, ty = tid >> 4;
    const float* xn = x + (size_t)n * 64 * PP;
    ZERO_ACC();

#pragma unroll
    for (int k0 = 0; k0 < 64; k0 += 16) {
        FILL_A_T(W + (oBlk + m_) * 64, k0)
#pragma unroll
        for (int rr = 0; rr < 2; rr++) {
            int r = (tid >> 5) + (rr << 3);
            int c2 = tid & 31;
            *(float4*)&Bs[r][c2 << 2] =
                *(const float4*)(xn + (size_t)(k0 + r) * PP + pBlk + (c2 << 2));
        }
        __syncthreads();
#pragma unroll
        for (int kk = 0; kk < 16; kk++) FRAG88(As, Bs, kk)
        __syncthreads();
    }
#pragma unroll
    for (int io = 0; io < 8; io++) {
        int o = oBlk + ((io >> 2) << 6) + (ty << 2) + (io & 3);
        float bi = bias[o];
#pragma unroll
        for (int jq = 0; jq < 2; jq++) {
            int col = (jq << 6) + (tx << 2);
            float2 p0 = unpk(acc2[io][jq * 2 + 0]);
            float2 p1 = unpk(acc2[io][jq * 2 + 1]);
            float4 r;
            r.x = p0.x + bi; r.y = p0.y + bi; r.z = p1.x + bi; r.w = p1.y + bi;
            *(float4*)(out + ((size_t)n * 256 + o) * PP + pBlk + col) = r;
        }
    }
}

// ---------------------------------------------------------------------------
// scores (split-K=2): partial[b][t][s] = (1/256)*sum_{c in half,v} a*b
// kh=0 -> g_adapt, kh=1 -> g_xa scratch. 128x128 tiles.
// ---------------------------------------------------------------------------
__global__ __launch_bounds__(256, 2) void scores_kernel()
{
    int bz = blockIdx.z;
    int kh = bz & 1, b = bz >> 1;
    int i = b >> 3, n = b & 7;
    int sBlk = blockIdx.x << 7, tBlk = blockIdx.y << 7;
    const float* aBase = g_ab + ((size_t)n * 256 + i * 64) * PP;
    const float* bBase = aBase + (size_t)32 * PP;
    __shared__ __align__(16) float As[16][132];
    __shared__ __align__(16) float Bs[16][132];
    int tid = threadIdx.x;
    int tx = tid & 15, ty = tid >> 4;
    ZERO_ACC();

    int c0 = kh << 4;
    for (int c = c0; c < c0 + 16; c++) {
        const float* ac = aBase + (size_t)c * PP;
        const float* bc = bBase + (size_t)c * PP;
        for (int v0 = 0; v0 < 256; v0 += 16) {
            FILL_A_T(ac + (size_t)(tBlk + m_) * 256, v0)
            // B transposed fill (same pattern, Bs)
#pragma unroll
            for (int rr = 0; rr < 2; rr++) {
                int m_ = (tid >> 2) + (rr << 6);
                int kq_ = tid & 3;
                float4 bv = *(const float4*)(bc + (size_t)(sBlk + m_) * 256 + v0 + (kq_ << 2));
                Bs[(kq_ << 2) + 0][m_] = bv.x;
                Bs[(kq_ << 2) + 1][m_] = bv.y;
                Bs[(kq_ << 2) + 2][m_] = bv.z;
                Bs[(kq_ << 2) + 3][m_] = bv.w;
            }
            __syncthreads();
#pragma unroll
            for (int kk = 0; kk < 16; kk++) FRAG88(As, Bs, kk)
            __syncthreads();
        }
    }
    float* dst = (kh ? g_xa : g_adapt) + (size_t)b * PP;
    const float sc = 1.0f / 256.0f;
#pragma unroll
    for (int io = 0; io < 8; io++) {
        int t = tBlk + ((io >> 2) << 6) + (ty << 2) + (io & 3);
#pragma unroll
        for (int jq = 0; jq < 2; jq++) {
            int col = sBlk + (jq << 6) + (tx << 2);
            float2 p0 = unpk(acc2[io][jq * 2 + 0]);
            float2 p1 = unpk(acc2[io][jq * 2 + 1]);
            float4 r;
            r.x = p0.x * sc; r.y = p0.y * sc; r.z = p1.x * sc; r.w = p1.y * sc;
            *(float4*)(dst + (size_t)t * 256 + col) = r;
        }
    }
}

// ---------------------------------------------------------------------------
// softmax over t (dim -2) per column s on (g_adapt + g_xa partials),
// then adapt = mat_adj + adj_w + att, written to g_adapt.
// ---------------------------------------------------------------------------
__global__ __launch_bounds__(1024) void softmax_kernel(const float* __restrict__ mat_adj,
                                                       const float* __restrict__ adj_w)
{
    int b = blockIdx.x;
    int i = b >> 3;
    const float* p1 = g_adapt + (size_t)b * PP;
    const float* p2 = g_xa + (size_t)b * PP;
    float* dst = g_adapt + (size_t)b * PP;
    int s = threadIdx.x & 255, tq = threadIdx.x >> 8;   // 4 t-quarters
    __shared__ float red[4][256];
    int t0 = tq << 6, t1 = t0 + 64;
    float m = -1e30f;
    for (int t = t0; t < t1; t++) {
        int idx = t * 256 + s;
        m = fmaxf(m, p1[idx] + p2[idx]);
    }
    red[tq][s] = m;
    __syncthreads();
    m = fmaxf(fmaxf(red[0][s], red[1][s]), fmaxf(red[2][s], red[3][s]));
    __syncthreads();
    float sum = 0.f;
    for (int t = t0; t < t1; t++) {
        int idx = t * 256 + s;
        sum += expf(p1[idx] + p2[idx] - m);
    }
    red[tq][s] = sum;
    __syncthreads();
    sum = red[0][s] + red[1][s] + red[2][s] + red[3][s];
    float inv = 1.f / sum;
    const float* A1 = mat_adj + (size_t)i * PP;
    const float* A2 = adj_w + (size_t)i * PP;
    for (int t = t0; t < t1; t++) {
        int idx = t * 256 + s;
        float e = expf(p1[idx] + p2[idx] - m) * inv;
        dst[idx] = A1[idx] + A2[idx] + e;
    }
}

// ---------------------------------------------------------------------------
// xa[b2][v][s] = sum_t x[n,c,t,v] * adapt[bn,t,s];  b2 = bn*64+c
// 128x128 tiles, K=256.
// ---------------------------------------------------------------------------
__global__ __launch_bounds__(256, 2) void xa_kernel(const float* __restrict__ x)
{
    int b2 = blockIdx.z;
    int c = b2 & 63, bn = b2 >> 6;
    int n = bn & 7;
    int sBlk = blockIdx.x << 7, vBlk = blockIdx.y << 7;
    const float* xb = x + ((size_t)n * 64 + c) * PP;
    const float* ad = g_adapt + (size_t)bn * PP;
    __shared__ __align__(16) float As[16][132];
    __shared__ __align__(16) float Bs[16][132];
    int tid = threadIdx.x;
    int tx = tid & 15, ty = tid >> 4;
    ZERO_ACC();

#pragma unroll 2
    for (int k0 = 0; k0 < 256; k0 += 16) {
#pragma unroll
        for (int rr = 0; rr < 2; rr++) {
            int r = (tid >> 5) + (rr << 3);
            int c2 = tid & 31;
            *(float4*)&As[r][c2 << 2] =
                *(const float4*)(xb + (size_t)(k0 + r) * 256 + vBlk + (c2 << 2));
            *(float4*)&Bs[r][c2 << 2] =
                *(const float4*)(ad + (size_t)(k0 + r) * 256 + sBlk + (c2 << 2));
        }
        __syncthreads();
#pragma unroll
        for (int kk = 0; kk < 16; kk++) FRAG88(As, Bs, kk)
        __syncthreads();
    }
    float* op = g_xa + (size_t)b2 * PP;
#pragma unroll
    for (int io = 0; io < 8; io++) {
        int v = vBlk + ((io >> 2) << 6) + (ty << 2) + (io & 3);
#pragma unroll
        for (int jq = 0; jq < 2; jq++) {
            int col = sBlk + (jq << 6) + (tx << 2);
            float2 p0 = unpk(acc2[io][jq * 2 + 0]);
            float2 p1 = unpk(acc2[io][jq * 2 + 1]);
            float4 r;
            r.x = p0.x; r.y = p0.y; r.z = p1.x; r.w = p1.y;
            *(float4*)(op + (size_t)v * 256 + col) = r;
        }
    }
}

// ---------------------------------------------------------------------------
// y[n][o][p] = sum_{k=(i,c)} Wd[o][k] * xa[(i*8+n)*64+c][p] + Bd[o].  M=128, K=192
// ---------------------------------------------------------------------------
__global__ __launch_bounds__(256, 2) void ygemm_kernel()
{
    int pBlk = blockIdx.x << 7;
    int n    = blockIdx.z;
    __shared__ __align__(16) float As[16][132];
    __shared__ __align__(16) float Bs[16][132];
    int tid = threadIdx.x;
    int tx = tid & 15, ty = tid >> 4;
    ZERO_ACC();

#pragma unroll
    for (int k0 = 0; k0 < 192; k0 += 16) {
        // A transposed: only 128 rows of Wd
        {
            int m_ = tid >> 1;
            int kq_ = tid & 1;
#pragma unroll
            for (int hh = 0; hh < 2; hh++) {
                float4 av = *(const float4*)(g_Wd + (size_t)m_ * 192 + k0 + ((kq_ * 2 + hh) << 2));
                int kb = ((kq_ * 2 + hh) << 2);
                As[kb + 0][m_] = av.x;
                As[kb + 1][m_] = av.y;
                As[kb + 2][m_] = av.z;
                As[kb + 3][m_] = av.w;
            }
        }
#pragma unroll
        for (int rr = 0; rr < 2; rr++) {
            int r = (tid >> 5) + (rr << 3);
            int c2 = tid & 31;
            int k = k0 + r;
            int i = k >> 6, cc = k & 63;
            *(float4*)&Bs[r][c2 << 2] =
                *(const float4*)(g_xa + (size_t)((i << 9) + (n << 6) + cc) * PP + pBlk + (c2 << 2));
        }
        __syncthreads();
#pragma unroll
        for (int kk = 0; kk < 16; kk++) FRAG88(As, Bs, kk)
        __syncthreads();
    }
#pragma unroll
    for (int io = 0; io < 8; io++) {
        int o = ((io >> 2) << 6) + (ty << 2) + (io & 3);
        float bi = g_Bd[o];
#pragma unroll
        for (int jq = 0; jq < 2; jq++) {
            int col = pBlk + (jq << 6) + (tx << 2);
            float2 p0 = unpk(acc2[io][jq * 2 + 0]);
            float2 p1 = unpk(acc2[io][jq * 2 + 1]);
            float4 r;
            r.x = p0.x + bi; r.y = p0.y + bi; r.z = p1.x + bi; r.w = p1.y + bi;
            *(float4*)(g_y + ((size_t)(n * 128) + o) * PP + col) = r;
        }
    }
}

// ---------------------------------------------------------------------------
// gcn = relu(bn_g(y) + bn_c(cres))   elementwise, raw-index add (T==V)
// ---------------------------------------------------------------------------
__global__ __launch_bounds__(256) void gcn_kernel()
{
    size_t i4 = (size_t)blockIdx.x * 256 + threadIdx.x;
    size_t e = i4 << 2;
    int no = (int)(e >> 16);
    int o = no & 127, n = no >> 7;
    float sg = g_bnp[o],       hg = g_bnp[128 + o];
    float sc = g_bnp[256 + o], hc = g_bnp[384 + o];
    float4 yv = *(const float4*)(g_y + e);
    float4 cv = *(const float4*)(g_crt + (((size_t)(n * 256 + o)) << 16) + (e & 65535));
    float4 g;
    g.x = fmaxf(yv.x * sg + hg + cv.x * sc + hc, 0.f);
    g.y = fmaxf(yv.y * sg + hg + cv.y * sc + hc, 0.f);
    g.z = fmaxf(yv.z * sg + hg + cv.z * sc + hc, 0.f);
    g.w = fmaxf(yv.w * sg + hg + cv.w * sc + hc, 0.f);
    *(float4*)(g_gcn + e) = g;
}

// ---------------------------------------------------------------------------
// TCN implicit GEMM + fused epilogue. 128(o) x 128(w) tile, K=1152, chunk 16,
// double-buffered shared memory (1 barrier per K-chunk).
// ---------------------------------------------------------------------------
__global__ __launch_bounds__(256) void tcn_kernel(float* __restrict__ out)
{
    int wBlk = blockIdx.x << 7;
    int h    = blockIdx.y;
    int n    = blockIdx.z;
    __shared__ __align__(16) float As[2][16][132];
    __shared__ __align__(16) float Bs[2][16][132];
    int tid = threadIdx.x;
    int tx = tid & 15, ty = tid >> 4;
    int lk = tid >> 5, lq = tid & 31;
    const float* gn = g_gcn + (size_t)n * 128 * PP;
    ZERO_ACC();
    float4 aR[2], bR[2];

#define TCN_LDG(k0)                                                               \
    _Pragma("unroll")                                                             \
    for (int rr = 0; rr < 2; rr++) {                                              \
        int kg = (k0) + lk + (rr << 3);                                           \
        aR[rr] = *(const float4*)(g_WtT + (size_t)kg * 128 + (lq << 2));          \
        int c = kg / 9;                                                           \
        int k9 = kg - c * 9;                                                      \
        int hs = h + k9 - 4;                                                      \
        bR[rr] = make_float4(0.f, 0.f, 0.f, 0.f);                                 \
        if ((unsigned)hs < 256u)                                                  \
            bR[rr] = *(const float4*)(gn + ((size_t)c * 256 + hs) * 256 + wBlk + (lq << 2)); \
    }
#define TCN_STS(bf)                                                               \
    _Pragma("unroll")                                                             \
    for (int rr = 0; rr < 2; rr++) {                                              \
        int row = lk + (rr << 3);                                                 \
        *(float4*)&As[bf][row][lq << 2] = aR[rr];                                 \
        *(float4*)&Bs[bf][row][lq << 2] = bR[rr];                                 \
    }

    TCN_LDG(0)
    TCN_STS(0)
    __syncthreads();
    int buf = 0;
    for (int k0 = 0; k0 < 1152; k0 += 16) {
        int nxt = k0 + 16;
        if (nxt < 1152) TCN_LDG(nxt)
#pragma unroll
        for (int kk = 0; kk < 16; kk++) FRAG88(As[buf], Bs[buf], kk)
        if (nxt < 1152) TCN_STS(buf ^ 1)
        __syncthreads();
        buf ^= 1;
    }

#pragma unroll
    for (int io = 0; io < 8; io++) {
        int o = ((io >> 2) << 6) + (ty << 2) + (io & 3);
        float stt = g_bnp[512 + o], htt = g_bnp[640 + o];
        float srr = g_bnp[768 + o], hrr = g_bnp[896 + o];
        size_t ob = ((size_t)(n * 128 + o) * 256 + h) * 256 + wBlk;
        size_t rb = ((size_t)(n * 256 + 128 + o) * 256 + h) * 256 + wBlk;
#pragma unroll
        for (int jq = 0; jq < 2; jq++) {
            int w = (jq << 6) + (tx << 2);
            float4 rv = *(const float4*)(g_crt + rb + w);
            float2 p0 = unpk(acc2[io][jq * 2 + 0]);
            float2 p1 = unpk(acc2[io][jq * 2 + 1]);
            float4 ov;
            ov.x = fmaxf(p0.x * stt + htt + rv.x * srr + hrr, 0.f);
            ov.y = fmaxf(p0.y * stt + htt + rv.y * srr + hrr, 0.f);
            ov.z = fmaxf(p1.x * stt + htt + rv.z * srr + hrr, 0.f);
            ov.w = fmaxf(p1.y * stt + htt + rv.w * srr + hrr, 0.f);
            *(float4*)(out + ob + w) = ov;
        }
    }
}

// ---------------------------------------------------------------------------
extern "C" void kernel_launch(void* const* d_in, const int* in_sizes, int n_in,
                              void* d_out, int out_size)
{
    const float* x       = (const float*)d_in[0];
    const float* mat_adj = (const float*)d_in[1];
    const float* adj_w   = (const float*)d_in[2];
    const float* wa      = (const float*)d_in[3];
    const float* ba      = (const float*)d_in[4];
    const float* wb      = (const float*)d_in[5];
    const float* bb      = (const float*)d_in[6];
    const float* wd      = (const float*)d_in[7];
    const float* bd      = (const float*)d_in[8];
    const float* gcn_bn  = (const float*)d_in[9];
    const float* cres_w  = (const float*)d_in[10];
    const float* cres_b  = (const float*)d_in[11];
    const float* cres_bn = (const float*)d_in[12];
    const float* tcn_w   = (const float*)d_in[13];
    const float* tcn_b   = (const float*)d_in[14];
    const float* tcn_bn  = (const float*)d_in[15];
    const float* rt_w    = (const float*)d_in[16];
    const float* rt_b    = (const float*)d_in[17];
    const float* rt_bn   = (const float*)d_in[18];
    float* out = (float*)d_out;

    pack_kernel<<<128, 256>>>(wa, ba, wb, bb, wd, bd, cres_w, cres_b,
                              rt_w, rt_b, gcn_bn, cres_bn, tcn_bn, rt_bn,
                              tcn_w, tcn_b);
    conv1x1_kernel<0><<<dim3(512, 2, 8), 256>>>(x);   // a|b embeds (padded M=256)
    conv1x1_kernel<1><<<dim3(512, 2, 8), 256>>>(x);   // cres | rt
    scores_kernel<<<dim3(2, 2, 48), 256>>>();         // split-K=2
    softmax_kernel<<<24, 1024>>>(mat_adj, adj_w);
    xa_kernel<<<dim3(2, 2, 1536), 256>>>(x);
    ygemm_kernel<<<dim3(512, 1, 8), 256>>>();
    gcn_kernel<<<65536, 256>>>();
    tcn_kernel<<<dim3(2, 256, 8), 256>>>(out);
}

// round 7
// speedup vs baseline: 2.6035x; 1.2253x over previous
#include <cuda_runtime.h>
#include <cuda_bf16.h>
#include <math.h>
#include <stdint.h>

// ---------------------------------------------------------------------------
// Problem dims: N=8, C=64, COUT=128, T=V=256, S=3, IC=32, P=T*V=65536
// ---------------------------------------------------------------------------
#define PP 65536

typedef unsigned long long u64;

__device__ __forceinline__ void ffma2(u64& d, u64 a, u64 b) {
    asm("fma.rn.f32x2 %0, %1, %2, %3;" : "=l"(d) : "l"(a), "l"(b), "l"(d));
}
__device__ __forceinline__ u64 bcast2(float x) {
    u64 r;
    asm("mov.b64 %0, {%1, %1};" : "=l"(r) : "r"(__float_as_uint(x)));
    return r;
}
__device__ __forceinline__ float2 unpk(u64 v) {
    unsigned a, b;
    asm("mov.b64 {%0, %1}, %2;" : "=r"(a), "=r"(b) : "l"(v));
    return make_float2(__uint_as_float(a), __uint_as_float(b));
}
__device__ __forceinline__ uint32_t smem_u32(const void* p) {
    uint32_t a;
    asm("{ .reg .u64 t; cvta.to.shared.u64 t, %1; cvt.u32.u64 %0, t; }"
        : "=r"(a) : "l"(p));
    return a;
}
__device__ __forceinline__ void ldsm_x4(uint32_t* r, uint32_t addr) {
    asm volatile("ldmatrix.sync.aligned.m8n8.x4.shared.b16 {%0,%1,%2,%3}, [%4];"
                 : "=r"(r[0]), "=r"(r[1]), "=r"(r[2]), "=r"(r[3]) : "r"(addr));
}
__device__ __forceinline__ void ldsm_x2(uint32_t* r, uint32_t addr) {
    asm volatile("ldmatrix.sync.aligned.m8n8.x2.shared.b16 {%0,%1}, [%2];"
                 : "=r"(r[0]), "=r"(r[1]) : "r"(addr));
}
__device__ __forceinline__ void mma_bf16(float* d, const uint32_t* a, const uint32_t* b) {
    asm volatile(
        "mma.sync.aligned.m16n8k16.row.col.f32.bf16.bf16.f32 "
        "{%0,%1,%2,%3}, {%4,%5,%6,%7}, {%8,%9}, {%0,%1,%2,%3};"
        : "+f"(d[0]), "+f"(d[1]), "+f"(d[2]), "+f"(d[3])
        : "r"(a[0]), "r"(a[1]), "r"(a[2]), "r"(a[3]), "r"(b[0]), "r"(b[1]));
}

// ------------------------- packed parameters -------------------------------
__device__ float g_Wab[256 * 64];
__device__ float g_Bab[256];
__device__ float g_Wcrt[256 * 64];
__device__ float g_Bcrt[256];
__device__ float g_Wd[128 * 192];
__device__ float g_Bd[128];
__device__ float g_bnp[1024];           // sg,hg, sc,hc, st,ht2, sr,hr
__device__ __nv_bfloat16 g_W9h[9 * 128 * 128];   // [k9][o][c] hi
__device__ __nv_bfloat16 g_W9l[9 * 128 * 128];   // lo

// ------------------------- scratch buffers ---------------------------------
__device__ float g_ab[134217728];       // [n][256][65536]
__device__ float g_adapt[1572864];      // [i*8+n][t][s]
__device__ float g_xa[100663296];
__device__ float g_y[67108864];
__device__ float g_crt[134217728];      // (cres | rt)
__device__ __nv_bfloat16 g_gTh[67108864];  // [n][h][w][c] hi
__device__ __nv_bfloat16 g_gTl[67108864];  // lo

// ---------------------------------------------------------------------------
__global__ void pack_kernel(const float* __restrict__ wa, const float* __restrict__ ba,
                            const float* __restrict__ wb, const float* __restrict__ bb,
                            const float* __restrict__ wd, const float* __restrict__ bd,
                            const float* __restrict__ cres_w, const float* __restrict__ cres_b,
                            const float* __restrict__ rt_w, const float* __restrict__ rt_b,
                            const float* __restrict__ gcn_bn, const float* __restrict__ cres_bn,
                            const float* __restrict__ tcn_bn, const float* __restrict__ rt_bn,
                            const float* __restrict__ tcn_w, const float* __restrict__ tcn_b)
{
    int tid = blockIdx.x * blockDim.x + threadIdx.x;
    int nth = gridDim.x * blockDim.x;
    for (int idx = tid; idx < 256 * 64; idx += nth) {
        int o = idx >> 6, c = idx & 63;
        int i = o >> 6, sub = o & 63;
        float v = 0.f;
        if (o < 192) v = (sub < 32) ? wa[(i * 32 + sub) * 64 + c]
                                    : wb[(i * 32 + sub - 32) * 64 + c];
        g_Wab[idx] = v;
    }
    for (int o = tid; o < 256; o += nth) {
        int i = o >> 6, sub = o & 63;
        float v = 0.f;
        if (o < 192) v = (sub < 32) ? ba[i * 32 + sub] : bb[i * 32 + sub - 32];
        g_Bab[o] = v;
    }
    for (int idx = tid; idx < 256 * 64; idx += nth) {
        int o = idx >> 6, c = idx & 63;
        g_Wcrt[idx] = (o < 128) ? cres_w[o * 64 + c] : rt_w[(o - 128) * 64 + c];
    }
    for (int o = tid; o < 256; o += nth)
        g_Bcrt[o] = (o < 128) ? cres_b[o] : rt_b[o - 128];
    for (int idx = tid; idx < 128 * 192; idx += nth) {
        int o = idx / 192, k = idx - o * 192;
        int i = k >> 6, c = k & 63;
        g_Wd[idx] = wd[(i * 128 + o) * 64 + c];
    }
    for (int o = tid; o < 128; o += nth)
        g_Bd[o] = bd[o] + bd[128 + o] + bd[256 + o];
    // TCN weights split to bf16 hi/lo: W9[k9][o][c] = tcn_w[o][c][k9]
    for (int idx = tid; idx < 9 * 128 * 128; idx += nth) {
        int k9 = idx >> 14;
        int rem = idx & 16383;
        int o = rem >> 7, c = rem & 127;
        float v = tcn_w[o * 1152 + c * 9 + k9];
        __nv_bfloat16 h = __float2bfloat16(v);
        g_W9h[idx] = h;
        g_W9l[idx] = __float2bfloat16(v - __bfloat162float(h));
    }
    for (int o = tid; o < 128; o += nth) {
        float g, b, m, v, s;
        g = gcn_bn[o]; b = gcn_bn[128 + o]; m = gcn_bn[256 + o]; v = gcn_bn[384 + o];
        s = g * rsqrtf(v + 1e-5f);
        g_bnp[o] = s; g_bnp[128 + o] = b - m * s;
        g = cres_bn[o]; b = cres_bn[128 + o]; m = cres_bn[256 + o]; v = cres_bn[384 + o];
        s = g * rsqrtf(v + 1e-5f);
        g_bnp[256 + o] = s; g_bnp[384 + o] = b - m * s;
        g = tcn_bn[o]; b = tcn_bn[128 + o]; m = tcn_bn[256 + o]; v = tcn_bn[384 + o];
        s = g * rsqrtf(v + 1e-5f);
        g_bnp[512 + o] = s; g_bnp[640 + o] = (tcn_b[o] - m) * s + b;
        g = rt_bn[o]; b = rt_bn[128 + o]; m = rt_bn[256 + o]; v = rt_bn[384 + o];
        s = g * rsqrtf(v + 1e-5f);
        g_bnp[768 + o] = s; g_bnp[896 + o] = b - m * s;
    }
}

// 8x8 fragment step on 128-wide tile, split-quad layout.
#define FRAG88(As_, Bs_, kk)                                                     \
    {                                                                            \
        float4 a0 = *(const float4*)&As_[kk][ty << 2];                           \
        float4 a1 = *(const float4*)&As_[kk][64 + (ty << 2)];                    \
        ulonglong2 b0 = *(const ulonglong2*)&Bs_[kk][tx << 2];                   \
        ulonglong2 b1 = *(const ulonglong2*)&Bs_[kk][64 + (tx << 2)];            \
        u64 ap[8] = {bcast2(a0.x), bcast2(a0.y), bcast2(a0.z), bcast2(a0.w),     \
                     bcast2(a1.x), bcast2(a1.y), bcast2(a1.z), bcast2(a1.w)};    \
        u64 bp[4] = {b0.x, b0.y, b1.x, b1.y};                                    \
        _Pragma("unroll")                                                        \
        for (int _i = 0; _i < 8; _i++)                                           \
            _Pragma("unroll")                                                    \
            for (int _j = 0; _j < 4; _j++)                                       \
                ffma2(acc2[_i][_j], ap[_i], bp[_j]);                             \
    }

#define ZERO_ACC()                                                               \
    u64 acc2[8][4];                                                              \
    _Pragma("unroll") for (int _i = 0; _i < 8; _i++)                             \
        _Pragma("unroll") for (int _j = 0; _j < 4; _j++) acc2[_i][_j] = 0ull;

#define FILL_A_T(rowptr_expr, k0)                                                \
    _Pragma("unroll")                                                            \
    for (int rr = 0; rr < 2; rr++) {                                             \
        int m_ = (tid >> 2) + (rr << 6);                                         \
        int kq_ = tid & 3;                                                       \
        float4 av = *(const float4*)((rowptr_expr) + (k0) + (kq_ << 2));         \
        As[(kq_ << 2) + 0][m_] = av.x;                                           \
        As[(kq_ << 2) + 1][m_] = av.y;                                           \
        As[(kq_ << 2) + 2][m_] = av.z;                                           \
        As[(kq_ << 2) + 3][m_] = av.w;                                           \
    }

// ---------------------------------------------------------------------------
template <int MODE>
__global__ __launch_bounds__(256, 2) void conv1x1_kernel(const float* __restrict__ x)
{
    const float* __restrict__ W    = MODE ? g_Wcrt : g_Wab;
    const float* __restrict__ bias = MODE ? g_Bcrt : g_Bab;
    float* __restrict__ out        = MODE ? g_crt  : g_ab;

    int pBlk = blockIdx.x << 7;
    int oBlk = blockIdx.y << 7;
    int n    = blockIdx.z;
    __shared__ __align__(16) float As[16][132];
    __shared__ __align__(16) float Bs[16][132];
    int tid = threadIdx.x;
    int tx = tid & 15, ty = tid >> 4;
    const float* xn = x + (size_t)n * 64 * PP;
    ZERO_ACC();

#pragma unroll
    for (int k0 = 0; k0 < 64; k0 += 16) {
        FILL_A_T(W + (oBlk + m_) * 64, k0)
#pragma unroll
        for (int rr = 0; rr < 2; rr++) {
            int r = (tid >> 5) + (rr << 3);
            int c2 = tid & 31;
            *(float4*)&Bs[r][c2 << 2] =
                *(const float4*)(xn + (size_t)(k0 + r) * PP + pBlk + (c2 << 2));
        }
        __syncthreads();
#pragma unroll
        for (int kk = 0; kk < 16; kk++) FRAG88(As, Bs, kk)
        __syncthreads();
    }
#pragma unroll
    for (int io = 0; io < 8; io++) {
        int o = oBlk + ((io >> 2) << 6) + (ty << 2) + (io & 3);
        float bi = bias[o];
#pragma unroll
        for (int jq = 0; jq < 2; jq++) {
            int col = (jq << 6) + (tx << 2);
            float2 p0 = unpk(acc2[io][jq * 2 + 0]);
            float2 p1 = unpk(acc2[io][jq * 2 + 1]);
            float4 r;
            r.x = p0.x + bi; r.y = p0.y + bi; r.z = p1.x + bi; r.w = p1.y + bi;
            *(float4*)(out + ((size_t)n * 256 + o) * PP + pBlk + col) = r;
        }
    }
}

// ---------------------------------------------------------------------------
__global__ __launch_bounds__(256, 2) void scores_kernel()
{
    int bz = blockIdx.z;
    int kh = bz & 1, b = bz >> 1;
    int i = b >> 3, n = b & 7;
    int sBlk = blockIdx.x << 7, tBlk = blockIdx.y << 7;
    const float* aBase = g_ab + ((size_t)n * 256 + i * 64) * PP;
    const float* bBase = aBase + (size_t)32 * PP;
    __shared__ __align__(16) float As[16][132];
    __shared__ __align__(16) float Bs[16][132];
    int tid = threadIdx.x;
    int tx = tid & 15, ty = tid >> 4;
    ZERO_ACC();

    int c0 = kh << 4;
    for (int c = c0; c < c0 + 16; c++) {
        const float* ac = aBase + (size_t)c * PP;
        const float* bc = bBase + (size_t)c * PP;
        for (int v0 = 0; v0 < 256; v0 += 16) {
            FILL_A_T(ac + (size_t)(tBlk + m_) * 256, v0)
#pragma unroll
            for (int rr = 0; rr < 2; rr++) {
                int m_ = (tid >> 2) + (rr << 6);
                int kq_ = tid & 3;
                float4 bv = *(const float4*)(bc + (size_t)(sBlk + m_) * 256 + v0 + (kq_ << 2));
                Bs[(kq_ << 2) + 0][m_] = bv.x;
                Bs[(kq_ << 2) + 1][m_] = bv.y;
                Bs[(kq_ << 2) + 2][m_] = bv.z;
                Bs[(kq_ << 2) + 3][m_] = bv.w;
            }
            __syncthreads();
#pragma unroll
            for (int kk = 0; kk < 16; kk++) FRAG88(As, Bs, kk)
            __syncthreads();
        }
    }
    float* dst = (kh ? g_xa : g_adapt) + (size_t)b * PP;
    const float sc = 1.0f / 256.0f;
#pragma unroll
    for (int io = 0; io < 8; io++) {
        int t = tBlk + ((io >> 2) << 6) + (ty << 2) + (io & 3);
#pragma unroll
        for (int jq = 0; jq < 2; jq++) {
            int col = sBlk + (jq << 6) + (tx << 2);
            float2 p0 = unpk(acc2[io][jq * 2 + 0]);
            float2 p1 = unpk(acc2[io][jq * 2 + 1]);
            float4 r;
            r.x = p0.x * sc; r.y = p0.y * sc; r.z = p1.x * sc; r.w = p1.y * sc;
            *(float4*)(dst + (size_t)t * 256 + col) = r;
        }
    }
}

// ---------------------------------------------------------------------------
__global__ __launch_bounds__(1024) void softmax_kernel(const float* __restrict__ mat_adj,
                                                       const float* __restrict__ adj_w)
{
    int b = blockIdx.x;
    int i = b >> 3;
    const float* p1 = g_adapt + (size_t)b * PP;
    const float* p2 = g_xa + (size_t)b * PP;
    float* dst = g_adapt + (size_t)b * PP;
    int s = threadIdx.x & 255, tq = threadIdx.x >> 8;
    __shared__ float red[4][256];
    int t0 = tq << 6, t1 = t0 + 64;
    float m = -1e30f;
    for (int t = t0; t < t1; t++) {
        int idx = t * 256 + s;
        m = fmaxf(m, p1[idx] + p2[idx]);
    }
    red[tq][s] = m;
    __syncthreads();
    m = fmaxf(fmaxf(red[0][s], red[1][s]), fmaxf(red[2][s], red[3][s]));
    __syncthreads();
    float sum = 0.f;
    for (int t = t0; t < t1; t++) {
        int idx = t * 256 + s;
        sum += expf(p1[idx] + p2[idx] - m);
    }
    red[tq][s] = sum;
    __syncthreads();
    sum = red[0][s] + red[1][s] + red[2][s] + red[3][s];
    float inv = 1.f / sum;
    const float* A1 = mat_adj + (size_t)i * PP;
    const float* A2 = adj_w + (size_t)i * PP;
    for (int t = t0; t < t1; t++) {
        int idx = t * 256 + s;
        float e = expf(p1[idx] + p2[idx] - m) * inv;
        dst[idx] = A1[idx] + A2[idx] + e;
    }
}

// ---------------------------------------------------------------------------
__global__ __launch_bounds__(256, 2) void xa_kernel(const float* __restrict__ x)
{
    int b2 = blockIdx.z;
    int c = b2 & 63, bn = b2 >> 6;
    int n = bn & 7;
    int sBlk = blockIdx.x << 7, vBlk = blockIdx.y << 7;
    const float* xb = x + ((size_t)n * 64 + c) * PP;
    const float* ad = g_adapt + (size_t)bn * PP;
    __shared__ __align__(16) float As[16][132];
    __shared__ __align__(16) float Bs[16][132];
    int tid = threadIdx.x;
    int tx = tid & 15, ty = tid >> 4;
    ZERO_ACC();

#pragma unroll 2
    for (int k0 = 0; k0 < 256; k0 += 16) {
#pragma unroll
        for (int rr = 0; rr < 2; rr++) {
            int r = (tid >> 5) + (rr << 3);
            int c2 = tid & 31;
            *(float4*)&As[r][c2 << 2] =
                *(const float4*)(xb + (size_t)(k0 + r) * 256 + vBlk + (c2 << 2));
            *(float4*)&Bs[r][c2 << 2] =
                *(const float4*)(ad + (size_t)(k0 + r) * 256 + sBlk + (c2 << 2));
        }
        __syncthreads();
#pragma unroll
        for (int kk = 0; kk < 16; kk++) FRAG88(As, Bs, kk)
        __syncthreads();
    }
    float* op = g_xa + (size_t)b2 * PP;
#pragma unroll
    for (int io = 0; io < 8; io++) {
        int v = vBlk + ((io >> 2) << 6) + (ty << 2) + (io & 3);
#pragma unroll
        for (int jq = 0; jq < 2; jq++) {
            int col = sBlk + (jq << 6) + (tx << 2);
            float2 p0 = unpk(acc2[io][jq * 2 + 0]);
            float2 p1 = unpk(acc2[io][jq * 2 + 1]);
            float4 r;
            r.x = p0.x; r.y = p0.y; r.z = p1.x; r.w = p1.y;
            *(float4*)(op + (size_t)v * 256 + col) = r;
        }
    }
}

// ---------------------------------------------------------------------------
__global__ __launch_bounds__(256, 2) void ygemm_kernel()
{
    int pBlk = blockIdx.x << 7;
    int n    = blockIdx.z;
    __shared__ __align__(16) float As[16][132];
    __shared__ __align__(16) float Bs[16][132];
    int tid = threadIdx.x;
    int tx = tid & 15, ty = tid >> 4;
    ZERO_ACC();

#pragma unroll
    for (int k0 = 0; k0 < 192; k0 += 16) {
        {
            int m_ = tid >> 1;
            int kq_ = tid & 1;
#pragma unroll
            for (int hh = 0; hh < 2; hh++) {
                float4 av = *(const float4*)(g_Wd + (size_t)m_ * 192 + k0 + ((kq_ * 2 + hh) << 2));
                int kb = ((kq_ * 2 + hh) << 2);
                As[kb + 0][m_] = av.x;
                As[kb + 1][m_] = av.y;
                As[kb + 2][m_] = av.z;
                As[kb + 3][m_] = av.w;
            }
        }
#pragma unroll
        for (int rr = 0; rr < 2; rr++) {
            int r = (tid >> 5) + (rr << 3);
            int c2 = tid & 31;
            int k = k0 + r;
            int i = k >> 6, cc = k & 63;
            *(float4*)&Bs[r][c2 << 2] =
                *(const float4*)(g_xa + (size_t)((i << 9) + (n << 6) + cc) * PP + pBlk + (c2 << 2));
        }
        __syncthreads();
#pragma unroll
        for (int kk = 0; kk < 16; kk++) FRAG88(As, Bs, kk)
        __syncthreads();
    }
#pragma unroll
    for (int io = 0; io < 8; io++) {
        int o = ((io >> 2) << 6) + (ty << 2) + (io & 3);
        float bi = g_Bd[o];
#pragma unroll
        for (int jq = 0; jq < 2; jq++) {
            int col = pBlk + (jq << 6) + (tx << 2);
            float2 p0 = unpk(acc2[io][jq * 2 + 0]);
            float2 p1 = unpk(acc2[io][jq * 2 + 1]);
            float4 r;
            r.x = p0.x + bi; r.y = p0.y + bi; r.z = p1.x + bi; r.w = p1.y + bi;
            *(float4*)(g_y + ((size_t)(n * 128) + o) * PP + col) = r;
        }
    }
}

// ---------------------------------------------------------------------------
// gcnT = relu(bn_g(y) + bn_c(cres)), written channel-last as bf16 hi/lo:
// g_gT*[((n*256+h)*256+w)*128 + c].  Tile 128c x 64w per block via smem.
// ---------------------------------------------------------------------------
__global__ __launch_bounds__(256) void gcnT_kernel()
{
    int wBlk = blockIdx.x << 6;
    int h    = blockIdx.y;
    int n    = blockIdx.z;
    __shared__ float ts[64][129];
    int tid = threadIdx.x;
    int wl = tid & 63, cg = tid >> 6;
#pragma unroll 8
    for (int c = cg; c < 128; c += 4) {
        float sg = g_bnp[c], hg = g_bnp[128 + c];
        float sc = g_bnp[256 + c], hc = g_bnp[384 + c];
        float yv = g_y[(size_t)(n * 128 + c) * PP + h * 256 + wBlk + wl];
        float cv = g_crt[(size_t)(n * 256 + c) * PP + h * 256 + wBlk + wl];
        ts[wl][c] = fmaxf(yv * sg + hg + cv * sc + hc, 0.f);
    }
    __syncthreads();
    int c2 = (tid & 63) << 1;
    int w0 = tid >> 6;
#pragma unroll 8
    for (int w = w0; w < 64; w += 4) {
        float v0 = ts[w][c2], v1 = ts[w][c2 + 1];
        __nv_bfloat16 h0 = __float2bfloat16(v0), h1 = __float2bfloat16(v1);
        __nv_bfloat16 l0 = __float2bfloat16(v0 - __bfloat162float(h0));
        __nv_bfloat16 l1 = __float2bfloat16(v1 - __bfloat162float(h1));
        size_t base = ((size_t)(n * 256 + h) * 256 + wBlk + w) * 128 + c2;
        __nv_bfloat162 ph; ph.x = h0; ph.y = h1;
        __nv_bfloat162 pl; pl.x = l0; pl.y = l1;
        *(__nv_bfloat162*)(g_gTh + base) = ph;
        *(__nv_bfloat162*)(g_gTl + base) = pl;
    }
}

// ---------------------------------------------------------------------------
// TCN via mma.sync bf16 (3-term hi/lo split), fp32 register accumulation.
// Block: 128(o) x 128(w) at fixed (n, h).  8 warps = 4(o) x 2(w); warp tile
// 32(o) x 64(w) = 2 x 8 m16n8k16 tiles.  K = 9 taps x 128 c (k16 chunks).
// Epilogue fused: out = relu(D*st + ht + rt*sr + hr).
// SMEM: A hi/lo + B hi/lo, 128 rows x 136 bf16 pitch each (136 = conflict-free).
// ---------------------------------------------------------------------------
#define SMP 136
__global__ __launch_bounds__(256) void tcn_mma_kernel(float* __restrict__ out)
{
    extern __shared__ __align__(16) __nv_bfloat16 sm[];
    __nv_bfloat16* sAh = sm;
    __nv_bfloat16* sAl = sm + 128 * SMP;
    __nv_bfloat16* sBh = sm + 2 * 128 * SMP;
    __nv_bfloat16* sBl = sm + 3 * 128 * SMP;

    int wBlk = blockIdx.x << 7;
    int h    = blockIdx.y;
    int n    = blockIdx.z;
    int tid  = threadIdx.x;
    int warp = tid >> 5, lane = tid & 31;
    int warpO = warp & 3, warpW = warp >> 2;

    float d[2][8][4];
#pragma unroll
    for (int i = 0; i < 2; i++)
#pragma unroll
        for (int j = 0; j < 8; j++)
#pragma unroll
            for (int k = 0; k < 4; k++) d[i][j][k] = 0.f;

    // ldmatrix base addresses (byte offsets into smem window)
    uint32_t uAh = smem_u32(sAh), uAl = smem_u32(sAl);
    uint32_t uBh = smem_u32(sBh), uBl = smem_u32(sBl);
    int aRow = warpO * 32 + (lane & 15);            // A: rows m, col sel by lane>>4
    int aColSel = (lane >> 4) << 3;
    int l16 = lane & 15;
    int bRowOff = warpW * 64 + (l16 & 7);           // B: rows n(=w), col sel
    int bColSel = ((l16 >> 3) & 1) << 3;

    for (int k9 = 0; k9 < 9; k9++) {
        int hs = h + k9 - 4;
        if ((unsigned)hs >= 256u) continue;
        __syncthreads();
        // ---- cooperative smem fill: A = W9[k9] (128o x 128c), B = gcnT row panel
        {
            const uint4* whv = (const uint4*)(g_W9h + k9 * 16384);
            const uint4* wlv = (const uint4*)(g_W9l + k9 * 16384);
            size_t gbase = ((size_t)(n * 256 + hs) * 256 + wBlk) * 128;
            const uint4* bhv = (const uint4*)(g_gTh + gbase);
            const uint4* blv = (const uint4*)(g_gTl + gbase);
#pragma unroll
            for (int t = 0; t < 8; t++) {
                int idx = tid + t * 256;            // 2048 uint4 per operand
                int r = idx >> 4, c8 = idx & 15;
                int doff = r * SMP + (c8 << 3);     // element offset
                *(uint4*)(sAh + doff) = whv[idx];
                *(uint4*)(sAl + doff) = wlv[idx];
                *(uint4*)(sBh + doff) = bhv[idx];
                *(uint4*)(sBl + doff) = blv[idx];
            }
        }
        __syncthreads();
        // ---- compute: 8 k16 chunks
#pragma unroll
        for (int kc = 0; kc < 8; kc++) {
            int c0 = kc << 4;
            uint32_t ah[2][4], al[2][4];
#pragma unroll
            for (int mt = 0; mt < 2; mt++) {
                uint32_t off = (uint32_t)(((aRow + mt * 16) * SMP + c0 + aColSel) << 1);
                ldsm_x4(ah[mt], uAh + off);
                ldsm_x4(al[mt], uAl + off);
            }
            uint32_t bh[8][2], bl[8][2];
#pragma unroll
            for (int nt = 0; nt < 8; nt++) {
                uint32_t off = (uint32_t)(((bRowOff + nt * 8) * SMP + c0 + bColSel) << 1);
                ldsm_x2(bh[nt], uBh + off);
                ldsm_x2(bl[nt], uBl + off);
            }
#pragma unroll
            for (int mt = 0; mt < 2; mt++)
#pragma unroll
                for (int nt = 0; nt < 8; nt++) {
                    mma_bf16(d[mt][nt], ah[mt], bh[nt]);
                    mma_bf16(d[mt][nt], ah[mt], bl[nt]);
                    mma_bf16(d[mt][nt], al[mt], bh[nt]);
                }
        }
    }

    // ---- epilogue: relu(D*st + ht + rt*sr + hr)
    int oB = warpO * 32;
    int wB = wBlk + warpW * 64;
#pragma unroll
    for (int mt = 0; mt < 2; mt++) {
        int o0 = oB + mt * 16 + (lane >> 2);
#pragma unroll
        for (int half = 0; half < 2; half++) {
            int o = o0 + half * 8;
            float st = g_bnp[512 + o], ht = g_bnp[640 + o];
            float sr = g_bnp[768 + o], hr = g_bnp[896 + o];
            size_t ob = ((size_t)(n * 128 + o) * 256 + h) * 256;
            size_t rb = ((size_t)(n * 256 + 128 + o) * 256 + h) * 256;
#pragma unroll
            for (int nt = 0; nt < 8; nt++) {
                int w = wB + nt * 8 + ((lane & 3) << 1);
                float2 rv = *(const float2*)(g_crt + rb + w);
                float v0 = d[mt][nt][half * 2 + 0];
                float v1 = d[mt][nt][half * 2 + 1];
                float2 ov;
                ov.x = fmaxf(v0 * st + ht + rv.x * sr + hr, 0.f);
                ov.y = fmaxf(v1 * st + ht + rv.y * sr + hr, 0.f);
                *(float2*)(out + ob + w) = ov;
            }
        }
    }
}

// ---------------------------------------------------------------------------
extern "C" void kernel_launch(void* const* d_in, const int* in_sizes, int n_in,
                              void* d_out, int out_size)
{
    const float* x       = (const float*)d_in[0];
    const float* mat_adj = (const float*)d_in[1];
    const float* adj_w   = (const float*)d_in[2];
    const float* wa      = (const float*)d_in[3];
    const float* ba      = (const float*)d_in[4];
    const float* wb      = (const float*)d_in[5];
    const float* bb      = (const float*)d_in[6];
    const float* wd      = (const float*)d_in[7];
    const float* bd      = (const float*)d_in[8];
    const float* gcn_bn  = (const float*)d_in[9];
    const float* cres_w  = (const float*)d_in[10];
    const float* cres_b  = (const float*)d_in[11];
    const float* cres_bn = (const float*)d_in[12];
    const float* tcn_w   = (const float*)d_in[13];
    const float* tcn_b   = (const float*)d_in[14];
    const float* tcn_bn  = (const float*)d_in[15];
    const float* rt_w    = (const float*)d_in[16];
    const float* rt_b    = (const float*)d_in[17];
    const float* rt_bn   = (const float*)d_in[18];
    float* out = (float*)d_out;

    const int tcn_smem = 4 * 128 * SMP * 2;   // 139264 bytes
    cudaFuncSetAttribute(tcn_mma_kernel,
                         cudaFuncAttributeMaxDynamicSharedMemorySize, tcn_smem);

    pack_kernel<<<128, 256>>>(wa, ba, wb, bb, wd, bd, cres_w, cres_b,
                              rt_w, rt_b, gcn_bn, cres_bn, tcn_bn, rt_bn,
                              tcn_w, tcn_b);
    conv1x1_kernel<0><<<dim3(512, 2, 8), 256>>>(x);
    conv1x1_kernel<1><<<dim3(512, 2, 8), 256>>>(x);
    scores_kernel<<<dim3(2, 2, 48), 256>>>();
    softmax_kernel<<<24, 1024>>>(mat_adj, adj_w);
    xa_kernel<<<dim3(2, 2, 1536), 256>>>(x);
    ygemm_kernel<<<dim3(512, 1, 8), 256>>>();
    gcnT_kernel<<<dim3(4, 256, 8), 256>>>();
    tcn_mma_kernel<<<dim3(2, 256, 8), 256, tcn_smem>>>(out);
}

// round 8
// speedup vs baseline: 3.0268x; 1.1626x over previous
#include <cuda_runtime.h>
#include <cuda_bf16.h>
#include <math.h>
#include <stdint.h>

// ---------------------------------------------------------------------------
// Problem dims: N=8, C=64, COUT=128, T=V=256, S=3, IC=32, P=T*V=65536
// ---------------------------------------------------------------------------
#define PP 65536

typedef unsigned long long u64;

__device__ __forceinline__ void ffma2(u64& d, u64 a, u64 b) {
    asm("fma.rn.f32x2 %0, %1, %2, %3;" : "=l"(d) : "l"(a), "l"(b), "l"(d));
}
__device__ __forceinline__ u64 bcast2(float x) {
    u64 r;
    asm("mov.b64 %0, {%1, %1};" : "=l"(r) : "r"(__float_as_uint(x)));
    return r;
}
__device__ __forceinline__ float2 unpk(u64 v) {
    unsigned a, b;
    asm("mov.b64 {%0, %1}, %2;" : "=r"(a), "=r"(b) : "l"(v));
    return make_float2(__uint_as_float(a), __uint_as_float(b));
}
__device__ __forceinline__ uint32_t smem_u32(const void* p) {
    uint32_t a;
    asm("{ .reg .u64 t; cvta.to.shared.u64 t, %1; cvt.u32.u64 %0, t; }"
        : "=r"(a) : "l"(p));
    return a;
}
__device__ __forceinline__ void ldsm_x4(uint32_t* r, uint32_t addr) {
    asm volatile("ldmatrix.sync.aligned.m8n8.x4.shared.b16 {%0,%1,%2,%3}, [%4];"
                 : "=r"(r[0]), "=r"(r[1]), "=r"(r[2]), "=r"(r[3]) : "r"(addr));
}
__device__ __forceinline__ void ldsm_x2(uint32_t* r, uint32_t addr) {
    asm volatile("ldmatrix.sync.aligned.m8n8.x2.shared.b16 {%0,%1}, [%2];"
                 : "=r"(r[0]), "=r"(r[1]) : "r"(addr));
}
__device__ __forceinline__ void ldsm_x4_t(uint32_t* r, uint32_t addr) {
    asm volatile("ldmatrix.sync.aligned.m8n8.x4.trans.shared.b16 {%0,%1,%2,%3}, [%4];"
                 : "=r"(r[0]), "=r"(r[1]), "=r"(r[2]), "=r"(r[3]) : "r"(addr));
}
__device__ __forceinline__ void ldsm_x2_t(uint32_t* r, uint32_t addr) {
    asm volatile("ldmatrix.sync.aligned.m8n8.x2.trans.shared.b16 {%0,%1}, [%2];"
                 : "=r"(r[0]), "=r"(r[1]) : "r"(addr));
}
__device__ __forceinline__ void mma_bf16(float* d, const uint32_t* a, const uint32_t* b) {
    asm volatile(
        "mma.sync.aligned.m16n8k16.row.col.f32.bf16.bf16.f32 "
        "{%0,%1,%2,%3}, {%4,%5,%6,%7}, {%8,%9}, {%0,%1,%2,%3};"
        : "+f"(d[0]), "+f"(d[1]), "+f"(d[2]), "+f"(d[3])
        : "r"(a[0]), "r"(a[1]), "r"(a[2]), "r"(a[3]), "r"(b[0]), "r"(b[1]));
}
__device__ __forceinline__ void bsplit(float v, __nv_bfloat16& h, __nv_bfloat16& l) {
    h = __float2bfloat16(v);
    l = __float2bfloat16(v - __bfloat162float(h));
}

// ------------------------- packed parameters -------------------------------
__device__ float g_Wab[256 * 64];
__device__ float g_Bab[256];
__device__ float g_Wcrt[256 * 64];
__device__ float g_Bcrt[256];
__device__ float g_Wd[128 * 192];
__device__ float g_Bd[128];
__device__ float g_bnp[1024];           // sg,hg, sc,hc, st,ht2, sr,hr
__device__ __nv_bfloat16 g_W9h[9 * 128 * 128];   // [k9][o][c] hi
__device__ __nv_bfloat16 g_W9l[9 * 128 * 128];   // lo

// ------------------------- scratch buffers ---------------------------------
__device__ __nv_bfloat16 g_abh[134217728]; // [n][256][PP] embeds hi (rows 192+ pad)
__device__ __nv_bfloat16 g_abl[134217728]; // lo
__device__ __nv_bfloat16 g_xh[33554432];   // [n][64][t][v] x hi
__device__ __nv_bfloat16 g_xl[33554432];   // lo
__device__ __nv_bfloat16 g_adh[1572864];   // [bn][t][s] adapt hi
__device__ __nv_bfloat16 g_adl[1572864];   // lo
__device__ float g_adapt[1572864];         // fp32 scores partial (kh=0)
__device__ float g_xa[100663296];          // xa out; head = scores partial (kh=1)
__device__ float g_y[67108864];            // [n][128][PP]
__device__ float g_crt[134217728];         // (cres | rt)
__device__ __nv_bfloat16 g_gTh[67108864];  // [n][h][w][c] hi
__device__ __nv_bfloat16 g_gTl[67108864];  // lo

// ---------------------------------------------------------------------------
__global__ void pack_kernel(const float* __restrict__ wa, const float* __restrict__ ba,
                            const float* __restrict__ wb, const float* __restrict__ bb,
                            const float* __restrict__ wd, const float* __restrict__ bd,
                            const float* __restrict__ cres_w, const float* __restrict__ cres_b,
                            const float* __restrict__ rt_w, const float* __restrict__ rt_b,
                            const float* __restrict__ gcn_bn, const float* __restrict__ cres_bn,
                            const float* __restrict__ tcn_bn, const float* __restrict__ rt_bn,
                            const float* __restrict__ tcn_w, const float* __restrict__ tcn_b)
{
    int tid = blockIdx.x * blockDim.x + threadIdx.x;
    int nth = gridDim.x * blockDim.x;
    for (int idx = tid; idx < 256 * 64; idx += nth) {
        int o = idx >> 6, c = idx & 63;
        int i = o >> 6, sub = o & 63;
        float v = 0.f;
        if (o < 192) v = (sub < 32) ? wa[(i * 32 + sub) * 64 + c]
                                    : wb[(i * 32 + sub - 32) * 64 + c];
        g_Wab[idx] = v;
    }
    for (int o = tid; o < 256; o += nth) {
        int i = o >> 6, sub = o & 63;
        float v = 0.f;
        if (o < 192) v = (sub < 32) ? ba[i * 32 + sub] : bb[i * 32 + sub - 32];
        g_Bab[o] = v;
    }
    for (int idx = tid; idx < 256 * 64; idx += nth) {
        int o = idx >> 6, c = idx & 63;
        g_Wcrt[idx] = (o < 128) ? cres_w[o * 64 + c] : rt_w[(o - 128) * 64 + c];
    }
    for (int o = tid; o < 256; o += nth)
        g_Bcrt[o] = (o < 128) ? cres_b[o] : rt_b[o - 128];
    for (int idx = tid; idx < 128 * 192; idx += nth) {
        int o = idx / 192, k = idx - o * 192;
        int i = k >> 6, c = k & 63;
        g_Wd[idx] = wd[(i * 128 + o) * 64 + c];
    }
    for (int o = tid; o < 128; o += nth)
        g_Bd[o] = bd[o] + bd[128 + o] + bd[256 + o];
    for (int idx = tid; idx < 9 * 128 * 128; idx += nth) {
        int k9 = idx >> 14;
        int rem = idx & 16383;
        int o = rem >> 7, c = rem & 127;
        float v = tcn_w[o * 1152 + c * 9 + k9];
        __nv_bfloat16 h, l;
        bsplit(v, h, l);
        g_W9h[idx] = h; g_W9l[idx] = l;
    }
    for (int o = tid; o < 128; o += nth) {
        float g, b, m, v, s;
        g = gcn_bn[o]; b = gcn_bn[128 + o]; m = gcn_bn[256 + o]; v = gcn_bn[384 + o];
        s = g * rsqrtf(v + 1e-5f);
        g_bnp[o] = s; g_bnp[128 + o] = b - m * s;
        g = cres_bn[o]; b = cres_bn[128 + o]; m = cres_bn[256 + o]; v = cres_bn[384 + o];
        s = g * rsqrtf(v + 1e-5f);
        g_bnp[256 + o] = s; g_bnp[384 + o] = b - m * s;
        g = tcn_bn[o]; b = tcn_bn[128 + o]; m = tcn_bn[256 + o]; v = tcn_bn[384 + o];
        s = g * rsqrtf(v + 1e-5f);
        g_bnp[512 + o] = s; g_bnp[640 + o] = (tcn_b[o] - m) * s + b;
        g = rt_bn[o]; b = rt_bn[128 + o]; m = rt_bn[256 + o]; v = rt_bn[384 + o];
        s = g * rsqrtf(v + 1e-5f);
        g_bnp[768 + o] = s; g_bnp[896 + o] = b - m * s;
    }
}

// ---------------------------------------------------------------------------
// x -> bf16 hi/lo split (same layout)
// ---------------------------------------------------------------------------
__global__ __launch_bounds__(256) void xsplit_kernel(const float* __restrict__ x)
{
    size_t i = (size_t)blockIdx.x * 256 + threadIdx.x;   // 8388608 float4
    float4 v = ((const float4*)x)[i];
    __nv_bfloat16 h0, l0, h1, l1, h2, l2, h3, l3;
    bsplit(v.x, h0, l0); bsplit(v.y, h1, l1);
    bsplit(v.z, h2, l2); bsplit(v.w, h3, l3);
    __nv_bfloat162 ph0; ph0.x = h0; ph0.y = h1;
    __nv_bfloat162 ph1; ph1.x = h2; ph1.y = h3;
    __nv_bfloat162 pl0; pl0.x = l0; pl0.y = l1;
    __nv_bfloat162 pl1; pl1.x = l2; pl1.y = l3;
    *(__nv_bfloat162*)(g_xh + i * 4) = ph0;
    *(__nv_bfloat162*)(g_xh + i * 4 + 2) = ph1;
    *(__nv_bfloat162*)(g_xl + i * 4) = pl0;
    *(__nv_bfloat162*)(g_xl + i * 4 + 2) = pl1;
}

// 8x8 fragment step (FFMA2 path, kept for conv1x1/ygemm)
#define FRAG88(As_, Bs_, kk)                                                     \
    {                                                                            \
        float4 a0 = *(const float4*)&As_[kk][ty << 2];                           \
        float4 a1 = *(const float4*)&As_[kk][64 + (ty << 2)];                    \
        ulonglong2 b0 = *(const ulonglong2*)&Bs_[kk][tx << 2];                   \
        ulonglong2 b1 = *(const ulonglong2*)&Bs_[kk][64 + (tx << 2)];            \
        u64 ap[8] = {bcast2(a0.x), bcast2(a0.y), bcast2(a0.z), bcast2(a0.w),     \
                     bcast2(a1.x), bcast2(a1.y), bcast2(a1.z), bcast2(a1.w)};    \
        u64 bp[4] = {b0.x, b0.y, b1.x, b1.y};                                    \
        _Pragma("unroll")                                                        \
        for (int _i = 0; _i < 8; _i++)                                           \
            _Pragma("unroll")                                                    \
            for (int _j = 0; _j < 4; _j++)                                       \
                ffma2(acc2[_i][_j], ap[_i], bp[_j]);                             \
    }

#define ZERO_ACC()                                                               \
    u64 acc2[8][4];                                                              \
    _Pragma("unroll") for (int _i = 0; _i < 8; _i++)                             \
        _Pragma("unroll") for (int _j = 0; _j < 4; _j++) acc2[_i][_j] = 0ull;

#define FILL_A_T(rowptr_expr, k0)                                                \
    _Pragma("unroll")                                                            \
    for (int rr = 0; rr < 2; rr++) {                                             \
        int m_ = (tid >> 2) + (rr << 6);                                         \
        int kq_ = tid & 3;                                                       \
        float4 av = *(const float4*)((rowptr_expr) + (k0) + (kq_ << 2));         \
        As[(kq_ << 2) + 0][m_] = av.x;                                           \
        As[(kq_ << 2) + 1][m_] = av.y;                                           \
        As[(kq_ << 2) + 2][m_] = av.z;                                           \
        As[(kq_ << 2) + 3][m_] = av.w;                                           \
    }

// ---------------------------------------------------------------------------
// conv1x1 (FFMA2): MODE 0 -> ab embeds, output bf16 hi/lo; MODE 1 -> crt fp32
// ---------------------------------------------------------------------------
template <int MODE>
__global__ __launch_bounds__(256, 2) void conv1x1_kernel(const float* __restrict__ x)
{
    const float* __restrict__ W    = MODE ? g_Wcrt : g_Wab;
    const float* __restrict__ bias = MODE ? g_Bcrt : g_Bab;

    int pBlk = blockIdx.x << 7;
    int oBlk = blockIdx.y << 7;
    int n    = blockIdx.z;
    __shared__ __align__(16) float As[16][132];
    __shared__ __align__(16) float Bs[16][132];
    int tid = threadIdx.x;
    int tx = tid & 15, ty = tid >> 4;
    const float* xn = x + (size_t)n * 64 * PP;
    ZERO_ACC();

#pragma unroll
    for (int k0 = 0; k0 < 64; k0 += 16) {
        FILL_A_T(W + (oBlk + m_) * 64, k0)
#pragma unroll
        for (int rr = 0; rr < 2; rr++) {
            int r = (tid >> 5) + (rr << 3);
            int c2 = tid & 31;
            *(float4*)&Bs[r][c2 << 2] =
                *(const float4*)(xn + (size_t)(k0 + r) * PP + pBlk + (c2 << 2));
        }
        __syncthreads();
#pragma unroll
        for (int kk = 0; kk < 16; kk++) FRAG88(As, Bs, kk)
        __syncthreads();
    }
#pragma unroll
    for (int io = 0; io < 8; io++) {
        int o = oBlk + ((io >> 2) << 6) + (ty << 2) + (io & 3);
        float bi = bias[o];
        size_t base = ((size_t)n * 256 + o) * PP + pBlk;
#pragma unroll
        for (int jq = 0; jq < 2; jq++) {
            int col = (jq << 6) + (tx << 2);
            float2 p0 = unpk(acc2[io][jq * 2 + 0]);
            float2 p1 = unpk(acc2[io][jq * 2 + 1]);
            float vv[4] = {p0.x + bi, p0.y + bi, p1.x + bi, p1.y + bi};
            if (MODE) {
                *(float4*)(g_crt + base + col) = make_float4(vv[0], vv[1], vv[2], vv[3]);
            } else {
                __nv_bfloat16 h0, l0, h1, l1, h2, l2, h3, l3;
                bsplit(vv[0], h0, l0); bsplit(vv[1], h1, l1);
                bsplit(vv[2], h2, l2); bsplit(vv[3], h3, l3);
                __nv_bfloat162 ph0; ph0.x = h0; ph0.y = h1;
                __nv_bfloat162 ph1; ph1.x = h2; ph1.y = h3;
                __nv_bfloat162 pl0; pl0.x = l0; pl0.y = l1;
                __nv_bfloat162 pl1; pl1.x = l2; pl1.y = l3;
                *(__nv_bfloat162*)(g_abh + base + col) = ph0;
                *(__nv_bfloat162*)(g_abh + base + col + 2) = ph1;
                *(__nv_bfloat162*)(g_abl + base + col) = pl0;
                *(__nv_bfloat162*)(g_abl + base + col + 2) = pl1;
            }
        }
    }
}

// ---------------------------------------------------------------------------
// scores via mma.sync (3-term split), split-K=2 over c.
// Block: 128(t) x 128(s); A = a-embed [t][v] row-major, B = b-embed [s][v].
// ---------------------------------------------------------------------------
#define SMP 136
__global__ __launch_bounds__(256) void scores_mma_kernel()
{
    extern __shared__ __align__(16) __nv_bfloat16 sm[];
    __nv_bfloat16* sAh = sm;
    __nv_bfloat16* sAl = sm + 128 * SMP;
    __nv_bfloat16* sBh = sm + 2 * 128 * SMP;
    __nv_bfloat16* sBl = sm + 3 * 128 * SMP;

    int kh = blockIdx.z & 1, b = blockIdx.z >> 1;
    int i = b >> 3, n = b & 7;
    int sBlk = blockIdx.x << 7, tBlk = blockIdx.y << 7;
    size_t aOff = ((size_t)n * 256 + i * 64) * PP;
    size_t bOff = aOff + (size_t)32 * PP;

    int tid = threadIdx.x;
    int warp = tid >> 5, lane = tid & 31;
    int warpO = warp & 3, warpW = warp >> 2;

    float d[2][8][4];
#pragma unroll
    for (int a = 0; a < 2; a++)
#pragma unroll
        for (int bq = 0; bq < 8; bq++)
#pragma unroll
            for (int k = 0; k < 4; k++) d[a][bq][k] = 0.f;

    uint32_t uAh = smem_u32(sAh), uAl = smem_u32(sAl);
    uint32_t uBh = smem_u32(sBh), uBl = smem_u32(sBl);
    int aRow = warpO * 32 + (lane & 15);
    int aColSel = (lane >> 4) << 3;
    int l16 = lane & 15;
    int bRowOff = warpW * 64 + (l16 & 7);
    int bColSel = ((l16 >> 3) & 1) << 3;

    int c0 = kh << 4;
    for (int c = c0; c < c0 + 16; c++) {
#pragma unroll 1
        for (int vh = 0; vh < 2; vh++) {
            int v0 = vh << 7;
            __syncthreads();
            const __nv_bfloat16* aH = g_abh + aOff + (size_t)c * PP;
            const __nv_bfloat16* aL = g_abl + aOff + (size_t)c * PP;
            const __nv_bfloat16* bH = g_abh + bOff + (size_t)c * PP;
            const __nv_bfloat16* bL = g_abl + bOff + (size_t)c * PP;
#pragma unroll
            for (int t = 0; t < 8; t++) {
                int idx = tid + t * 256;
                int r = idx >> 4, c8 = idx & 15;
                int doff = r * SMP + (c8 << 3);
                *(uint4*)(sAh + doff) = *(const uint4*)(aH + (size_t)(tBlk + r) * 256 + v0 + (c8 << 3));
                *(uint4*)(sAl + doff) = *(const uint4*)(aL + (size_t)(tBlk + r) * 256 + v0 + (c8 << 3));
                *(uint4*)(sBh + doff) = *(const uint4*)(bH + (size_t)(sBlk + r) * 256 + v0 + (c8 << 3));
                *(uint4*)(sBl + doff) = *(const uint4*)(bL + (size_t)(sBlk + r) * 256 + v0 + (c8 << 3));
            }
            __syncthreads();
#pragma unroll
            for (int kc = 0; kc < 8; kc++) {
                int k16 = kc << 4;
                uint32_t ah[2][4], al[2][4];
#pragma unroll
                for (int mt = 0; mt < 2; mt++) {
                    uint32_t off = (uint32_t)(((aRow + mt * 16) * SMP + k16 + aColSel) << 1);
                    ldsm_x4(ah[mt], uAh + off);
                    ldsm_x4(al[mt], uAl + off);
                }
                uint32_t bh[8][2], bl[8][2];
#pragma unroll
                for (int nt = 0; nt < 8; nt++) {
                    uint32_t off = (uint32_t)(((bRowOff + nt * 8) * SMP + k16 + bColSel) << 1);
                    ldsm_x2(bh[nt], uBh + off);
                    ldsm_x2(bl[nt], uBl + off);
                }
#pragma unroll
                for (int mt = 0; mt < 2; mt++)
#pragma unroll
                    for (int nt = 0; nt < 8; nt++) {
                        mma_bf16(d[mt][nt], ah[mt], bh[nt]);
                        mma_bf16(d[mt][nt], ah[mt], bl[nt]);
                        mma_bf16(d[mt][nt], al[mt], bh[nt]);
                    }
            }
        }
    }

    float* dst = (kh ? g_xa : g_adapt) + (size_t)b * PP;
    const float sc = 1.0f / 256.0f;
#pragma unroll
    for (int mt = 0; mt < 2; mt++) {
        int t0 = tBlk + warpO * 32 + mt * 16 + (lane >> 2);
#pragma unroll
        for (int half = 0; half < 2; half++) {
            int t = t0 + half * 8;
#pragma unroll
            for (int nt = 0; nt < 8; nt++) {
                int s = sBlk + warpW * 64 + nt * 8 + ((lane & 3) << 1);
                float2 ov;
                ov.x = d[mt][nt][half * 2 + 0] * sc;
                ov.y = d[mt][nt][half * 2 + 1] * sc;
                *(float2*)(dst + (size_t)t * 256 + s) = ov;
            }
        }
    }
}

// ---------------------------------------------------------------------------
// softmax over t per column s on (g_adapt + g_xa partials),
// adapt = mat_adj + adj_w + att -> bf16 hi/lo (g_adh/g_adl).
// ---------------------------------------------------------------------------
__global__ __launch_bounds__(1024) void softmax_kernel(const float* __restrict__ mat_adj,
                                                       const float* __restrict__ adj_w)
{
    int b = blockIdx.x;
    int i = b >> 3;
    const float* p1 = g_adapt + (size_t)b * PP;
    const float* p2 = g_xa + (size_t)b * PP;
    int s = threadIdx.x & 255, tq = threadIdx.x >> 8;
    __shared__ float red[4][256];
    int t0 = tq << 6, t1 = t0 + 64;
    float m = -1e30f;
    for (int t = t0; t < t1; t++) {
        int idx = t * 256 + s;
        m = fmaxf(m, p1[idx] + p2[idx]);
    }
    red[tq][s] = m;
    __syncthreads();
    m = fmaxf(fmaxf(red[0][s], red[1][s]), fmaxf(red[2][s], red[3][s]));
    __syncthreads();
    float sum = 0.f;
    for (int t = t0; t < t1; t++) {
        int idx = t * 256 + s;
        sum += expf(p1[idx] + p2[idx] - m);
    }
    red[tq][s] = sum;
    __syncthreads();
    sum = red[0][s] + red[1][s] + red[2][s] + red[3][s];
    float inv = 1.f / sum;
    const float* A1 = mat_adj + (size_t)i * PP;
    const float* A2 = adj_w + (size_t)i * PP;
    __nv_bfloat16* dh = g_adh + (size_t)b * PP;
    __nv_bfloat16* dl = g_adl + (size_t)b * PP;
    for (int t = t0; t < t1; t++) {
        int idx = t * 256 + s;
        float e = expf(p1[idx] + p2[idx] - m) * inv;
        float v = A1[idx] + A2[idx] + e;
        __nv_bfloat16 h, l;
        bsplit(v, h, l);
        dh[idx] = h; dl[idx] = l;
    }
}

// ---------------------------------------------------------------------------
// xa via mma.sync (3-term split), trans ldmatrix for both operands.
// xa[b2][v][s] = sum_t x[n,c,t,v] * adapt[bn,t,s]; block 128v x 128s, K=256.
// A stored [t][v] (k-major) -> ldsm.trans; B stored [t][s] -> ldsm.trans.
// ---------------------------------------------------------------------------
__global__ __launch_bounds__(256) void xa_mma_kernel()
{
    extern __shared__ __align__(16) __nv_bfloat16 sm[];
    __nv_bfloat16* sAh = sm;
    __nv_bfloat16* sAl = sm + 128 * SMP;
    __nv_bfloat16* sBh = sm + 2 * 128 * SMP;
    __nv_bfloat16* sBl = sm + 3 * 128 * SMP;

    int b2 = blockIdx.z;
    int c = b2 & 63, bn = b2 >> 6;
    int n = bn & 7;
    int sBlk = blockIdx.x << 7, vBlk = blockIdx.y << 7;
    const __nv_bfloat16* xH = g_xh + ((size_t)n * 64 + c) * PP;
    const __nv_bfloat16* xL = g_xl + ((size_t)n * 64 + c) * PP;
    const __nv_bfloat16* aH = g_adh + (size_t)bn * PP;
    const __nv_bfloat16* aL = g_adl + (size_t)bn * PP;

    int tid = threadIdx.x;
    int warp = tid >> 5, lane = tid & 31;
    int warpV = warp & 3, warpS = warp >> 2;

    float d[2][8][4];
#pragma unroll
    for (int a = 0; a < 2; a++)
#pragma unroll
        for (int bq = 0; bq < 8; bq++)
#pragma unroll
            for (int k = 0; k < 4; k++) d[a][bq][k] = 0.f;

    uint32_t uAh = smem_u32(sAh), uAl = smem_u32(sAl);
    uint32_t uBh = smem_u32(sBh), uBl = smem_u32(sBl);
    // trans A: lanes 0-7: (t0-7, v0); 8-15: (t0-7, v+8); 16-23: (t8-15, v0); 24-31: (t8-15, v+8)
    int tRowA = (lane & 7) + ((lane & 16) >> 1);
    int vColA = ((lane >> 3) & 1) << 3;
    // trans B (x2, lanes 0-15): lanes 0-7 -> t0-7, lanes 8-15 -> t8-15, col = s
    int l16 = lane & 15;
    int tRowB = l16;

#pragma unroll 1
    for (int th = 0; th < 2; th++) {
        int t0 = th << 7;
        __syncthreads();
#pragma unroll
        for (int t = 0; t < 8; t++) {
            int idx = tid + t * 256;
            int r = idx >> 4, c8 = idx & 15;
            int doff = r * SMP + (c8 << 3);
            *(uint4*)(sAh + doff) = *(const uint4*)(xH + (size_t)(t0 + r) * 256 + vBlk + (c8 << 3));
            *(uint4*)(sAl + doff) = *(const uint4*)(xL + (size_t)(t0 + r) * 256 + vBlk + (c8 << 3));
            *(uint4*)(sBh + doff) = *(const uint4*)(aH + (size_t)(t0 + r) * 256 + sBlk + (c8 << 3));
            *(uint4*)(sBl + doff) = *(const uint4*)(aL + (size_t)(t0 + r) * 256 + sBlk + (c8 << 3));
        }
        __syncthreads();
#pragma unroll
        for (int kc = 0; kc < 8; kc++) {
            int k16 = kc << 4;
            uint32_t ah[2][4], al[2][4];
#pragma unroll
            for (int mt = 0; mt < 2; mt++) {
                int vCol = warpV * 32 + mt * 16 + vColA;
                uint32_t off = (uint32_t)(((k16 + tRowA) * SMP + vCol) << 1);
                ldsm_x4_t(ah[mt], uAh + off);
                ldsm_x4_t(al[mt], uAl + off);
            }
            uint32_t bh[8][2], bl[8][2];
#pragma unroll
            for (int nt = 0; nt < 8; nt++) {
                int sCol = warpS * 64 + nt * 8;
                uint32_t off = (uint32_t)(((k16 + tRowB) * SMP + sCol) << 1);
                ldsm_x2_t(bh[nt], uBh + off);
                ldsm_x2_t(bl[nt], uBl + off);
            }
#pragma unroll
            for (int mt = 0; mt < 2; mt++)
#pragma unroll
                for (int nt = 0; nt < 8; nt++) {
                    mma_bf16(d[mt][nt], ah[mt], bh[nt]);
                    mma_bf16(d[mt][nt], ah[mt], bl[nt]);
                    mma_bf16(d[mt][nt], al[mt], bh[nt]);
                }
        }
    }

    float* op = g_xa + (size_t)b2 * PP;
#pragma unroll
    for (int mt = 0; mt < 2; mt++) {
        int v0 = vBlk + warpV * 32 + mt * 16 + (lane >> 2);
#pragma unroll
        for (int half = 0; half < 2; half++) {
            int v = v0 + half * 8;
#pragma unroll
            for (int nt = 0; nt < 8; nt++) {
                int s = sBlk + warpS * 64 + nt * 8 + ((lane & 3) << 1);
                float2 ov;
                ov.x = d[mt][nt][half * 2 + 0];
                ov.y = d[mt][nt][half * 2 + 1];
                *(float2*)(op + (size_t)v * 256 + s) = ov;
            }
        }
    }
}

// ---------------------------------------------------------------------------
// y GEMM (FFMA2): y[n][o][p] = sum_k Wd[o][k]*xa[..][p] + Bd[o].  M=128, K=192
// ---------------------------------------------------------------------------
__global__ __launch_bounds__(256, 2) void ygemm_kernel()
{
    int pBlk = blockIdx.x << 7;
    int n    = blockIdx.z;
    __shared__ __align__(16) float As[16][132];
    __shared__ __align__(16) float Bs[16][132];
    int tid = threadIdx.x;
    int tx = tid & 15, ty = tid >> 4;
    ZERO_ACC();

#pragma unroll
    for (int k0 = 0; k0 < 192; k0 += 16) {
        {
            int m_ = tid >> 1;
            int kq_ = tid & 1;
#pragma unroll
            for (int hh = 0; hh < 2; hh++) {
                float4 av = *(const float4*)(g_Wd + (size_t)m_ * 192 + k0 + ((kq_ * 2 + hh) << 2));
                int kb = ((kq_ * 2 + hh) << 2);
                As[kb + 0][m_] = av.x;
                As[kb + 1][m_] = av.y;
                As[kb + 2][m_] = av.z;
                As[kb + 3][m_] = av.w;
            }
        }
#pragma unroll
        for (int rr = 0; rr < 2; rr++) {
            int r = (tid >> 5) + (rr << 3);
            int c2 = tid & 31;
            int k = k0 + r;
            int i = k >> 6, cc = k & 63;
            *(float4*)&Bs[r][c2 << 2] =
                *(const float4*)(g_xa + (size_t)((i << 9) + (n << 6) + cc) * PP + pBlk + (c2 << 2));
        }
        __syncthreads();
#pragma unroll
        for (int kk = 0; kk < 16; kk++) FRAG88(As, Bs, kk)
        __syncthreads();
    }
#pragma unroll
    for (int io = 0; io < 8; io++) {
        int o = ((io >> 2) << 6) + (ty << 2) + (io & 3);
        float bi = g_Bd[o];
#pragma unroll
        for (int jq = 0; jq < 2; jq++) {
            int col = pBlk + (jq << 6) + (tx << 2);
            float2 p0 = unpk(acc2[io][jq * 2 + 0]);
            float2 p1 = unpk(acc2[io][jq * 2 + 1]);
            float4 r;
            r.x = p0.x + bi; r.y = p0.y + bi; r.z = p1.x + bi; r.w = p1.y + bi;
            *(float4*)(g_y + ((size_t)(n * 128) + o) * PP + col) = r;
        }
    }
}

// ---------------------------------------------------------------------------
// gcnT = relu(bn_g(y) + bn_c(cres)) -> channel-last bf16 hi/lo
// ---------------------------------------------------------------------------
__global__ __launch_bounds__(256) void gcnT_kernel()
{
    int wBlk = blockIdx.x << 6;
    int h    = blockIdx.y;
    int n    = blockIdx.z;
    __shared__ float ts[64][129];
    int tid = threadIdx.x;
    int wl = tid & 63, cg = tid >> 6;
#pragma unroll 8
    for (int c = cg; c < 128; c += 4) {
        float sg = g_bnp[c], hg = g_bnp[128 + c];
        float sc = g_bnp[256 + c], hc = g_bnp[384 + c];
        float yv = g_y[(size_t)(n * 128 + c) * PP + h * 256 + wBlk + wl];
        float cv = g_crt[(size_t)(n * 256 + c) * PP + h * 256 + wBlk + wl];
        ts[wl][c] = fmaxf(yv * sg + hg + cv * sc + hc, 0.f);
    }
    __syncthreads();
    int c2 = (tid & 63) << 1;
    int w0 = tid >> 6;
#pragma unroll 8
    for (int w = w0; w < 64; w += 4) {
        float v0 = ts[w][c2], v1 = ts[w][c2 + 1];
        __nv_bfloat16 h0, l0, h1, l1;
        bsplit(v0, h0, l0); bsplit(v1, h1, l1);
        size_t base = ((size_t)(n * 256 + h) * 256 + wBlk + w) * 128 + c2;
        __nv_bfloat162 ph; ph.x = h0; ph.y = h1;
        __nv_bfloat162 pl; pl.x = l0; pl.y = l1;
        *(__nv_bfloat162*)(g_gTh + base) = ph;
        *(__nv_bfloat162*)(g_gTl + base) = pl;
    }
}

// ---------------------------------------------------------------------------
// TCN via mma.sync bf16 (3-term split) + fused epilogue (unchanged from R7)
// ---------------------------------------------------------------------------
__global__ __launch_bounds__(256) void tcn_mma_kernel(float* __restrict__ out)
{
    extern __shared__ __align__(16) __nv_bfloat16 sm[];
    __nv_bfloat16* sAh = sm;
    __nv_bfloat16* sAl = sm + 128 * SMP;
    __nv_bfloat16* sBh = sm + 2 * 128 * SMP;
    __nv_bfloat16* sBl = sm + 3 * 128 * SMP;

    int wBlk = blockIdx.x << 7;
    int h    = blockIdx.y;
    int n    = blockIdx.z;
    int tid  = threadIdx.x;
    int warp = tid >> 5, lane = tid & 31;
    int warpO = warp & 3, warpW = warp >> 2;

    float d[2][8][4];
#pragma unroll
    for (int i = 0; i < 2; i++)
#pragma unroll
        for (int j = 0; j < 8; j++)
#pragma unroll
            for (int k = 0; k < 4; k++) d[i][j][k] = 0.f;

    uint32_t uAh = smem_u32(sAh), uAl = smem_u32(sAl);
    uint32_t uBh = smem_u32(sBh), uBl = smem_u32(sBl);
    int aRow = warpO * 32 + (lane & 15);
    int aColSel = (lane >> 4) << 3;
    int l16 = lane & 31 & 15;
    int bRowOff = warpW * 64 + (l16 & 7);
    int bColSel = ((l16 >> 3) & 1) << 3;

    for (int k9 = 0; k9 < 9; k9++) {
        int hs = h + k9 - 4;
        if ((unsigned)hs >= 256u) continue;
        __syncthreads();
        {
            const uint4* whv = (const uint4*)(g_W9h + k9 * 16384);
            const uint4* wlv = (const uint4*)(g_W9l + k9 * 16384);
            size_t gbase = ((size_t)(n * 256 + hs) * 256 + wBlk) * 128;
            const uint4* bhv = (const uint4*)(g_gTh + gbase);
            const uint4* blv = (const uint4*)(g_gTl + gbase);
#pragma unroll
            for (int t = 0; t < 8; t++) {
                int idx = tid + t * 256;
                int r = idx >> 4, c8 = idx & 15;
                int doff = r * SMP + (c8 << 3);
                *(uint4*)(sAh + doff) = whv[idx];
                *(uint4*)(sAl + doff) = wlv[idx];
                *(uint4*)(sBh + doff) = bhv[idx];
                *(uint4*)(sBl + doff) = blv[idx];
            }
        }
        __syncthreads();
#pragma unroll
        for (int kc = 0; kc < 8; kc++) {
            int c0 = kc << 4;
            uint32_t ah[2][4], al[2][4];
#pragma unroll
            for (int mt = 0; mt < 2; mt++) {
                uint32_t off = (uint32_t)(((aRow + mt * 16) * SMP + c0 + aColSel) << 1);
                ldsm_x4(ah[mt], uAh + off);
                ldsm_x4(al[mt], uAl + off);
            }
            uint32_t bh[8][2], bl[8][2];
#pragma unroll
            for (int nt = 0; nt < 8; nt++) {
                uint32_t off = (uint32_t)(((bRowOff + nt * 8) * SMP + c0 + bColSel) << 1);
                ldsm_x2(bh[nt], uBh + off);
                ldsm_x2(bl[nt], uBl + off);
            }
#pragma unroll
            for (int mt = 0; mt < 2; mt++)
#pragma unroll
                for (int nt = 0; nt < 8; nt++) {
                    mma_bf16(d[mt][nt], ah[mt], bh[nt]);
                    mma_bf16(d[mt][nt], ah[mt], bl[nt]);
                    mma_bf16(d[mt][nt], al[mt], bh[nt]);
                }
        }
    }

    int oB = warpO * 32;
    int wB = wBlk + warpW * 64;
#pragma unroll
    for (int mt = 0; mt < 2; mt++) {
        int o0 = oB + mt * 16 + (lane >> 2);
#pragma unroll
        for (int half = 0; half < 2; half++) {
            int o = o0 + half * 8;
            float st = g_bnp[512 + o], ht = g_bnp[640 + o];
            float sr = g_bnp[768 + o], hr = g_bnp[896 + o];
            size_t ob = ((size_t)(n * 128 + o) * 256 + h) * 256;
            size_t rb = ((size_t)(n * 256 + 128 + o) * 256 + h) * 256;
#pragma unroll
            for (int nt = 0; nt < 8; nt++) {
                int w = wB + nt * 8 + ((lane & 3) << 1);
                float2 rv = *(const float2*)(g_crt + rb + w);
                float v0 = d[mt][nt][half * 2 + 0];
                float v1 = d[mt][nt][half * 2 + 1];
                float2 ov;
                ov.x = fmaxf(v0 * st + ht + rv.x * sr + hr, 0.f);
                ov.y = fmaxf(v1 * st + ht + rv.y * sr + hr, 0.f);
                *(float2*)(out + ob + w) = ov;
            }
        }
    }
}

// ---------------------------------------------------------------------------
extern "C" void kernel_launch(void* const* d_in, const int* in_sizes, int n_in,
                              void* d_out, int out_size)
{
    const float* x       = (const float*)d_in[0];
    const float* mat_adj = (const float*)d_in[1];
    const float* adj_w   = (const float*)d_in[2];
    const float* wa      = (const float*)d_in[3];
    const float* ba      = (const float*)d_in[4];
    const float* wb      = (const float*)d_in[5];
    const float* bb      = (const float*)d_in[6];
    const float* wd      = (const float*)d_in[7];
    const float* bd      = (const float*)d_in[8];
    const float* gcn_bn  = (const float*)d_in[9];
    const float* cres_w  = (const float*)d_in[10];
    const float* cres_b  = (const float*)d_in[11];
    const float* cres_bn = (const float*)d_in[12];
    const float* tcn_w   = (const float*)d_in[13];
    const float* tcn_b   = (const float*)d_in[14];
    const float* tcn_bn  = (const float*)d_in[15];
    const float* rt_w    = (const float*)d_in[16];
    const float* rt_b    = (const float*)d_in[17];
    const float* rt_bn   = (const float*)d_in[18];
    float* out = (float*)d_out;

    const int mma_smem = 4 * 128 * SMP * 2;   // 139264 bytes
    cudaFuncSetAttribute(tcn_mma_kernel,
                         cudaFuncAttributeMaxDynamicSharedMemorySize, mma_smem);
    cudaFuncSetAttribute(scores_mma_kernel,
                         cudaFuncAttributeMaxDynamicSharedMemorySize, mma_smem);
    cudaFuncSetAttribute(xa_mma_kernel,
                         cudaFuncAttributeMaxDynamicSharedMemorySize, mma_smem);

    pack_kernel<<<128, 256>>>(wa, ba, wb, bb, wd, bd, cres_w, cres_b,
                              rt_w, rt_b, gcn_bn, cres_bn, tcn_bn, rt_bn,
                              tcn_w, tcn_b);
    conv1x1_kernel<0><<<dim3(512, 2, 8), 256>>>(x);   // ab embeds -> bf16 hi/lo
    conv1x1_kernel<1><<<dim3(512, 2, 8), 256>>>(x);   // cres | rt fp32
    xsplit_kernel<<<32768, 256>>>(x);
    scores_mma_kernel<<<dim3(2, 2, 48), 256, mma_smem>>>();
    softmax_kernel<<<24, 1024>>>(mat_adj, adj_w);
    xa_mma_kernel<<<dim3(2, 2, 1536), 256, mma_smem>>>();
    ygemm_kernel<<<dim3(512, 1, 8), 256>>>();
    gcnT_kernel<<<dim3(4, 256, 8), 256>>>();
    tcn_mma_kernel<<<dim3(2, 256, 8), 256, mma_smem>>>(out);
}

// round 9
// speedup vs baseline: 4.3857x; 1.4490x over previous
#include <cuda_runtime.h>
#include <cuda_bf16.h>
#include <math.h>
#include <stdint.h>

// ---------------------------------------------------------------------------
// Problem dims: N=8, C=64, COUT=128, T=V=256, S=3, IC=32, P=T*V=65536
// ---------------------------------------------------------------------------
#define PP 65536
#define SMP 136

__device__ __forceinline__ uint32_t smem_u32(const void* p) {
    uint32_t a;
    asm("{ .reg .u64 t; cvta.to.shared.u64 t, %1; cvt.u32.u64 %0, t; }"
        : "=r"(a) : "l"(p));
    return a;
}
__device__ __forceinline__ void ldsm_x4(uint32_t* r, uint32_t addr) {
    asm volatile("ldmatrix.sync.aligned.m8n8.x4.shared.b16 {%0,%1,%2,%3}, [%4];"
                 : "=r"(r[0]), "=r"(r[1]), "=r"(r[2]), "=r"(r[3]) : "r"(addr));
}
__device__ __forceinline__ void ldsm_x2(uint32_t* r, uint32_t addr) {
    asm volatile("ldmatrix.sync.aligned.m8n8.x2.shared.b16 {%0,%1}, [%2];"
                 : "=r"(r[0]), "=r"(r[1]) : "r"(addr));
}
__device__ __forceinline__ void ldsm_x4_t(uint32_t* r, uint32_t addr) {
    asm volatile("ldmatrix.sync.aligned.m8n8.x4.trans.shared.b16 {%0,%1,%2,%3}, [%4];"
                 : "=r"(r[0]), "=r"(r[1]), "=r"(r[2]), "=r"(r[3]) : "r"(addr));
}
__device__ __forceinline__ void ldsm_x2_t(uint32_t* r, uint32_t addr) {
    asm volatile("ldmatrix.sync.aligned.m8n8.x2.trans.shared.b16 {%0,%1}, [%2];"
                 : "=r"(r[0]), "=r"(r[1]) : "r"(addr));
}
__device__ __forceinline__ void mma_bf16(float* d, const uint32_t* a, const uint32_t* b) {
    asm volatile(
        "mma.sync.aligned.m16n8k16.row.col.f32.bf16.bf16.f32 "
        "{%0,%1,%2,%3}, {%4,%5,%6,%7}, {%8,%9}, {%0,%1,%2,%3};"
        : "+f"(d[0]), "+f"(d[1]), "+f"(d[2]), "+f"(d[3])
        : "r"(a[0]), "r"(a[1]), "r"(a[2]), "r"(a[3]), "r"(b[0]), "r"(b[1]));
}
__device__ __forceinline__ void bsplit(float v, __nv_bfloat16& h, __nv_bfloat16& l) {
    h = __float2bfloat16(v);
    l = __float2bfloat16(v - __bfloat162float(h));
}

// ------------------------- packed parameters -------------------------------
__device__ __nv_bfloat16 g_Wabh[256 * 64];       // hi only (y-path)
__device__ float g_Bab[256];
__device__ __nv_bfloat16 g_Wcrth[256 * 64];      // hi/lo (precision path)
__device__ __nv_bfloat16 g_Wcrtl[256 * 64];
__device__ float g_Bcrt[256];
__device__ __nv_bfloat16 g_Wdh[128 * 192];       // hi only
__device__ float g_Bd[128];
__device__ float g_bnp[1024];                    // sg,hg, sc,hc, st,ht2, sr,hr
__device__ __nv_bfloat16 g_W9h[9 * 128 * 128];   // [k9][o][c] hi
__device__ __nv_bfloat16 g_W9l[9 * 128 * 128];   // lo

// ------------------------- scratch buffers ---------------------------------
__device__ __nv_bfloat16 g_abh[134217728]; // [n][256][PP] embeds (bf16)
__device__ __nv_bfloat16 g_xh[33554432];   // [n][64][t][v] x hi
__device__ __nv_bfloat16 g_xl[33554432];   // lo (conv mode1 only)
__device__ __nv_bfloat16 g_adh[1572864];   // [bn][t][s] adapt bf16
__device__ float g_adapt[1572864];         // fp32 scores partial (kh=0)
__device__ float g_adapt2[1572864];        // fp32 scores partial (kh=1)
__device__ __nv_bfloat16 g_xab[100663296]; // xa out bf16 [b2][v][s]
__device__ float g_y[67108864];            // [n][128][PP]
__device__ float g_crt[134217728];         // (cres | rt) fp32
__device__ __nv_bfloat16 g_gTh[67108864];  // [n][h][w][c] hi
__device__ __nv_bfloat16 g_gTl[67108864];  // lo

// ---------------------------------------------------------------------------
__global__ void pack_kernel(const float* __restrict__ wa, const float* __restrict__ ba,
                            const float* __restrict__ wb, const float* __restrict__ bb,
                            const float* __restrict__ wd, const float* __restrict__ bd,
                            const float* __restrict__ cres_w, const float* __restrict__ cres_b,
                            const float* __restrict__ rt_w, const float* __restrict__ rt_b,
                            const float* __restrict__ gcn_bn, const float* __restrict__ cres_bn,
                            const float* __restrict__ tcn_bn, const float* __restrict__ rt_bn,
                            const float* __restrict__ tcn_w, const float* __restrict__ tcn_b)
{
    int tid = blockIdx.x * blockDim.x + threadIdx.x;
    int nth = gridDim.x * blockDim.x;
    for (int idx = tid; idx < 256 * 64; idx += nth) {
        int o = idx >> 6, c = idx & 63;
        int i = o >> 6, sub = o & 63;
        float v = 0.f;
        if (o < 192) v = (sub < 32) ? wa[(i * 32 + sub) * 64 + c]
                                    : wb[(i * 32 + sub - 32) * 64 + c];
        g_Wabh[idx] = __float2bfloat16(v);
    }
    for (int o = tid; o < 256; o += nth) {
        int i = o >> 6, sub = o & 63;
        float v = 0.f;
        if (o < 192) v = (sub < 32) ? ba[i * 32 + sub] : bb[i * 32 + sub - 32];
        g_Bab[o] = v;
    }
    for (int idx = tid; idx < 256 * 64; idx += nth) {
        int o = idx >> 6, c = idx & 63;
        float v = (o < 128) ? cres_w[o * 64 + c] : rt_w[(o - 128) * 64 + c];
        __nv_bfloat16 h, l;
        bsplit(v, h, l);
        g_Wcrth[idx] = h; g_Wcrtl[idx] = l;
    }
    for (int o = tid; o < 256; o += nth)
        g_Bcrt[o] = (o < 128) ? cres_b[o] : rt_b[o - 128];
    for (int idx = tid; idx < 128 * 192; idx += nth) {
        int o = idx / 192, k = idx - o * 192;
        int i = k >> 6, c = k & 63;
        g_Wdh[idx] = __float2bfloat16(wd[(i * 128 + o) * 64 + c]);
    }
    for (int o = tid; o < 128; o += nth)
        g_Bd[o] = bd[o] + bd[128 + o] + bd[256 + o];
    for (int idx = tid; idx < 9 * 128 * 128; idx += nth) {
        int k9 = idx >> 14;
        int rem = idx & 16383;
        int o = rem >> 7, c = rem & 127;
        float v = tcn_w[o * 1152 + c * 9 + k9];
        __nv_bfloat16 h, l;
        bsplit(v, h, l);
        g_W9h[idx] = h; g_W9l[idx] = l;
    }
    for (int o = tid; o < 128; o += nth) {
        float g, b, m, v, s;
        g = gcn_bn[o]; b = gcn_bn[128 + o]; m = gcn_bn[256 + o]; v = gcn_bn[384 + o];
        s = g * rsqrtf(v + 1e-5f);
        g_bnp[o] = s; g_bnp[128 + o] = b - m * s;
        g = cres_bn[o]; b = cres_bn[128 + o]; m = cres_bn[256 + o]; v = cres_bn[384 + o];
        s = g * rsqrtf(v + 1e-5f);
        g_bnp[256 + o] = s; g_bnp[384 + o] = b - m * s;
        g = tcn_bn[o]; b = tcn_bn[128 + o]; m = tcn_bn[256 + o]; v = tcn_bn[384 + o];
        s = g * rsqrtf(v + 1e-5f);
        g_bnp[512 + o] = s; g_bnp[640 + o] = (tcn_b[o] - m) * s + b;
        g = rt_bn[o]; b = rt_bn[128 + o]; m = rt_bn[256 + o]; v = rt_bn[384 + o];
        s = g * rsqrtf(v + 1e-5f);
        g_bnp[768 + o] = s; g_bnp[896 + o] = b - m * s;
    }
}

// ---------------------------------------------------------------------------
__global__ __launch_bounds__(256) void xsplit_kernel(const float* __restrict__ x)
{
    size_t i = (size_t)blockIdx.x * 256 + threadIdx.x;   // 8388608 float4
    float4 v = ((const float4*)x)[i];
    __nv_bfloat16 h0, l0, h1, l1, h2, l2, h3, l3;
    bsplit(v.x, h0, l0); bsplit(v.y, h1, l1);
    bsplit(v.z, h2, l2); bsplit(v.w, h3, l3);
    __nv_bfloat162 ph0; ph0.x = h0; ph0.y = h1;
    __nv_bfloat162 ph1; ph1.x = h2; ph1.y = h3;
    __nv_bfloat162 pl0; pl0.x = l0; pl0.y = l1;
    __nv_bfloat162 pl1; pl1.x = l2; pl1.y = l3;
    *(__nv_bfloat162*)(g_xh + i * 4) = ph0;
    *(__nv_bfloat162*)(g_xh + i * 4 + 2) = ph1;
    *(__nv_bfloat162*)(g_xl + i * 4) = pl0;
    *(__nv_bfloat162*)(g_xl + i * 4 + 2) = pl1;
}

// ---------------------------------------------------------------------------
// conv1x1 via MMA. K=64.  A = W[o][c] (row-major, non-trans ldsm, pitch 72),
// B = x[c][p] (k-major, trans ldsm, pitch 136).  Block 128(o) x 128(p).
// MODE 0: 1-term hi, out bf16 embeds.  MODE 1: 3-term, out fp32 crt.
// ---------------------------------------------------------------------------
#define APITCH 72
template <int MODE>
__global__ __launch_bounds__(256) void conv_mma_kernel()
{
    extern __shared__ __align__(16) __nv_bfloat16 sm[];
    __nv_bfloat16* sAh = sm;                         // 128 x 72
    __nv_bfloat16* sBh = sm + 128 * APITCH;          // 64 x 136
    __nv_bfloat16* sAl = sBh + 64 * SMP;             // MODE1 only
    __nv_bfloat16* sBl = sAl + 128 * APITCH;

    int pBlk = blockIdx.x << 7;
    int oBlk = blockIdx.y << 7;
    int n    = blockIdx.z;
    int tid  = threadIdx.x;
    int warp = tid >> 5, lane = tid & 31;
    int warpO = warp & 3, warpW = warp >> 2;

    const __nv_bfloat16* Wh = MODE ? g_Wcrth : g_Wabh;

    float d[2][8][4];
#pragma unroll
    for (int a = 0; a < 2; a++)
#pragma unroll
        for (int bq = 0; bq < 8; bq++)
#pragma unroll
            for (int k = 0; k < 4; k++) d[a][bq][k] = 0.f;

    // stage A: 128 x 64 -> 1024 uint4 per buffer
#pragma unroll
    for (int t = 0; t < 4; t++) {
        int idx = tid + t * 256;
        int r = idx >> 3, c8 = idx & 7;
        int doff = r * APITCH + (c8 << 3);
        *(uint4*)(sAh + doff) = *(const uint4*)(Wh + (oBlk + r) * 64 + (c8 << 3));
        if (MODE)
            *(uint4*)(sAl + doff) = *(const uint4*)(g_Wcrtl + (oBlk + r) * 64 + (c8 << 3));
    }
    // stage B: 64 x 128 -> 1024 uint4 per buffer
#pragma unroll
    for (int t = 0; t < 4; t++) {
        int idx = tid + t * 256;
        int r = idx >> 4, c8 = idx & 15;
        int doff = r * SMP + (c8 << 3);
        *(uint4*)(sBh + doff) = *(const uint4*)(g_xh + ((size_t)n * 64 + r) * PP + pBlk + (c8 << 3));
        if (MODE)
            *(uint4*)(sBl + doff) = *(const uint4*)(g_xl + ((size_t)n * 64 + r) * PP + pBlk + (c8 << 3));
    }
    __syncthreads();

    uint32_t uAh = smem_u32(sAh), uAl = smem_u32(sAl);
    uint32_t uBh = smem_u32(sBh), uBl = smem_u32(sBl);
    int aRow = warpO * 32 + (lane & 15);
    int aColSel = (lane >> 4) << 3;
    int tRowB = lane & 15;

#pragma unroll
    for (int kc = 0; kc < 4; kc++) {
        int k16 = kc << 4;
        uint32_t ah[2][4], al[2][4];
#pragma unroll
        for (int mt = 0; mt < 2; mt++) {
            uint32_t off = (uint32_t)(((aRow + mt * 16) * APITCH + k16 + aColSel) << 1);
            ldsm_x4(ah[mt], uAh + off);
            if (MODE) ldsm_x4(al[mt], uAl + off);
        }
        uint32_t bh[8][2], bl[8][2];
#pragma unroll
        for (int nt = 0; nt < 8; nt++) {
            int sCol = warpW * 64 + nt * 8;
            uint32_t off = (uint32_t)(((k16 + tRowB) * SMP + sCol) << 1);
            ldsm_x2_t(bh[nt], uBh + off);
            if (MODE) ldsm_x2_t(bl[nt], uBl + off);
        }
#pragma unroll
        for (int mt = 0; mt < 2; mt++)
#pragma unroll
            for (int nt = 0; nt < 8; nt++) {
                mma_bf16(d[mt][nt], ah[mt], bh[nt]);
                if (MODE) {
                    mma_bf16(d[mt][nt], ah[mt], bl[nt]);
                    mma_bf16(d[mt][nt], al[mt], bh[nt]);
                }
            }
    }

#pragma unroll
    for (int mt = 0; mt < 2; mt++) {
        int o0 = oBlk + warpO * 32 + mt * 16 + (lane >> 2);
#pragma unroll
        for (int half = 0; half < 2; half++) {
            int o = o0 + half * 8;
            float bi = MODE ? g_Bcrt[o] : g_Bab[o];
            size_t base = ((size_t)n * 256 + o) * PP + pBlk;
#pragma unroll
            for (int nt = 0; nt < 8; nt++) {
                int p = warpW * 64 + nt * 8 + ((lane & 3) << 1);
                float v0 = d[mt][nt][half * 2 + 0] + bi;
                float v1 = d[mt][nt][half * 2 + 1] + bi;
                if (MODE) {
                    *(float2*)(g_crt + base + p) = make_float2(v0, v1);
                } else {
                    __nv_bfloat162 pk;
                    pk.x = __float2bfloat16(v0);
                    pk.y = __float2bfloat16(v1);
                    *(__nv_bfloat162*)(g_abh + base + p) = pk;
                }
            }
        }
    }
}

// ---------------------------------------------------------------------------
// scores via mma (1-term), split-K=2 over c. Block 128(t) x 128(s).
// ---------------------------------------------------------------------------
__global__ __launch_bounds__(256) void scores_mma_kernel()
{
    extern __shared__ __align__(16) __nv_bfloat16 sm[];
    __nv_bfloat16* sA = sm;
    __nv_bfloat16* sB = sm + 128 * SMP;

    int kh = blockIdx.z & 1, b = blockIdx.z >> 1;
    int i = b >> 3, n = b & 7;
    int sBlk = blockIdx.x << 7, tBlk = blockIdx.y << 7;
    size_t aOff = ((size_t)n * 256 + i * 64) * PP;
    size_t bOff = aOff + (size_t)32 * PP;

    int tid = threadIdx.x;
    int warp = tid >> 5, lane = tid & 31;
    int warpO = warp & 3, warpW = warp >> 2;

    float d[2][8][4];
#pragma unroll
    for (int a = 0; a < 2; a++)
#pragma unroll
        for (int bq = 0; bq < 8; bq++)
#pragma unroll
            for (int k = 0; k < 4; k++) d[a][bq][k] = 0.f;

    uint32_t uA = smem_u32(sA), uB = smem_u32(sB);
    int aRow = warpO * 32 + (lane & 15);
    int aColSel = (lane >> 4) << 3;
    int l16 = lane & 15;
    int bRowOff = warpW * 64 + (l16 & 7);
    int bColSel = ((l16 >> 3) & 1) << 3;

    int c0 = kh << 4;
    for (int c = c0; c < c0 + 16; c++) {
        const __nv_bfloat16* aH = g_abh + aOff + (size_t)c * PP;
        const __nv_bfloat16* bH = g_abh + bOff + (size_t)c * PP;
#pragma unroll 1
        for (int vh = 0; vh < 2; vh++) {
            int v0 = vh << 7;
            __syncthreads();
#pragma unroll
            for (int t = 0; t < 8; t++) {
                int idx = tid + t * 256;
                int r = idx >> 4, c8 = idx & 15;
                int doff = r * SMP + (c8 << 3);
                *(uint4*)(sA + doff) = *(const uint4*)(aH + (size_t)(tBlk + r) * 256 + v0 + (c8 << 3));
                *(uint4*)(sB + doff) = *(const uint4*)(bH + (size_t)(sBlk + r) * 256 + v0 + (c8 << 3));
            }
            __syncthreads();
#pragma unroll
            for (int kc = 0; kc < 8; kc++) {
                int k16 = kc << 4;
                uint32_t a4[2][4];
#pragma unroll
                for (int mt = 0; mt < 2; mt++) {
                    uint32_t off = (uint32_t)(((aRow + mt * 16) * SMP + k16 + aColSel) << 1);
                    ldsm_x4(a4[mt], uA + off);
                }
                uint32_t b2[8][2];
#pragma unroll
                for (int nt = 0; nt < 8; nt++) {
                    uint32_t off = (uint32_t)(((bRowOff + nt * 8) * SMP + k16 + bColSel) << 1);
                    ldsm_x2(b2[nt], uB + off);
                }
#pragma unroll
                for (int mt = 0; mt < 2; mt++)
#pragma unroll
                    for (int nt = 0; nt < 8; nt++)
                        mma_bf16(d[mt][nt], a4[mt], b2[nt]);
            }
        }
    }

    float* dst = (kh ? g_adapt2 : g_adapt) + (size_t)b * PP;
    const float sc = 1.0f / 256.0f;
#pragma unroll
    for (int mt = 0; mt < 2; mt++) {
        int t0 = tBlk + warpO * 32 + mt * 16 + (lane >> 2);
#pragma unroll
        for (int half = 0; half < 2; half++) {
            int t = t0 + half * 8;
#pragma unroll
            for (int nt = 0; nt < 8; nt++) {
                int s = sBlk + warpW * 64 + nt * 8 + ((lane & 3) << 1);
                float2 ov;
                ov.x = d[mt][nt][half * 2 + 0] * sc;
                ov.y = d[mt][nt][half * 2 + 1] * sc;
                *(float2*)(dst + (size_t)t * 256 + s) = ov;
            }
        }
    }
}

// ---------------------------------------------------------------------------
// softmax over t per column s, adapt -> bf16 (hi only).
// ---------------------------------------------------------------------------
__global__ __launch_bounds__(1024) void softmax_kernel(const float* __restrict__ mat_adj,
                                                       const float* __restrict__ adj_w)
{
    int b = blockIdx.x;
    int i = b >> 3;
    const float* p1 = g_adapt + (size_t)b * PP;
    const float* p2 = g_adapt2 + (size_t)b * PP;
    int s = threadIdx.x & 255, tq = threadIdx.x >> 8;
    __shared__ float red[4][256];
    int t0 = tq << 6, t1 = t0 + 64;
    float m = -1e30f;
    for (int t = t0; t < t1; t++) {
        int idx = t * 256 + s;
        m = fmaxf(m, p1[idx] + p2[idx]);
    }
    red[tq][s] = m;
    __syncthreads();
    m = fmaxf(fmaxf(red[0][s], red[1][s]), fmaxf(red[2][s], red[3][s]));
    __syncthreads();
    float sum = 0.f;
    for (int t = t0; t < t1; t++) {
        int idx = t * 256 + s;
        sum += expf(p1[idx] + p2[idx] - m);
    }
    red[tq][s] = sum;
    __syncthreads();
    sum = red[0][s] + red[1][s] + red[2][s] + red[3][s];
    float inv = 1.f / sum;
    const float* A1 = mat_adj + (size_t)i * PP;
    const float* A2 = adj_w + (size_t)i * PP;
    __nv_bfloat16* dh = g_adh + (size_t)b * PP;
    for (int t = t0; t < t1; t++) {
        int idx = t * 256 + s;
        float e = expf(p1[idx] + p2[idx] - m) * inv;
        dh[idx] = __float2bfloat16(A1[idx] + A2[idx] + e);
    }
}

// ---------------------------------------------------------------------------
// xa via mma (1-term), trans ldsm both operands; output bf16.
// xa[b2][v][s] = sum_t x[n,c,t,v] * adapt[bn,t,s]; block 128v x 128s, K=256.
// ---------------------------------------------------------------------------
__global__ __launch_bounds__(256) void xa_mma_kernel()
{
    extern __shared__ __align__(16) __nv_bfloat16 sm[];
    __nv_bfloat16* sA = sm;
    __nv_bfloat16* sB = sm + 128 * SMP;

    int b2 = blockIdx.z;
    int c = b2 & 63, bn = b2 >> 6;
    int n = bn & 7;
    int sBlk = blockIdx.x << 7, vBlk = blockIdx.y << 7;
    const __nv_bfloat16* xH = g_xh + ((size_t)n * 64 + c) * PP;
    const __nv_bfloat16* aH = g_adh + (size_t)bn * PP;

    int tid = threadIdx.x;
    int warp = tid >> 5, lane = tid & 31;
    int warpV = warp & 3, warpS = warp >> 2;

    float d[2][8][4];
#pragma unroll
    for (int a = 0; a < 2; a++)
#pragma unroll
        for (int bq = 0; bq < 8; bq++)
#pragma unroll
            for (int k = 0; k < 4; k++) d[a][bq][k] = 0.f;

    uint32_t uA = smem_u32(sA), uB = smem_u32(sB);
    int tRowA = (lane & 7) + ((lane & 16) >> 1);
    int vColA = ((lane >> 3) & 1) << 3;
    int tRowB = lane & 15;

#pragma unroll 1
    for (int th = 0; th < 2; th++) {
        int t0 = th << 7;
        __syncthreads();
#pragma unroll
        for (int t = 0; t < 8; t++) {
            int idx = tid + t * 256;
            int r = idx >> 4, c8 = idx & 15;
            int doff = r * SMP + (c8 << 3);
            *(uint4*)(sA + doff) = *(const uint4*)(xH + (size_t)(t0 + r) * 256 + vBlk + (c8 << 3));
            *(uint4*)(sB + doff) = *(const uint4*)(aH + (size_t)(t0 + r) * 256 + sBlk + (c8 << 3));
        }
        __syncthreads();
#pragma unroll
        for (int kc = 0; kc < 8; kc++) {
            int k16 = kc << 4;
            uint32_t a4[2][4];
#pragma unroll
            for (int mt = 0; mt < 2; mt++) {
                int vCol = warpV * 32 + mt * 16 + vColA;
                uint32_t off = (uint32_t)(((k16 + tRowA) * SMP + vCol) << 1);
                ldsm_x4_t(a4[mt], uA + off);
            }
            uint32_t b2f[8][2];
#pragma unroll
            for (int nt = 0; nt < 8; nt++) {
                int sCol = warpS * 64 + nt * 8;
                uint32_t off = (uint32_t)(((k16 + tRowB) * SMP + sCol) << 1);
                ldsm_x2_t(b2f[nt], uB + off);
            }
#pragma unroll
            for (int mt = 0; mt < 2; mt++)
#pragma unroll
                for (int nt = 0; nt < 8; nt++)
                    mma_bf16(d[mt][nt], a4[mt], b2f[nt]);
        }
    }

    __nv_bfloat16* op = g_xab + (size_t)b2 * PP;
#pragma unroll
    for (int mt = 0; mt < 2; mt++) {
        int v0 = vBlk + warpV * 32 + mt * 16 + (lane >> 2);
#pragma unroll
        for (int half = 0; half < 2; half++) {
            int v = v0 + half * 8;
#pragma unroll
            for (int nt = 0; nt < 8; nt++) {
                int s = sBlk + warpS * 64 + nt * 8 + ((lane & 3) << 1);
                __nv_bfloat162 pk;
                pk.x = __float2bfloat16(d[mt][nt][half * 2 + 0]);
                pk.y = __float2bfloat16(d[mt][nt][half * 2 + 1]);
                *(__nv_bfloat162*)(op + (size_t)v * 256 + s) = pk;
            }
        }
    }
}

// ---------------------------------------------------------------------------
// y GEMM via mma (1-term).  y[n][o][p] = sum_k Wd[o][k]*xa[..][p] + Bd[o].
// M=128, K=192 (12 k16 chunks).  A staged whole (pitch 200), B per chunk.
// ---------------------------------------------------------------------------
#define YPITCH 200
__global__ __launch_bounds__(256) void ygemm_mma_kernel()
{
    extern __shared__ __align__(16) __nv_bfloat16 sm[];
    __nv_bfloat16* sA = sm;                   // 128 x 200
    __nv_bfloat16* sB = sm + 128 * YPITCH;    // 16 x 136

    int pBlk = blockIdx.x << 7;
    int n    = blockIdx.z;
    int tid  = threadIdx.x;
    int warp = tid >> 5, lane = tid & 31;
    int warpO = warp & 3, warpW = warp >> 2;

    float d[2][8][4];
#pragma unroll
    for (int a = 0; a < 2; a++)
#pragma unroll
        for (int bq = 0; bq < 8; bq++)
#pragma unroll
            for (int k = 0; k < 4; k++) d[a][bq][k] = 0.f;

    // stage A: 128 x 192 = 3072 uint4
#pragma unroll
    for (int t = 0; t < 12; t++) {
        int idx = tid + t * 256;
        int r = idx / 24, c8 = idx - r * 24;
        *(uint4*)(sA + r * YPITCH + (c8 << 3)) = *(const uint4*)(g_Wdh + r * 192 + (c8 << 3));
    }

    uint32_t uA = smem_u32(sA), uB = smem_u32(sB);
    int aRow = warpO * 32 + (lane & 15);
    int aColSel = (lane >> 4) << 3;
    int tRowB = lane & 15;

    for (int kc = 0; kc < 12; kc++) {
        if (kc) __syncthreads();
        // stage B chunk: 16 x 128 = 256 uint4
        {
            int r = tid >> 4, c8 = tid & 15;
            int k = (kc << 4) + r;
            int i = k >> 6, cc = k & 63;
            *(uint4*)(sB + r * SMP + (c8 << 3)) =
                *(const uint4*)(g_xab + (size_t)((i << 9) + (n << 6) + cc) * PP + pBlk + (c8 << 3));
        }
        __syncthreads();
        int k16 = kc << 4;
        uint32_t a4[2][4];
#pragma unroll
        for (int mt = 0; mt < 2; mt++) {
            uint32_t off = (uint32_t)(((aRow + mt * 16) * YPITCH + k16 + aColSel) << 1);
            ldsm_x4(a4[mt], uA + off);
        }
        uint32_t b2[8][2];
#pragma unroll
        for (int nt = 0; nt < 8; nt++) {
            int sCol = warpW * 64 + nt * 8;
            uint32_t off = (uint32_t)((tRowB * SMP + sCol) << 1);
            ldsm_x2_t(b2[nt], uB + off);
        }
#pragma unroll
        for (int mt = 0; mt < 2; mt++)
#pragma unroll
            for (int nt = 0; nt < 8; nt++)
                mma_bf16(d[mt][nt], a4[mt], b2[nt]);
    }

#pragma unroll
    for (int mt = 0; mt < 2; mt++) {
        int o0 = warpO * 32 + mt * 16 + (lane >> 2);
#pragma unroll
        for (int half = 0; half < 2; half++) {
            int o = o0 + half * 8;
            float bi = g_Bd[o];
            size_t base = ((size_t)(n * 128) + o) * PP + pBlk;
#pragma unroll
            for (int nt = 0; nt < 8; nt++) {
                int p = warpW * 64 + nt * 8 + ((lane & 3) << 1);
                float2 ov;
                ov.x = d[mt][nt][half * 2 + 0] + bi;
                ov.y = d[mt][nt][half * 2 + 1] + bi;
                *(float2*)(g_y + base + p) = ov;
            }
        }
    }
}

// ---------------------------------------------------------------------------
// gcnT = relu(bn_g(y) + bn_c(cres)) -> channel-last bf16 hi/lo
// ---------------------------------------------------------------------------
__global__ __launch_bounds__(256) void gcnT_kernel()
{
    int wBlk = blockIdx.x << 6;
    int h    = blockIdx.y;
    int n    = blockIdx.z;
    __shared__ float ts[64][129];
    int tid = threadIdx.x;
    int wl = tid & 63, cg = tid >> 6;
#pragma unroll 8
    for (int c = cg; c < 128; c += 4) {
        float sg = g_bnp[c], hg = g_bnp[128 + c];
        float sc = g_bnp[256 + c], hc = g_bnp[384 + c];
        float yv = g_y[(size_t)(n * 128 + c) * PP + h * 256 + wBlk + wl];
        float cv = g_crt[(size_t)(n * 256 + c) * PP + h * 256 + wBlk + wl];
        ts[wl][c] = fmaxf(yv * sg + hg + cv * sc + hc, 0.f);
    }
    __syncthreads();
    int c2 = (tid & 63) << 1;
    int w0 = tid >> 6;
#pragma unroll 8
    for (int w = w0; w < 64; w += 4) {
        float v0 = ts[w][c2], v1 = ts[w][c2 + 1];
        __nv_bfloat16 h0, l0, h1, l1;
        bsplit(v0, h0, l0); bsplit(v1, h1, l1);
        size_t base = ((size_t)(n * 256 + h) * 256 + wBlk + w) * 128 + c2;
        __nv_bfloat162 ph; ph.x = h0; ph.y = h1;
        __nv_bfloat162 pl; pl.x = l0; pl.y = l1;
        *(__nv_bfloat162*)(g_gTh + base) = ph;
        *(__nv_bfloat162*)(g_gTl + base) = pl;
    }
}

// ---------------------------------------------------------------------------
// TCN via mma.sync bf16 (3-term split) + fused epilogue
// ---------------------------------------------------------------------------
__global__ __launch_bounds__(256) void tcn_mma_kernel(float* __restrict__ out)
{
    extern __shared__ __align__(16) __nv_bfloat16 sm[];
    __nv_bfloat16* sAh = sm;
    __nv_bfloat16* sAl = sm + 128 * SMP;
    __nv_bfloat16* sBh = sm + 2 * 128 * SMP;
    __nv_bfloat16* sBl = sm + 3 * 128 * SMP;

    int wBlk = blockIdx.x << 7;
    int h    = blockIdx.y;
    int n    = blockIdx.z;
    int tid  = threadIdx.x;
    int warp = tid >> 5, lane = tid & 31;
    int warpO = warp & 3, warpW = warp >> 2;

    float d[2][8][4];
#pragma unroll
    for (int i = 0; i < 2; i++)
#pragma unroll
        for (int j = 0; j < 8; j++)
#pragma unroll
            for (int k = 0; k < 4; k++) d[i][j][k] = 0.f;

    uint32_t uAh = smem_u32(sAh), uAl = smem_u32(sAl);
    uint32_t uBh = smem_u32(sBh), uBl = smem_u32(sBl);
    int aRow = warpO * 32 + (lane & 15);
    int aColSel = (lane >> 4) << 3;
    int l16 = lane & 15;
    int bRowOff = warpW * 64 + (l16 & 7);
    int bColSel = ((l16 >> 3) & 1) << 3;

    for (int k9 = 0; k9 < 9; k9++) {
        int hs = h + k9 - 4;
        if ((unsigned)hs >= 256u) continue;
        __syncthreads();
        {
            const uint4* whv = (const uint4*)(g_W9h + k9 * 16384);
            const uint4* wlv = (const uint4*)(g_W9l + k9 * 16384);
            size_t gbase = ((size_t)(n * 256 + hs) * 256 + wBlk) * 128;
            const uint4* bhv = (const uint4*)(g_gTh + gbase);
            const uint4* blv = (const uint4*)(g_gTl + gbase);
#pragma unroll
            for (int t = 0; t < 8; t++) {
                int idx = tid + t * 256;
                int r = idx >> 4, c8 = idx & 15;
                int doff = r * SMP + (c8 << 3);
                *(uint4*)(sAh + doff) = whv[idx];
                *(uint4*)(sAl + doff) = wlv[idx];
                *(uint4*)(sBh + doff) = bhv[idx];
                *(uint4*)(sBl + doff) = blv[idx];
            }
        }
        __syncthreads();
#pragma unroll
        for (int kc = 0; kc < 8; kc++) {
            int c0 = kc << 4;
            uint32_t ah[2][4], al[2][4];
#pragma unroll
            for (int mt = 0; mt < 2; mt++) {
                uint32_t off = (uint32_t)(((aRow + mt * 16) * SMP + c0 + aColSel) << 1);
                ldsm_x4(ah[mt], uAh + off);
                ldsm_x4(al[mt], uAl + off);
            }
            uint32_t bh[8][2], bl[8][2];
#pragma unroll
            for (int nt = 0; nt < 8; nt++) {
                uint32_t off = (uint32_t)(((bRowOff + nt * 8) * SMP + c0 + bColSel) << 1);
                ldsm_x2(bh[nt], uBh + off);
                ldsm_x2(bl[nt], uBl + off);
            }
#pragma unroll
            for (int mt = 0; mt < 2; mt++)
#pragma unroll
                for (int nt = 0; nt < 8; nt++) {
                    mma_bf16(d[mt][nt], ah[mt], bh[nt]);
                    mma_bf16(d[mt][nt], ah[mt], bl[nt]);
                    mma_bf16(d[mt][nt], al[mt], bh[nt]);
                }
        }
    }

    int oB = warpO * 32;
    int wB = wBlk + warpW * 64;
#pragma unroll
    for (int mt = 0; mt < 2; mt++) {
        int o0 = oB + mt * 16 + (lane >> 2);
#pragma unroll
        for (int half = 0; half < 2; half++) {
            int o = o0 + half * 8;
            float st = g_bnp[512 + o], ht = g_bnp[640 + o];
            float sr = g_bnp[768 + o], hr = g_bnp[896 + o];
            size_t ob = ((size_t)(n * 128 + o) * 256 + h) * 256;
            size_t rb = ((size_t)(n * 256 + 128 + o) * 256 + h) * 256;
#pragma unroll
            for (int nt = 0; nt < 8; nt++) {
                int w = wB + nt * 8 + ((lane & 3) << 1);
                float2 rv = *(const float2*)(g_crt + rb + w);
                float v0 = d[mt][nt][half * 2 + 0];
                float v1 = d[mt][nt][half * 2 + 1];
                float2 ov;
                ov.x = fmaxf(v0 * st + ht + rv.x * sr + hr, 0.f);
                ov.y = fmaxf(v1 * st + ht + rv.y * sr + hr, 0.f);
                *(float2*)(out + ob + w) = ov;
            }
        }
    }
}

// ---------------------------------------------------------------------------
extern "C" void kernel_launch(void* const* d_in, const int* in_sizes, int n_in,
                              void* d_out, int out_size)
{
    const float* x       = (const float*)d_in[0];
    const float* mat_adj = (const float*)d_in[1];
    const float* adj_w   = (const float*)d_in[2];
    const float* wa      = (const float*)d_in[3];
    const float* ba      = (const float*)d_in[4];
    const float* wb      = (const float*)d_in[5];
    const float* bb      = (const float*)d_in[6];
    const float* wd      = (const float*)d_in[7];
    const float* bd      = (const float*)d_in[8];
    const float* gcn_bn  = (const float*)d_in[9];
    const float* cres_w  = (const float*)d_in[10];
    const float* cres_b  = (const float*)d_in[11];
    const float* cres_bn = (const float*)d_in[12];
    const float* tcn_w   = (const float*)d_in[13];
    const float* tcn_b   = (const float*)d_in[14];
    const float* tcn_bn  = (const float*)d_in[15];
    const float* rt_w    = (const float*)d_in[16];
    const float* rt_b    = (const float*)d_in[17];
    const float* rt_bn   = (const float*)d_in[18];
    float* out = (float*)d_out;

    const int tcn_smem   = 4 * 128 * SMP * 2;                         // 139264
    const int gem_smem   = 2 * 128 * SMP * 2;                         // 69632
    const int conv0_smem = (128 * APITCH + 64 * SMP) * 2;             // 35840
    const int conv1_smem = 2 * (128 * APITCH + 64 * SMP) * 2;         // 71680
    const int ygemm_smem = (128 * YPITCH + 16 * SMP) * 2;             // 55552
    cudaFuncSetAttribute(tcn_mma_kernel,
                         cudaFuncAttributeMaxDynamicSharedMemorySize, tcn_smem);
    cudaFuncSetAttribute(scores_mma_kernel,
                         cudaFuncAttributeMaxDynamicSharedMemorySize, gem_smem);
    cudaFuncSetAttribute(xa_mma_kernel,
                         cudaFuncAttributeMaxDynamicSharedMemorySize, gem_smem);
    cudaFuncSetAttribute(conv_mma_kernel<0>,
                         cudaFuncAttributeMaxDynamicSharedMemorySize, conv0_smem);
    cudaFuncSetAttribute(conv_mma_kernel<1>,
                         cudaFuncAttributeMaxDynamicSharedMemorySize, conv1_smem);
    cudaFuncSetAttribute(ygemm_mma_kernel,
                         cudaFuncAttributeMaxDynamicSharedMemorySize, ygemm_smem);

    pack_kernel<<<128, 256>>>(wa, ba, wb, bb, wd, bd, cres_w, cres_b,
                              rt_w, rt_b, gcn_bn, cres_bn, tcn_bn, rt_bn,
                              tcn_w, tcn_b);
    xsplit_kernel<<<32768, 256>>>(x);
    conv_mma_kernel<0><<<dim3(512, 2, 8), 256, conv0_smem>>>();
    conv_mma_kernel<1><<<dim3(512, 2, 8), 256, conv1_smem>>>();
    scores_mma_kernel<<<dim3(2, 2, 48), 256, gem_smem>>>();
    softmax_kernel<<<24, 1024>>>(mat_adj, adj_w);
    xa_mma_kernel<<<dim3(2, 2, 1536), 256, gem_smem>>>();
    ygemm_mma_kernel<<<dim3(512, 1, 8), 256, ygemm_smem>>>();
    gcnT_kernel<<<dim3(4, 256, 8), 256>>>();
    tcn_mma_kernel<<<dim3(2, 256, 8), 256, tcn_smem>>>(out);
}

// round 10
// speedup vs baseline: 5.0457x; 1.1505x over previous
#include <cuda_runtime.h>
#include <cuda_fp16.h>
#include <math.h>
#include <stdint.h>

// ---------------------------------------------------------------------------
// Problem dims: N=8, C=64, COUT=128, T=V=256, S=3, IC=32, P=T*V=65536
// ---------------------------------------------------------------------------
#define PP 65536
#define SMP 136

__device__ __forceinline__ uint32_t smem_u32(const void* p) {
    uint32_t a;
    asm("{ .reg .u64 t; cvta.to.shared.u64 t, %1; cvt.u32.u64 %0, t; }"
        : "=r"(a) : "l"(p));
    return a;
}
__device__ __forceinline__ void ldsm_x4(uint32_t* r, uint32_t addr) {
    asm volatile("ldmatrix.sync.aligned.m8n8.x4.shared.b16 {%0,%1,%2,%3}, [%4];"
                 : "=r"(r[0]), "=r"(r[1]), "=r"(r[2]), "=r"(r[3]) : "r"(addr));
}
__device__ __forceinline__ void ldsm_x2(uint32_t* r, uint32_t addr) {
    asm volatile("ldmatrix.sync.aligned.m8n8.x2.shared.b16 {%0,%1}, [%2];"
                 : "=r"(r[0]), "=r"(r[1]) : "r"(addr));
}
__device__ __forceinline__ void ldsm_x4_t(uint32_t* r, uint32_t addr) {
    asm volatile("ldmatrix.sync.aligned.m8n8.x4.trans.shared.b16 {%0,%1,%2,%3}, [%4];"
                 : "=r"(r[0]), "=r"(r[1]), "=r"(r[2]), "=r"(r[3]) : "r"(addr));
}
__device__ __forceinline__ void ldsm_x2_t(uint32_t* r, uint32_t addr) {
    asm volatile("ldmatrix.sync.aligned.m8n8.x2.trans.shared.b16 {%0,%1}, [%2];"
                 : "=r"(r[0]), "=r"(r[1]) : "r"(addr));
}
__device__ __forceinline__ void mma_f16(float* d, const uint32_t* a, const uint32_t* b) {
    asm volatile(
        "mma.sync.aligned.m16n8k16.row.col.f32.f16.f16.f32 "
        "{%0,%1,%2,%3}, {%4,%5,%6,%7}, {%8,%9}, {%0,%1,%2,%3};"
        : "+f"(d[0]), "+f"(d[1]), "+f"(d[2]), "+f"(d[3])
        : "r"(a[0]), "r"(a[1]), "r"(a[2]), "r"(a[3]), "r"(b[0]), "r"(b[1]));
}
__device__ __forceinline__ void hsplit(float v, __half& h, __half& l) {
    h = __float2half_rn(v);
    l = __float2half_rn(v - __half2float(h));
}
#define CP_ASYNC(dst, src) \
    asm volatile("cp.async.cg.shared.global [%0], [%1], 16;" :: "r"(dst), "l"(src))
#define CP_COMMIT() asm volatile("cp.async.commit_group;")
#define CP_WAIT(N)  asm volatile("cp.async.wait_group %0;" :: "n"(N))

// ------------------------- packed parameters -------------------------------
__device__ __half g_Wabh[256 * 64];        // single (y-path)
__device__ float g_Bab[256];
__device__ __half g_Wcrth[256 * 64];       // hi/lo (precision path)
__device__ __half g_Wcrtl[256 * 64];
__device__ float g_Bcrt[256];
__device__ __half g_Wdh[128 * 192];        // single
__device__ float g_Bd[128];
__device__ float g_bnp[1024];              // sg,hg, sc,hc, st,ht2, sr,hr
__device__ __half g_W9h[9 * 128 * 128];    // [k9][o][c] hi
__device__ __half g_W9l[9 * 128 * 128];    // lo

// ------------------------- scratch buffers ---------------------------------
__device__ __half g_abh[134217728];  // [n][256][PP] embeds (fp16 single)
__device__ __half g_xh[33554432];    // x hi
__device__ __half g_xl[33554432];    // x lo (conv1 only)
__device__ __half g_adh[1572864];    // adapt fp16
__device__ float g_adapt[1572864];   // scores partial kh=0
__device__ float g_adapt2[1572864];  // scores partial kh=1
__device__ __half g_xab[100663296];  // xa out fp16
__device__ float g_y[67108864];
__device__ float g_crt[134217728];   // (cres | rt) fp32
__device__ __half g_gT[67108864];    // [n][h][w][c] gcn fp16 single

// ---------------------------------------------------------------------------
__global__ void pack_kernel(const float* __restrict__ wa, const float* __restrict__ ba,
                            const float* __restrict__ wb, const float* __restrict__ bb,
                            const float* __restrict__ wd, const float* __restrict__ bd,
                            const float* __restrict__ cres_w, const float* __restrict__ cres_b,
                            const float* __restrict__ rt_w, const float* __restrict__ rt_b,
                            const float* __restrict__ gcn_bn, const float* __restrict__ cres_bn,
                            const float* __restrict__ tcn_bn, const float* __restrict__ rt_bn,
                            const float* __restrict__ tcn_w, const float* __restrict__ tcn_b)
{
    int tid = blockIdx.x * blockDim.x + threadIdx.x;
    int nth = gridDim.x * blockDim.x;
    for (int idx = tid; idx < 256 * 64; idx += nth) {
        int o = idx >> 6, c = idx & 63;
        int i = o >> 6, sub = o & 63;
        float v = 0.f;
        if (o < 192) v = (sub < 32) ? wa[(i * 32 + sub) * 64 + c]
                                    : wb[(i * 32 + sub - 32) * 64 + c];
        g_Wabh[idx] = __float2half_rn(v);
    }
    for (int o = tid; o < 256; o += nth) {
        int i = o >> 6, sub = o & 63;
        float v = 0.f;
        if (o < 192) v = (sub < 32) ? ba[i * 32 + sub] : bb[i * 32 + sub - 32];
        g_Bab[o] = v;
    }
    for (int idx = tid; idx < 256 * 64; idx += nth) {
        int o = idx >> 6, c = idx & 63;
        float v = (o < 128) ? cres_w[o * 64 + c] : rt_w[(o - 128) * 64 + c];
        __half h, l;
        hsplit(v, h, l);
        g_Wcrth[idx] = h; g_Wcrtl[idx] = l;
    }
    for (int o = tid; o < 256; o += nth)
        g_Bcrt[o] = (o < 128) ? cres_b[o] : rt_b[o - 128];
    for (int idx = tid; idx < 128 * 192; idx += nth) {
        int o = idx / 192, k = idx - o * 192;
        int i = k >> 6, c = k & 63;
        g_Wdh[idx] = __float2half_rn(wd[(i * 128 + o) * 64 + c]);
    }
    for (int o = tid; o < 128; o += nth)
        g_Bd[o] = bd[o] + bd[128 + o] + bd[256 + o];
    for (int idx = tid; idx < 9 * 128 * 128; idx += nth) {
        int k9 = idx >> 14;
        int rem = idx & 16383;
        int o = rem >> 7, c = rem & 127;
        float v = tcn_w[o * 1152 + c * 9 + k9];
        __half h, l;
        hsplit(v, h, l);
        g_W9h[idx] = h; g_W9l[idx] = l;
    }
    for (int o = tid; o < 128; o += nth) {
        float g, b, m, v, s;
        g = gcn_bn[o]; b = gcn_bn[128 + o]; m = gcn_bn[256 + o]; v = gcn_bn[384 + o];
        s = g * rsqrtf(v + 1e-5f);
        g_bnp[o] = s; g_bnp[128 + o] = b - m * s;
        g = cres_bn[o]; b = cres_bn[128 + o]; m = cres_bn[256 + o]; v = cres_bn[384 + o];
        s = g * rsqrtf(v + 1e-5f);
        g_bnp[256 + o] = s; g_bnp[384 + o] = b - m * s;
        g = tcn_bn[o]; b = tcn_bn[128 + o]; m = tcn_bn[256 + o]; v = tcn_bn[384 + o];
        s = g * rsqrtf(v + 1e-5f);
        g_bnp[512 + o] = s; g_bnp[640 + o] = (tcn_b[o] - m) * s + b;
        g = rt_bn[o]; b = rt_bn[128 + o]; m = rt_bn[256 + o]; v = rt_bn[384 + o];
        s = g * rsqrtf(v + 1e-5f);
        g_bnp[768 + o] = s; g_bnp[896 + o] = b - m * s;
    }
}

// ---------------------------------------------------------------------------
__global__ __launch_bounds__(256) void xsplit_kernel(const float* __restrict__ x)
{
    size_t i = (size_t)blockIdx.x * 256 + threadIdx.x;   // 8388608 float4
    float4 v = ((const float4*)x)[i];
    __half h0, l0, h1, l1, h2, l2, h3, l3;
    hsplit(v.x, h0, l0); hsplit(v.y, h1, l1);
    hsplit(v.z, h2, l2); hsplit(v.w, h3, l3);
    __half2 ph0; ph0.x = h0; ph0.y = h1;
    __half2 ph1; ph1.x = h2; ph1.y = h3;
    __half2 pl0; pl0.x = l0; pl0.y = l1;
    __half2 pl1; pl1.x = l2; pl1.y = l3;
    *(__half2*)(g_xh + i * 4) = ph0;
    *(__half2*)(g_xh + i * 4 + 2) = ph1;
    *(__half2*)(g_xl + i * 4) = pl0;
    *(__half2*)(g_xl + i * 4 + 2) = pl1;
}

// ---------------------------------------------------------------------------
// conv1x1 via MMA. K=64.  MODE 0: 1-term, out fp16 embeds.  MODE 1: 3-term,
// out fp32 crt.
// ---------------------------------------------------------------------------
#define APITCH 72
template <int MODE>
__global__ __launch_bounds__(256) void conv_mma_kernel()
{
    extern __shared__ __align__(16) __half sm[];
    __half* sAh = sm;                         // 128 x 72
    __half* sBh = sm + 128 * APITCH;          // 64 x 136
    __half* sAl = sBh + 64 * SMP;             // MODE1 only
    __half* sBl = sAl + 128 * APITCH;

    int pBlk = blockIdx.x << 7;
    int oBlk = blockIdx.y << 7;
    int n    = blockIdx.z;
    int tid  = threadIdx.x;
    int warp = tid >> 5, lane = tid & 31;
    int warpO = warp & 3, warpW = warp >> 2;

    const __half* Wh = MODE ? g_Wcrth : g_Wabh;

    float d[2][8][4];
#pragma unroll
    for (int a = 0; a < 2; a++)
#pragma unroll
        for (int bq = 0; bq < 8; bq++)
#pragma unroll
            for (int k = 0; k < 4; k++) d[a][bq][k] = 0.f;

#pragma unroll
    for (int t = 0; t < 4; t++) {
        int idx = tid + t * 256;
        int r = idx >> 3, c8 = idx & 7;
        int doff = r * APITCH + (c8 << 3);
        *(uint4*)(sAh + doff) = *(const uint4*)(Wh + (oBlk + r) * 64 + (c8 << 3));
        if (MODE)
            *(uint4*)(sAl + doff) = *(const uint4*)(g_Wcrtl + (oBlk + r) * 64 + (c8 << 3));
    }
#pragma unroll
    for (int t = 0; t < 4; t++) {
        int idx = tid + t * 256;
        int r = idx >> 4, c8 = idx & 15;
        int doff = r * SMP + (c8 << 3);
        *(uint4*)(sBh + doff) = *(const uint4*)(g_xh + ((size_t)n * 64 + r) * PP + pBlk + (c8 << 3));
        if (MODE)
            *(uint4*)(sBl + doff) = *(const uint4*)(g_xl + ((size_t)n * 64 + r) * PP + pBlk + (c8 << 3));
    }
    __syncthreads();

    uint32_t uAh = smem_u32(sAh), uAl = smem_u32(sAl);
    uint32_t uBh = smem_u32(sBh), uBl = smem_u32(sBl);
    int aRow = warpO * 32 + (lane & 15);
    int aColSel = (lane >> 4) << 3;
    int tRowB = lane & 15;

#pragma unroll
    for (int kc = 0; kc < 4; kc++) {
        int k16 = kc << 4;
        uint32_t ah[2][4], al[2][4];
#pragma unroll
        for (int mt = 0; mt < 2; mt++) {
            uint32_t off = (uint32_t)(((aRow + mt * 16) * APITCH + k16 + aColSel) << 1);
            ldsm_x4(ah[mt], uAh + off);
            if (MODE) ldsm_x4(al[mt], uAl + off);
        }
        uint32_t bh[8][2], bl[8][2];
#pragma unroll
        for (int nt = 0; nt < 8; nt++) {
            int sCol = warpW * 64 + nt * 8;
            uint32_t off = (uint32_t)(((k16 + tRowB) * SMP + sCol) << 1);
            ldsm_x2_t(bh[nt], uBh + off);
            if (MODE) ldsm_x2_t(bl[nt], uBl + off);
        }
#pragma unroll
        for (int mt = 0; mt < 2; mt++)
#pragma unroll
            for (int nt = 0; nt < 8; nt++) {
                mma_f16(d[mt][nt], ah[mt], bh[nt]);
                if (MODE) {
                    mma_f16(d[mt][nt], ah[mt], bl[nt]);
                    mma_f16(d[mt][nt], al[mt], bh[nt]);
                }
            }
    }

#pragma unroll
    for (int mt = 0; mt < 2; mt++) {
        int o0 = oBlk + warpO * 32 + mt * 16 + (lane >> 2);
#pragma unroll
        for (int half = 0; half < 2; half++) {
            int o = o0 + half * 8;
            float bi = MODE ? g_Bcrt[o] : g_Bab[o];
            size_t base = ((size_t)n * 256 + o) * PP + pBlk;
#pragma unroll
            for (int nt = 0; nt < 8; nt++) {
                int p = warpW * 64 + nt * 8 + ((lane & 3) << 1);
                float v0 = d[mt][nt][half * 2 + 0] + bi;
                float v1 = d[mt][nt][half * 2 + 1] + bi;
                if (MODE) {
                    *(float2*)(g_crt + base + p) = make_float2(v0, v1);
                } else {
                    __half2 pk;
                    pk.x = __float2half_rn(v0);
                    pk.y = __float2half_rn(v1);
                    *(__half2*)(g_abh + base + p) = pk;
                }
            }
        }
    }
}

// ---------------------------------------------------------------------------
// scores via mma (1-term), split-K=2 over c. Block 128(t) x 128(s).
// ---------------------------------------------------------------------------
__global__ __launch_bounds__(256) void scores_mma_kernel()
{
    extern __shared__ __align__(16) __half sm[];
    __half* sA = sm;
    __half* sB = sm + 128 * SMP;

    int kh = blockIdx.z & 1, b = blockIdx.z >> 1;
    int i = b >> 3, n = b & 7;
    int sBlk = blockIdx.x << 7, tBlk = blockIdx.y << 7;
    size_t aOff = ((size_t)n * 256 + i * 64) * PP;
    size_t bOff = aOff + (size_t)32 * PP;

    int tid = threadIdx.x;
    int warp = tid >> 5, lane = tid & 31;
    int warpO = warp & 3, warpW = warp >> 2;

    float d[2][8][4];
#pragma unroll
    for (int a = 0; a < 2; a++)
#pragma unroll
        for (int bq = 0; bq < 8; bq++)
#pragma unroll
            for (int k = 0; k < 4; k++) d[a][bq][k] = 0.f;

    uint32_t uA = smem_u32(sA), uB = smem_u32(sB);
    int aRow = warpO * 32 + (lane & 15);
    int aColSel = (lane >> 4) << 3;
    int l16 = lane & 15;
    int bRowOff = warpW * 64 + (l16 & 7);
    int bColSel = ((l16 >> 3) & 1) << 3;

    int c0 = kh << 4;
    for (int c = c0; c < c0 + 16; c++) {
        const __half* aH = g_abh + aOff + (size_t)c * PP;
        const __half* bH = g_abh + bOff + (size_t)c * PP;
#pragma unroll 1
        for (int vh = 0; vh < 2; vh++) {
            int v0 = vh << 7;
            __syncthreads();
#pragma unroll
            for (int t = 0; t < 8; t++) {
                int idx = tid + t * 256;
                int r = idx >> 4, c8 = idx & 15;
                int doff = r * SMP + (c8 << 3);
                *(uint4*)(sA + doff) = *(const uint4*)(aH + (size_t)(tBlk + r) * 256 + v0 + (c8 << 3));
                *(uint4*)(sB + doff) = *(const uint4*)(bH + (size_t)(sBlk + r) * 256 + v0 + (c8 << 3));
            }
            __syncthreads();
#pragma unroll
            for (int kc = 0; kc < 8; kc++) {
                int k16 = kc << 4;
                uint32_t a4[2][4];
#pragma unroll
                for (int mt = 0; mt < 2; mt++) {
                    uint32_t off = (uint32_t)(((aRow + mt * 16) * SMP + k16 + aColSel) << 1);
                    ldsm_x4(a4[mt], uA + off);
                }
                uint32_t b2[8][2];
#pragma unroll
                for (int nt = 0; nt < 8; nt++) {
                    uint32_t off = (uint32_t)(((bRowOff + nt * 8) * SMP + k16 + bColSel) << 1);
                    ldsm_x2(b2[nt], uB + off);
                }
#pragma unroll
                for (int mt = 0; mt < 2; mt++)
#pragma unroll
                    for (int nt = 0; nt < 8; nt++)
                        mma_f16(d[mt][nt], a4[mt], b2[nt]);
            }
        }
    }

    float* dst = (kh ? g_adapt2 : g_adapt) + (size_t)b * PP;
    const float sc = 1.0f / 256.0f;
#pragma unroll
    for (int mt = 0; mt < 2; mt++) {
        int t0 = tBlk + warpO * 32 + mt * 16 + (lane >> 2);
#pragma unroll
        for (int half = 0; half < 2; half++) {
            int t = t0 + half * 8;
#pragma unroll
            for (int nt = 0; nt < 8; nt++) {
                int s = sBlk + warpW * 64 + nt * 8 + ((lane & 3) << 1);
                float2 ov;
                ov.x = d[mt][nt][half * 2 + 0] * sc;
                ov.y = d[mt][nt][half * 2 + 1] * sc;
                *(float2*)(dst + (size_t)t * 256 + s) = ov;
            }
        }
    }
}

// ---------------------------------------------------------------------------
__global__ __launch_bounds__(1024) void softmax_kernel(const float* __restrict__ mat_adj,
                                                       const float* __restrict__ adj_w)
{
    int b = blockIdx.x;
    int i = b >> 3;
    const float* p1 = g_adapt + (size_t)b * PP;
    const float* p2 = g_adapt2 + (size_t)b * PP;
    int s = threadIdx.x & 255, tq = threadIdx.x >> 8;
    __shared__ float red[4][256];
    int t0 = tq << 6, t1 = t0 + 64;
    float m = -1e30f;
    for (int t = t0; t < t1; t++) {
        int idx = t * 256 + s;
        m = fmaxf(m, p1[idx] + p2[idx]);
    }
    red[tq][s] = m;
    __syncthreads();
    m = fmaxf(fmaxf(red[0][s], red[1][s]), fmaxf(red[2][s], red[3][s]));
    __syncthreads();
    float sum = 0.f;
    for (int t = t0; t < t1; t++) {
        int idx = t * 256 + s;
        sum += expf(p1[idx] + p2[idx] - m);
    }
    red[tq][s] = sum;
    __syncthreads();
    sum = red[0][s] + red[1][s] + red[2][s] + red[3][s];
    float inv = 1.f / sum;
    const float* A1 = mat_adj + (size_t)i * PP;
    const float* A2 = adj_w + (size_t)i * PP;
    __half* dh = g_adh + (size_t)b * PP;
    for (int t = t0; t < t1; t++) {
        int idx = t * 256 + s;
        float e = expf(p1[idx] + p2[idx] - m) * inv;
        dh[idx] = __float2half_rn(A1[idx] + A2[idx] + e);
    }
}

// ---------------------------------------------------------------------------
// xa via mma (1-term), trans ldsm both operands; output fp16.
// ---------------------------------------------------------------------------
__global__ __launch_bounds__(256) void xa_mma_kernel()
{
    extern __shared__ __align__(16) __half sm[];
    __half* sA = sm;
    __half* sB = sm + 128 * SMP;

    int b2 = blockIdx.z;
    int c = b2 & 63, bn = b2 >> 6;
    int n = bn & 7;
    int sBlk = blockIdx.x << 7, vBlk = blockIdx.y << 7;
    const __half* xH = g_xh + ((size_t)n * 64 + c) * PP;
    const __half* aH = g_adh + (size_t)bn * PP;

    int tid = threadIdx.x;
    int warp = tid >> 5, lane = tid & 31;
    int warpV = warp & 3, warpS = warp >> 2;

    float d[2][8][4];
#pragma unroll
    for (int a = 0; a < 2; a++)
#pragma unroll
        for (int bq = 0; bq < 8; bq++)
#pragma unroll
            for (int k = 0; k < 4; k++) d[a][bq][k] = 0.f;

    uint32_t uA = smem_u32(sA), uB = smem_u32(sB);
    int tRowA = (lane & 7) + ((lane & 16) >> 1);
    int vColA = ((lane >> 3) & 1) << 3;
    int tRowB = lane & 15;

#pragma unroll 1
    for (int th = 0; th < 2; th++) {
        int t0 = th << 7;
        __syncthreads();
#pragma unroll
        for (int t = 0; t < 8; t++) {
            int idx = tid + t * 256;
            int r = idx >> 4, c8 = idx & 15;
            int doff = r * SMP + (c8 << 3);
            *(uint4*)(sA + doff) = *(const uint4*)(xH + (size_t)(t0 + r) * 256 + vBlk + (c8 << 3));
            *(uint4*)(sB + doff) = *(const uint4*)(aH + (size_t)(t0 + r) * 256 + sBlk + (c8 << 3));
        }
        __syncthreads();
#pragma unroll
        for (int kc = 0; kc < 8; kc++) {
            int k16 = kc << 4;
            uint32_t a4[2][4];
#pragma unroll
            for (int mt = 0; mt < 2; mt++) {
                int vCol = warpV * 32 + mt * 16 + vColA;
                uint32_t off = (uint32_t)(((k16 + tRowA) * SMP + vCol) << 1);
                ldsm_x4_t(a4[mt], uA + off);
            }
            uint32_t b2f[8][2];
#pragma unroll
            for (int nt = 0; nt < 8; nt++) {
                int sCol = warpS * 64 + nt * 8;
                uint32_t off = (uint32_t)(((k16 + tRowB) * SMP + sCol) << 1);
                ldsm_x2_t(b2f[nt], uB + off);
            }
#pragma unroll
            for (int mt = 0; mt < 2; mt++)
#pragma unroll
                for (int nt = 0; nt < 8; nt++)
                    mma_f16(d[mt][nt], a4[mt], b2f[nt]);
        }
    }

    __half* op = g_xab + (size_t)b2 * PP;
#pragma unroll
    for (int mt = 0; mt < 2; mt++) {
        int v0 = vBlk + warpV * 32 + mt * 16 + (lane >> 2);
#pragma unroll
        for (int half = 0; half < 2; half++) {
            int v = v0 + half * 8;
#pragma unroll
            for (int nt = 0; nt < 8; nt++) {
                int s = sBlk + warpS * 64 + nt * 8 + ((lane & 3) << 1);
                __half2 pk;
                pk.x = __float2half_rn(d[mt][nt][half * 2 + 0]);
                pk.y = __float2half_rn(d[mt][nt][half * 2 + 1]);
                *(__half2*)(op + (size_t)v * 256 + s) = pk;
            }
        }
    }
}

// ---------------------------------------------------------------------------
// y GEMM via mma (1-term).  M=128, K=192.
// ---------------------------------------------------------------------------
#define YPITCH 200
__global__ __launch_bounds__(256) void ygemm_mma_kernel()
{
    extern __shared__ __align__(16) __half sm[];
    __half* sA = sm;                   // 128 x 200
    __half* sB = sm + 128 * YPITCH;    // 16 x 136

    int pBlk = blockIdx.x << 7;
    int n    = blockIdx.z;
    int tid  = threadIdx.x;
    int warp = tid >> 5, lane = tid & 31;
    int warpO = warp & 3, warpW = warp >> 2;

    float d[2][8][4];
#pragma unroll
    for (int a = 0; a < 2; a++)
#pragma unroll
        for (int bq = 0; bq < 8; bq++)
#pragma unroll
            for (int k = 0; k < 4; k++) d[a][bq][k] = 0.f;

#pragma unroll
    for (int t = 0; t < 12; t++) {
        int idx = tid + t * 256;
        int r = idx / 24, c8 = idx - r * 24;
        *(uint4*)(sA + r * YPITCH + (c8 << 3)) = *(const uint4*)(g_Wdh + r * 192 + (c8 << 3));
    }

    uint32_t uA = smem_u32(sA), uB = smem_u32(sB);
    int aRow = warpO * 32 + (lane & 15);
    int aColSel = (lane >> 4) << 3;
    int tRowB = lane & 15;

    for (int kc = 0; kc < 12; kc++) {
        if (kc) __syncthreads();
        {
            int r = tid >> 4, c8 = tid & 15;
            int k = (kc << 4) + r;
            int i = k >> 6, cc = k & 63;
            *(uint4*)(sB + r * SMP + (c8 << 3)) =
                *(const uint4*)(g_xab + (size_t)((i << 9) + (n << 6) + cc) * PP + pBlk + (c8 << 3));
        }
        __syncthreads();
        int k16 = kc << 4;
        uint32_t a4[2][4];
#pragma unroll
        for (int mt = 0; mt < 2; mt++) {
            uint32_t off = (uint32_t)(((aRow + mt * 16) * YPITCH + k16 + aColSel) << 1);
            ldsm_x4(a4[mt], uA + off);
        }
        uint32_t b2[8][2];
#pragma unroll
        for (int nt = 0; nt < 8; nt++) {
            int sCol = warpW * 64 + nt * 8;
            uint32_t off = (uint32_t)((tRowB * SMP + sCol) << 1);
            ldsm_x2_t(b2[nt], uB + off);
        }
#pragma unroll
        for (int mt = 0; mt < 2; mt++)
#pragma unroll
            for (int nt = 0; nt < 8; nt++)
                mma_f16(d[mt][nt], a4[mt], b2[nt]);
    }

#pragma unroll
    for (int mt = 0; mt < 2; mt++) {
        int o0 = warpO * 32 + mt * 16 + (lane >> 2);
#pragma unroll
        for (int half = 0; half < 2; half++) {
            int o = o0 + half * 8;
            float bi = g_Bd[o];
            size_t base = ((size_t)(n * 128) + o) * PP + pBlk;
#pragma unroll
            for (int nt = 0; nt < 8; nt++) {
                int p = warpW * 64 + nt * 8 + ((lane & 3) << 1);
                float2 ov;
                ov.x = d[mt][nt][half * 2 + 0] + bi;
                ov.y = d[mt][nt][half * 2 + 1] + bi;
                *(float2*)(g_y + base + p) = ov;
            }
        }
    }
}

// ---------------------------------------------------------------------------
// gcnT = relu(bn_g(y) + bn_c(cres)) -> channel-last fp16 single
// ---------------------------------------------------------------------------
__global__ __launch_bounds__(256) void gcnT_kernel()
{
    int wBlk = blockIdx.x << 6;
    int h    = blockIdx.y;
    int n    = blockIdx.z;
    __shared__ float ts[64][129];
    int tid = threadIdx.x;
    int wl = tid & 63, cg = tid >> 6;
#pragma unroll 8
    for (int c = cg; c < 128; c += 4) {
        float sg = g_bnp[c], hg = g_bnp[128 + c];
        float sc = g_bnp[256 + c], hc = g_bnp[384 + c];
        float yv = g_y[(size_t)(n * 128 + c) * PP + h * 256 + wBlk + wl];
        float cv = g_crt[(size_t)(n * 256 + c) * PP + h * 256 + wBlk + wl];
        ts[wl][c] = fmaxf(yv * sg + hg + cv * sc + hc, 0.f);
    }
    __syncthreads();
    int c2 = (tid & 63) << 1;
    int w0 = tid >> 6;
#pragma unroll 8
    for (int w = w0; w < 64; w += 4) {
        __half2 ph;
        ph.x = __float2half_rn(ts[w][c2]);
        ph.y = __float2half_rn(ts[w][c2 + 1]);
        size_t base = ((size_t)(n * 256 + h) * 256 + wBlk + w) * 128 + c2;
        *(__half2*)(g_gT + base) = ph;
    }
}

// ---------------------------------------------------------------------------
// TCN via mma.sync fp16: A = W9 split hi/lo (2 terms), B = gcn single fp16.
// Double-buffered via cp.async (2 stages x 96KB).  Fused epilogue.
// ---------------------------------------------------------------------------
#define TSTAGE (3 * 128 * SMP)          // elems per stage (Ah | Al | B)
#define TBUF_B (128 * SMP * 2)          // bytes per operand buffer
__global__ __launch_bounds__(256) void tcn_mma_kernel(float* __restrict__ out)
{
    extern __shared__ __align__(16) __half sm[];

    int wBlk = blockIdx.x << 7;
    int h    = blockIdx.y;
    int n    = blockIdx.z;
    int tid  = threadIdx.x;
    int warp = tid >> 5, lane = tid & 31;
    int warpO = warp & 3, warpW = warp >> 2;

    float d[2][8][4];
#pragma unroll
    for (int i = 0; i < 2; i++)
#pragma unroll
        for (int j = 0; j < 8; j++)
#pragma unroll
            for (int k = 0; k < 4; k++) d[i][j][k] = 0.f;

    // valid tap list
    int k9L[9], nt = 0;
#pragma unroll
    for (int k9 = 0; k9 < 9; k9++) {
        int hs = h + k9 - 4;
        if ((unsigned)hs < 256u) k9L[nt++] = k9;
    }

    uint32_t uS0 = smem_u32(sm);
    uint32_t uS1 = uS0 + (uint32_t)(TSTAGE * 2);

    // fill stage: 3 buffers x 2048 uint4 -> 24 cp.async per thread
    int fr = tid >> 4, fc8 = tid & 15;
#define TCN_FILL(base_u32, ti)                                                    \
    {                                                                             \
        int k9_ = k9L[ti];                                                        \
        int hs_ = h + k9_ - 4;                                                    \
        const __half* wh_ = g_W9h + k9_ * 16384;                                  \
        const __half* wl_ = g_W9l + k9_ * 16384;                                  \
        const __half* gb_ = g_gT + ((size_t)(n * 256 + hs_) * 256 + wBlk) * 128;  \
        _Pragma("unroll")                                                         \
        for (int t_ = 0; t_ < 8; t_++) {                                          \
            int r_ = fr + t_ * 16;                                                \
            uint32_t doff = (uint32_t)((r_ * SMP + (fc8 << 3)) << 1);             \
            int goff = r_ * 128 + (fc8 << 3);                                     \
            CP_ASYNC((base_u32) + doff, wh_ + goff);                              \
            CP_ASYNC((base_u32) + TBUF_B + doff, wl_ + goff);                     \
            CP_ASYNC((base_u32) + 2 * TBUF_B + doff, gb_ + goff);                 \
        }                                                                         \
        CP_COMMIT();                                                              \
    }

    TCN_FILL(uS0, 0)

    int aRow = warpO * 32 + (lane & 15);
    int aColSel = (lane >> 4) << 3;
    int l16 = lane & 15;
    int bRowOff = warpW * 64 + (l16 & 7);
    int bColSel = ((l16 >> 3) & 1) << 3;

    uint32_t bases[2] = {uS0, uS1};
    int buf = 0;
    for (int it = 0; it < nt; it++) {
        if (it + 1 < nt) {
            TCN_FILL(bases[buf ^ 1], it + 1)
            CP_WAIT(1);
        } else {
            CP_WAIT(0);
        }
        __syncthreads();
        uint32_t uAh = bases[buf];
        uint32_t uAl = bases[buf] + TBUF_B;
        uint32_t uB  = bases[buf] + 2 * TBUF_B;
#pragma unroll
        for (int kc = 0; kc < 8; kc++) {
            int c0 = kc << 4;
            uint32_t ah[2][4], al[2][4];
#pragma unroll
            for (int mt = 0; mt < 2; mt++) {
                uint32_t off = (uint32_t)(((aRow + mt * 16) * SMP + c0 + aColSel) << 1);
                ldsm_x4(ah[mt], uAh + off);
                ldsm_x4(al[mt], uAl + off);
            }
            uint32_t b2[8][2];
#pragma unroll
            for (int ntt = 0; ntt < 8; ntt++) {
                uint32_t off = (uint32_t)(((bRowOff + ntt * 8) * SMP + c0 + bColSel) << 1);
                ldsm_x2(b2[ntt], uB + off);
            }
#pragma unroll
            for (int mt = 0; mt < 2; mt++)
#pragma unroll
                for (int ntt = 0; ntt < 8; ntt++) {
                    mma_f16(d[mt][ntt], ah[mt], b2[ntt]);
                    mma_f16(d[mt][ntt], al[mt], b2[ntt]);
                }
        }
        buf ^= 1;
        __syncthreads();
    }

    int oB = warpO * 32;
    int wB = wBlk + warpW * 64;
#pragma unroll
    for (int mt = 0; mt < 2; mt++) {
        int o0 = oB + mt * 16 + (lane >> 2);
#pragma unroll
        for (int half = 0; half < 2; half++) {
            int o = o0 + half * 8;
            float st = g_bnp[512 + o], ht = g_bnp[640 + o];
            float sr = g_bnp[768 + o], hr = g_bnp[896 + o];
            size_t ob = ((size_t)(n * 128 + o) * 256 + h) * 256;
            size_t rb = ((size_t)(n * 256 + 128 + o) * 256 + h) * 256;
#pragma unroll
            for (int ntt = 0; ntt < 8; ntt++) {
                int w = wB + ntt * 8 + ((lane & 3) << 1);
                float2 rv = *(const float2*)(g_crt + rb + w);
                float v0 = d[mt][ntt][half * 2 + 0];
                float v1 = d[mt][ntt][half * 2 + 1];
                float2 ov;
                ov.x = fmaxf(v0 * st + ht + rv.x * sr + hr, 0.f);
                ov.y = fmaxf(v1 * st + ht + rv.y * sr + hr, 0.f);
                *(float2*)(out + ob + w) = ov;
            }
        }
    }
}

// ---------------------------------------------------------------------------
extern "C" void kernel_launch(void* const* d_in, const int* in_sizes, int n_in,
                              void* d_out, int out_size)
{
    const float* x       = (const float*)d_in[0];
    const float* mat_adj = (const float*)d_in[1];
    const float* adj_w   = (const float*)d_in[2];
    const float* wa      = (const float*)d_in[3];
    const float* ba      = (const float*)d_in[4];
    const float* wb      = (const float*)d_in[5];
    const float* bb      = (const float*)d_in[6];
    const float* wd      = (const float*)d_in[7];
    const float* bd      = (const float*)d_in[8];
    const float* gcn_bn  = (const float*)d_in[9];
    const float* cres_w  = (const float*)d_in[10];
    const float* cres_b  = (const float*)d_in[11];
    const float* cres_bn = (const float*)d_in[12];
    const float* tcn_w   = (const float*)d_in[13];
    const float* tcn_b   = (const float*)d_in[14];
    const float* tcn_bn  = (const float*)d_in[15];
    const float* rt_w    = (const float*)d_in[16];
    const float* rt_b    = (const float*)d_in[17];
    const float* rt_bn   = (const float*)d_in[18];
    float* out = (float*)d_out;

    const int tcn_smem   = 2 * TSTAGE * 2;                    // 208896
    const int gem_smem   = 2 * 128 * SMP * 2;                 // 69632
    const int conv0_smem = (128 * APITCH + 64 * SMP) * 2;     // 35840
    const int conv1_smem = 2 * (128 * APITCH + 64 * SMP) * 2; // 71680
    const int ygemm_smem = (128 * YPITCH + 16 * SMP) * 2;     // 55552
    cudaFuncSetAttribute(tcn_mma_kernel,
                         cudaFuncAttributeMaxDynamicSharedMemorySize, tcn_smem);
    cudaFuncSetAttribute(scores_mma_kernel,
                         cudaFuncAttributeMaxDynamicSharedMemorySize, gem_smem);
    cudaFuncSetAttribute(xa_mma_kernel,
                         cudaFuncAttributeMaxDynamicSharedMemorySize, gem_smem);
    cudaFuncSetAttribute(conv_mma_kernel<0>,
                         cudaFuncAttributeMaxDynamicSharedMemorySize, conv0_smem);
    cudaFuncSetAttribute(conv_mma_kernel<1>,
                         cudaFuncAttributeMaxDynamicSharedMemorySize, conv1_smem);
    cudaFuncSetAttribute(ygemm_mma_kernel,
                         cudaFuncAttributeMaxDynamicSharedMemorySize, ygemm_smem);

    pack_kernel<<<128, 256>>>(wa, ba, wb, bb, wd, bd, cres_w, cres_b,
                              rt_w, rt_b, gcn_bn, cres_bn, tcn_bn, rt_bn,
                              tcn_w, tcn_b);
    xsplit_kernel<<<32768, 256>>>(x);
    conv_mma_kernel<0><<<dim3(512, 2, 8), 256, conv0_smem>>>();
    conv_mma_kernel<1><<<dim3(512, 2, 8), 256, conv1_smem>>>();
    scores_mma_kernel<<<dim3(2, 2, 48), 256, gem_smem>>>();
    softmax_kernel<<<24, 1024>>>(mat_adj, adj_w);
    xa_mma_kernel<<<dim3(2, 2, 1536), 256, gem_smem>>>();
    ygemm_mma_kernel<<<dim3(512, 1, 8), 256, ygemm_smem>>>();
    gcnT_kernel<<<dim3(4, 256, 8), 256>>>();
    tcn_mma_kernel<<<dim3(2, 256, 8), 256, tcn_smem>>>(out);
}

// round 11
// speedup vs baseline: 5.0588x; 1.0026x over previous
#include <cuda_runtime.h>
#include <cuda_fp16.h>
#include <math.h>
#include <stdint.h>

// ---------------------------------------------------------------------------
// Problem dims: N=8, C=64, COUT=128, T=V=256, S=3, IC=32, P=T*V=65536
// ---------------------------------------------------------------------------
#define PP 65536
#define SMP 136

__device__ __forceinline__ uint32_t smem_u32(const void* p) {
    uint32_t a;
    asm("{ .reg .u64 t; cvta.to.shared.u64 t, %1; cvt.u32.u64 %0, t; }"
        : "=r"(a) : "l"(p));
    return a;
}
__device__ __forceinline__ void ldsm_x4(uint32_t* r, uint32_t addr) {
    asm volatile("ldmatrix.sync.aligned.m8n8.x4.shared.b16 {%0,%1,%2,%3}, [%4];"
                 : "=r"(r[0]), "=r"(r[1]), "=r"(r[2]), "=r"(r[3]) : "r"(addr));
}
__device__ __forceinline__ void ldsm_x4_t(uint32_t* r, uint32_t addr) {
    asm volatile("ldmatrix.sync.aligned.m8n8.x4.trans.shared.b16 {%0,%1,%2,%3}, [%4];"
                 : "=r"(r[0]), "=r"(r[1]), "=r"(r[2]), "=r"(r[3]) : "r"(addr));
}
__device__ __forceinline__ void mma_f16(float* d, const uint32_t* a, const uint32_t* b) {
    asm volatile(
        "mma.sync.aligned.m16n8k16.row.col.f32.f16.f16.f32 "
        "{%0,%1,%2,%3}, {%4,%5,%6,%7}, {%8,%9}, {%0,%1,%2,%3};"
        : "+f"(d[0]), "+f"(d[1]), "+f"(d[2]), "+f"(d[3])
        : "r"(a[0]), "r"(a[1]), "r"(a[2]), "r"(a[3]), "r"(b[0]), "r"(b[1]));
}
__device__ __forceinline__ void hsplit(float v, __half& h, __half& l) {
    h = __float2half_rn(v);
    l = __float2half_rn(v - __half2float(h));
}
#define CP_ASYNC(dst, src) \
    asm volatile("cp.async.cg.shared.global [%0], [%1], 16;" :: "r"(dst), "l"(src))
#define CP_COMMIT() asm volatile("cp.async.commit_group;")
#define CP_WAIT(N)  asm volatile("cp.async.wait_group %0;" :: "n"(N))

// ------------------------- packed parameters -------------------------------
__device__ __half g_Wabh[256 * 64];        // single (y-path)
__device__ float g_Bab[256];
__device__ __half g_Wcrth[256 * 64];       // hi/lo (precision path)
__device__ __half g_Wcrtl[256 * 64];
__device__ float g_Bcrt[256];
__device__ __half g_Wdh[128 * 192];        // single
__device__ float g_Bd[128];
__device__ float g_bnp[1024];              // sg,hg, sc,hc, st,ht2, sr,hr
__device__ __half g_W9h[9 * 128 * 128];    // [k9][o][c] hi
__device__ __half g_W9l[9 * 128 * 128];    // lo

// ------------------------- scratch buffers ---------------------------------
__device__ __half g_abh[134217728];  // [n][256][PP] embeds (fp16 single)
__device__ __half g_xh[33554432];    // x fp16 single
__device__ __half g_adh[1572864];    // adapt fp16
__device__ float g_adapt[1572864];   // scores partial kh=0
__device__ float g_adapt2[1572864];  // scores partial kh=1
__device__ __half g_xab[100663296];  // xa out fp16
__device__ float g_y[67108864];
__device__ float g_crt[134217728];   // (cres | rt) fp32
__device__ __half g_gT[67108864];    // [n][h][w][c] gcn fp16 single

// ---------------------------------------------------------------------------
__global__ void pack_kernel(const float* __restrict__ wa, const float* __restrict__ ba,
                            const float* __restrict__ wb, const float* __restrict__ bb,
                            const float* __restrict__ wd, const float* __restrict__ bd,
                            const float* __restrict__ cres_w, const float* __restrict__ cres_b,
                            const float* __restrict__ rt_w, const float* __restrict__ rt_b,
                            const float* __restrict__ gcn_bn, const float* __restrict__ cres_bn,
                            const float* __restrict__ tcn_bn, const float* __restrict__ rt_bn,
                            const float* __restrict__ tcn_w, const float* __restrict__ tcn_b)
{
    int tid = blockIdx.x * blockDim.x + threadIdx.x;
    int nth = gridDim.x * blockDim.x;
    for (int idx = tid; idx < 256 * 64; idx += nth) {
        int o = idx >> 6, c = idx & 63;
        int i = o >> 6, sub = o & 63;
        float v = 0.f;
        if (o < 192) v = (sub < 32) ? wa[(i * 32 + sub) * 64 + c]
                                    : wb[(i * 32 + sub - 32) * 64 + c];
        g_Wabh[idx] = __float2half_rn(v);
    }
    for (int o = tid; o < 256; o += nth) {
        int i = o >> 6, sub = o & 63;
        float v = 0.f;
        if (o < 192) v = (sub < 32) ? ba[i * 32 + sub] : bb[i * 32 + sub - 32];
        g_Bab[o] = v;
    }
    for (int idx = tid; idx < 256 * 64; idx += nth) {
        int o = idx >> 6, c = idx & 63;
        float v = (o < 128) ? cres_w[o * 64 + c] : rt_w[(o - 128) * 64 + c];
        __half h, l;
        hsplit(v, h, l);
        g_Wcrth[idx] = h; g_Wcrtl[idx] = l;
    }
    for (int o = tid; o < 256; o += nth)
        g_Bcrt[o] = (o < 128) ? cres_b[o] : rt_b[o - 128];
    for (int idx = tid; idx < 128 * 192; idx += nth) {
        int o = idx / 192, k = idx - o * 192;
        int i = k >> 6, c = k & 63;
        g_Wdh[idx] = __float2half_rn(wd[(i * 128 + o) * 64 + c]);
    }
    for (int o = tid; o < 128; o += nth)
        g_Bd[o] = bd[o] + bd[128 + o] + bd[256 + o];
    for (int idx = tid; idx < 9 * 128 * 128; idx += nth) {
        int k9 = idx >> 14;
        int rem = idx & 16383;
        int o = rem >> 7, c = rem & 127;
        float v = tcn_w[o * 1152 + c * 9 + k9];
        __half h, l;
        hsplit(v, h, l);
        g_W9h[idx] = h; g_W9l[idx] = l;
    }
    for (int o = tid; o < 128; o += nth) {
        float g, b, m, v, s;
        g = gcn_bn[o]; b = gcn_bn[128 + o]; m = gcn_bn[256 + o]; v = gcn_bn[384 + o];
        s = g * rsqrtf(v + 1e-5f);
        g_bnp[o] = s; g_bnp[128 + o] = b - m * s;
        g = cres_bn[o]; b = cres_bn[128 + o]; m = cres_bn[256 + o]; v = cres_bn[384 + o];
        s = g * rsqrtf(v + 1e-5f);
        g_bnp[256 + o] = s; g_bnp[384 + o] = b - m * s;
        g = tcn_bn[o]; b = tcn_bn[128 + o]; m = tcn_bn[256 + o]; v = tcn_bn[384 + o];
        s = g * rsqrtf(v + 1e-5f);
        g_bnp[512 + o] = s; g_bnp[640 + o] = (tcn_b[o] - m) * s + b;
        g = rt_bn[o]; b = rt_bn[128 + o]; m = rt_bn[256 + o]; v = rt_bn[384 + o];
        s = g * rsqrtf(v + 1e-5f);
        g_bnp[768 + o] = s; g_bnp[896 + o] = b - m * s;
    }
}

// ---------------------------------------------------------------------------
// x -> fp16 (hi only)
// ---------------------------------------------------------------------------
__global__ __launch_bounds__(256) void xsplit_kernel(const float* __restrict__ x)
{
    size_t i = (size_t)blockIdx.x * 256 + threadIdx.x;   // 8388608 float4
    float4 v = ((const float4*)x)[i];
    __half2 ph0, ph1;
    ph0.x = __float2half_rn(v.x); ph0.y = __float2half_rn(v.y);
    ph1.x = __float2half_rn(v.z); ph1.y = __float2half_rn(v.w);
    *(__half2*)(g_xh + i * 4) = ph0;
    *(__half2*)(g_xh + i * 4 + 2) = ph1;
}

// ---------------------------------------------------------------------------
// conv1x1 via MMA. K=64.  MODE 0: 1-term, out fp16 embeds.
// MODE 1: 2-term (W hi/lo, x single), out fp32 crt.
// B fragments loaded paired (ldsm.x4.trans covers 2 n-tiles).
// ---------------------------------------------------------------------------
#define APITCH 72
template <int MODE>
__global__ __launch_bounds__(256) void conv_mma_kernel()
{
    extern __shared__ __align__(16) __half sm[];
    __half* sAh = sm;                                  // 128 x 72
    __half* sAl = sm + 128 * APITCH;                   // MODE1 only
    __half* sBh = sm + (MODE ? 2 : 1) * 128 * APITCH;  // 64 x 136

    int pBlk = blockIdx.x << 7;
    int oBlk = blockIdx.y << 7;
    int n    = blockIdx.z;
    int tid  = threadIdx.x;
    int warp = tid >> 5, lane = tid & 31;
    int warpO = warp & 3, warpW = warp >> 2;

    const __half* Wh = MODE ? g_Wcrth : g_Wabh;

    float d[2][8][4];
#pragma unroll
    for (int a = 0; a < 2; a++)
#pragma unroll
        for (int bq = 0; bq < 8; bq++)
#pragma unroll
            for (int k = 0; k < 4; k++) d[a][bq][k] = 0.f;

#pragma unroll
    for (int t = 0; t < 4; t++) {
        int idx = tid + t * 256;
        int r = idx >> 3, c8 = idx & 7;
        int doff = r * APITCH + (c8 << 3);
        *(uint4*)(sAh + doff) = *(const uint4*)(Wh + (oBlk + r) * 64 + (c8 << 3));
        if (MODE)
            *(uint4*)(sAl + doff) = *(const uint4*)(g_Wcrtl + (oBlk + r) * 64 + (c8 << 3));
    }
#pragma unroll
    for (int t = 0; t < 4; t++) {
        int idx = tid + t * 256;
        int r = idx >> 4, c8 = idx & 15;
        int doff = r * SMP + (c8 << 3);
        *(uint4*)(sBh + doff) = *(const uint4*)(g_xh + ((size_t)n * 64 + r) * PP + pBlk + (c8 << 3));
    }
    __syncthreads();

    uint32_t uAh = smem_u32(sAh), uAl = smem_u32(sAl);
    uint32_t uBh = smem_u32(sBh);
    int aRow = warpO * 32 + (lane & 15);
    int aColSel = (lane >> 4) << 3;
    // trans-paired B: row = k16 + (lane&15), col = base + ((lane>>4)<<3)
    int bRowT = lane & 15;
    int bColT = (lane >> 4) << 3;

#pragma unroll
    for (int kc = 0; kc < 4; kc++) {
        int k16 = kc << 4;
        uint32_t ah[2][4], al[2][4];
#pragma unroll
        for (int mt = 0; mt < 2; mt++) {
            uint32_t off = (uint32_t)(((aRow + mt * 16) * APITCH + k16 + aColSel) << 1);
            ldsm_x4(ah[mt], uAh + off);
            if (MODE) ldsm_x4(al[mt], uAl + off);
        }
        uint32_t b2[8][2];
#pragma unroll
        for (int ntp = 0; ntp < 4; ntp++) {
            int sCol = warpW * 64 + ntp * 16 + bColT;
            uint32_t off = (uint32_t)(((k16 + bRowT) * SMP + sCol) << 1);
            ldsm_x4_t(&b2[2 * ntp][0], uBh + off);
        }
#pragma unroll
        for (int mt = 0; mt < 2; mt++)
#pragma unroll
            for (int nt = 0; nt < 8; nt++) {
                mma_f16(d[mt][nt], ah[mt], b2[nt]);
                if (MODE) mma_f16(d[mt][nt], al[mt], b2[nt]);
            }
    }

#pragma unroll
    for (int mt = 0; mt < 2; mt++) {
        int o0 = oBlk + warpO * 32 + mt * 16 + (lane >> 2);
#pragma unroll
        for (int half = 0; half < 2; half++) {
            int o = o0 + half * 8;
            float bi = MODE ? g_Bcrt[o] : g_Bab[o];
            size_t base = ((size_t)n * 256 + o) * PP + pBlk;
#pragma unroll
            for (int nt = 0; nt < 8; nt++) {
                int p = warpW * 64 + nt * 8 + ((lane & 3) << 1);
                float v0 = d[mt][nt][half * 2 + 0] + bi;
                float v1 = d[mt][nt][half * 2 + 1] + bi;
                if (MODE) {
                    *(float2*)(g_crt + base + p) = make_float2(v0, v1);
                } else {
                    __half2 pk;
                    pk.x = __float2half_rn(v0);
                    pk.y = __float2half_rn(v1);
                    *(__half2*)(g_abh + base + p) = pk;
                }
            }
        }
    }
}

// ---------------------------------------------------------------------------
// scores via mma (1-term), split-K=2 over c. Block 128(t) x 128(s).
// B paired non-trans ldsm.x4.
// ---------------------------------------------------------------------------
__global__ __launch_bounds__(256) void scores_mma_kernel()
{
    extern __shared__ __align__(16) __half sm[];
    __half* sA = sm;
    __half* sB = sm + 128 * SMP;

    int kh = blockIdx.z & 1, b = blockIdx.z >> 1;
    int i = b >> 3, n = b & 7;
    int sBlk = blockIdx.x << 7, tBlk = blockIdx.y << 7;
    size_t aOff = ((size_t)n * 256 + i * 64) * PP;
    size_t bOff = aOff + (size_t)32 * PP;

    int tid = threadIdx.x;
    int warp = tid >> 5, lane = tid & 31;
    int warpO = warp & 3, warpW = warp >> 2;

    float d[2][8][4];
#pragma unroll
    for (int a = 0; a < 2; a++)
#pragma unroll
        for (int bq = 0; bq < 8; bq++)
#pragma unroll
            for (int k = 0; k < 4; k++) d[a][bq][k] = 0.f;

    uint32_t uA = smem_u32(sA), uB = smem_u32(sB);
    int aRow = warpO * 32 + (lane & 15);
    int aColSel = (lane >> 4) << 3;
    // non-trans paired B: row = base + (lane&7) + ((lane>>4)<<3), col = k16 + ((lane>>3)&1)<<3
    int bRowP = warpW * 64 + (lane & 7) + ((lane >> 4) << 3);
    int bColP = ((lane >> 3) & 1) << 3;

    int c0 = kh << 4;
    for (int c = c0; c < c0 + 16; c++) {
        const __half* aH = g_abh + aOff + (size_t)c * PP;
        const __half* bH = g_abh + bOff + (size_t)c * PP;
#pragma unroll 1
        for (int vh = 0; vh < 2; vh++) {
            int v0 = vh << 7;
            __syncthreads();
#pragma unroll
            for (int t = 0; t < 8; t++) {
                int idx = tid + t * 256;
                int r = idx >> 4, c8 = idx & 15;
                int doff = r * SMP + (c8 << 3);
                *(uint4*)(sA + doff) = *(const uint4*)(aH + (size_t)(tBlk + r) * 256 + v0 + (c8 << 3));
                *(uint4*)(sB + doff) = *(const uint4*)(bH + (size_t)(sBlk + r) * 256 + v0 + (c8 << 3));
            }
            __syncthreads();
#pragma unroll
            for (int kc = 0; kc < 8; kc++) {
                int k16 = kc << 4;
                uint32_t a4[2][4];
#pragma unroll
                for (int mt = 0; mt < 2; mt++) {
                    uint32_t off = (uint32_t)(((aRow + mt * 16) * SMP + k16 + aColSel) << 1);
                    ldsm_x4(a4[mt], uA + off);
                }
                uint32_t b2[8][2];
#pragma unroll
                for (int ntp = 0; ntp < 4; ntp++) {
                    uint32_t off = (uint32_t)(((bRowP + ntp * 16) * SMP + k16 + bColP) << 1);
                    ldsm_x4(&b2[2 * ntp][0], uB + off);
                }
#pragma unroll
                for (int mt = 0; mt < 2; mt++)
#pragma unroll
                    for (int nt = 0; nt < 8; nt++)
                        mma_f16(d[mt][nt], a4[mt], b2[nt]);
            }
        }
    }

    float* dst = (kh ? g_adapt2 : g_adapt) + (size_t)b * PP;
    const float sc = 1.0f / 256.0f;
#pragma unroll
    for (int mt = 0; mt < 2; mt++) {
        int t0 = tBlk + warpO * 32 + mt * 16 + (lane >> 2);
#pragma unroll
        for (int half = 0; half < 2; half++) {
            int t = t0 + half * 8;
#pragma unroll
            for (int nt = 0; nt < 8; nt++) {
                int s = sBlk + warpW * 64 + nt * 8 + ((lane & 3) << 1);
                float2 ov;
                ov.x = d[mt][nt][half * 2 + 0] * sc;
                ov.y = d[mt][nt][half * 2 + 1] * sc;
                *(float2*)(dst + (size_t)t * 256 + s) = ov;
            }
        }
    }
}

// ---------------------------------------------------------------------------
__global__ __launch_bounds__(1024) void softmax_kernel(const float* __restrict__ mat_adj,
                                                       const float* __restrict__ adj_w)
{
    int b = blockIdx.x;
    int i = b >> 3;
    const float* p1 = g_adapt + (size_t)b * PP;
    const float* p2 = g_adapt2 + (size_t)b * PP;
    int s = threadIdx.x & 255, tq = threadIdx.x >> 8;
    __shared__ float red[4][256];
    int t0 = tq << 6, t1 = t0 + 64;
    float m = -1e30f;
    for (int t = t0; t < t1; t++) {
        int idx = t * 256 + s;
        m = fmaxf(m, p1[idx] + p2[idx]);
    }
    red[tq][s] = m;
    __syncthreads();
    m = fmaxf(fmaxf(red[0][s], red[1][s]), fmaxf(red[2][s], red[3][s]));
    __syncthreads();
    float sum = 0.f;
    for (int t = t0; t < t1; t++) {
        int idx = t * 256 + s;
        sum += expf(p1[idx] + p2[idx] - m);
    }
    red[tq][s] = sum;
    __syncthreads();
    sum = red[0][s] + red[1][s] + red[2][s] + red[3][s];
    float inv = 1.f / sum;
    const float* A1 = mat_adj + (size_t)i * PP;
    const float* A2 = adj_w + (size_t)i * PP;
    __half* dh = g_adh + (size_t)b * PP;
    for (int t = t0; t < t1; t++) {
        int idx = t * 256 + s;
        float e = expf(p1[idx] + p2[idx] - m) * inv;
        dh[idx] = __float2half_rn(A1[idx] + A2[idx] + e);
    }
}

// ---------------------------------------------------------------------------
// xa via mma (1-term), trans ldsm both operands; B paired; output fp16.
// ---------------------------------------------------------------------------
__global__ __launch_bounds__(256) void xa_mma_kernel()
{
    extern __shared__ __align__(16) __half sm[];
    __half* sA = sm;
    __half* sB = sm + 128 * SMP;

    int b2i = blockIdx.z;
    int c = b2i & 63, bn = b2i >> 6;
    int n = bn & 7;
    int sBlk = blockIdx.x << 7, vBlk = blockIdx.y << 7;
    const __half* xH = g_xh + ((size_t)n * 64 + c) * PP;
    const __half* aH = g_adh + (size_t)bn * PP;

    int tid = threadIdx.x;
    int warp = tid >> 5, lane = tid & 31;
    int warpV = warp & 3, warpS = warp >> 2;

    float d[2][8][4];
#pragma unroll
    for (int a = 0; a < 2; a++)
#pragma unroll
        for (int bq = 0; bq < 8; bq++)
#pragma unroll
            for (int k = 0; k < 4; k++) d[a][bq][k] = 0.f;

    uint32_t uA = smem_u32(sA), uB = smem_u32(sB);
    int tRowA = (lane & 7) + ((lane & 16) >> 1);
    int vColA = ((lane >> 3) & 1) << 3;
    int bRowT = lane & 15;
    int bColT = (lane >> 4) << 3;

#pragma unroll 1
    for (int th = 0; th < 2; th++) {
        int t0 = th << 7;
        __syncthreads();
#pragma unroll
        for (int t = 0; t < 8; t++) {
            int idx = tid + t * 256;
            int r = idx >> 4, c8 = idx & 15;
            int doff = r * SMP + (c8 << 3);
            *(uint4*)(sA + doff) = *(const uint4*)(xH + (size_t)(t0 + r) * 256 + vBlk + (c8 << 3));
            *(uint4*)(sB + doff) = *(const uint4*)(aH + (size_t)(t0 + r) * 256 + sBlk + (c8 << 3));
        }
        __syncthreads();
#pragma unroll
        for (int kc = 0; kc < 8; kc++) {
            int k16 = kc << 4;
            uint32_t a4[2][4];
#pragma unroll
            for (int mt = 0; mt < 2; mt++) {
                int vCol = warpV * 32 + mt * 16 + vColA;
                uint32_t off = (uint32_t)(((k16 + tRowA) * SMP + vCol) << 1);
                ldsm_x4_t(a4[mt], uA + off);
            }
            uint32_t b2[8][2];
#pragma unroll
            for (int ntp = 0; ntp < 4; ntp++) {
                int sCol = warpS * 64 + ntp * 16 + bColT;
                uint32_t off = (uint32_t)(((k16 + bRowT) * SMP + sCol) << 1);
                ldsm_x4_t(&b2[2 * ntp][0], uB + off);
            }
#pragma unroll
            for (int mt = 0; mt < 2; mt++)
#pragma unroll
                for (int nt = 0; nt < 8; nt++)
                    mma_f16(d[mt][nt], a4[mt], b2[nt]);
        }
    }

    __half* op = g_xab + (size_t)b2i * PP;
#pragma unroll
    for (int mt = 0; mt < 2; mt++) {
        int v0 = vBlk + warpV * 32 + mt * 16 + (lane >> 2);
#pragma unroll
        for (int half = 0; half < 2; half++) {
            int v = v0 + half * 8;
#pragma unroll
            for (int nt = 0; nt < 8; nt++) {
                int s = sBlk + warpS * 64 + nt * 8 + ((lane & 3) << 1);
                __half2 pk;
                pk.x = __float2half_rn(d[mt][nt][half * 2 + 0]);
                pk.y = __float2half_rn(d[mt][nt][half * 2 + 1]);
                *(__half2*)(op + (size_t)v * 256 + s) = pk;
            }
        }
    }
}

// ---------------------------------------------------------------------------
// y GEMM via mma (1-term).  M=128, K=192.  B paired trans.
// ---------------------------------------------------------------------------
#define YPITCH 200
__global__ __launch_bounds__(256) void ygemm_mma_kernel()
{
    extern __shared__ __align__(16) __half sm[];
    __half* sA = sm;                   // 128 x 200
    __half* sB = sm + 128 * YPITCH;    // 16 x 136

    int pBlk = blockIdx.x << 7;
    int n    = blockIdx.z;
    int tid  = threadIdx.x;
    int warp = tid >> 5, lane = tid & 31;
    int warpO = warp & 3, warpW = warp >> 2;

    float d[2][8][4];
#pragma unroll
    for (int a = 0; a < 2; a++)
#pragma unroll
        for (int bq = 0; bq < 8; bq++)
#pragma unroll
            for (int k = 0; k < 4; k++) d[a][bq][k] = 0.f;

#pragma unroll
    for (int t = 0; t < 12; t++) {
        int idx = tid + t * 256;
        int r = idx / 24, c8 = idx - r * 24;
        *(uint4*)(sA + r * YPITCH + (c8 << 3)) = *(const uint4*)(g_Wdh + r * 192 + (c8 << 3));
    }

    uint32_t uA = smem_u32(sA), uB = smem_u32(sB);
    int aRow = warpO * 32 + (lane & 15);
    int aColSel = (lane >> 4) << 3;
    int bRowT = lane & 15;
    int bColT = (lane >> 4) << 3;

    for (int kc = 0; kc < 12; kc++) {
        if (kc) __syncthreads();
        {
            int r = tid >> 4, c8 = tid & 15;
            int k = (kc << 4) + r;
            int i = k >> 6, cc = k & 63;
            *(uint4*)(sB + r * SMP + (c8 << 3)) =
                *(const uint4*)(g_xab + (size_t)((i << 9) + (n << 6) + cc) * PP + pBlk + (c8 << 3));
        }
        __syncthreads();
        int k16 = kc << 4;
        uint32_t a4[2][4];
#pragma unroll
        for (int mt = 0; mt < 2; mt++) {
            uint32_t off = (uint32_t)(((aRow + mt * 16) * YPITCH + k16 + aColSel) << 1);
            ldsm_x4(a4[mt], uA + off);
        }
        uint32_t b2[8][2];
#pragma unroll
        for (int ntp = 0; ntp < 4; ntp++) {
            int sCol = warpW * 64 + ntp * 16 + bColT;
            uint32_t off = (uint32_t)((bRowT * SMP + sCol) << 1);
            ldsm_x4_t(&b2[2 * ntp][0], uB + off);
        }
#pragma unroll
        for (int mt = 0; mt < 2; mt++)
#pragma unroll
            for (int nt = 0; nt < 8; nt++)
                mma_f16(d[mt][nt], a4[mt], b2[nt]);
    }

#pragma unroll
    for (int mt = 0; mt < 2; mt++) {
        int o0 = warpO * 32 + mt * 16 + (lane >> 2);
#pragma unroll
        for (int half = 0; half < 2; half++) {
            int o = o0 + half * 8;
            float bi = g_Bd[o];
            size_t base = ((size_t)(n * 128) + o) * PP + pBlk;
#pragma unroll
            for (int nt = 0; nt < 8; nt++) {
                int p = warpW * 64 + nt * 8 + ((lane & 3) << 1);
                float2 ov;
                ov.x = d[mt][nt][half * 2 + 0] + bi;
                ov.y = d[mt][nt][half * 2 + 1] + bi;
                *(float2*)(g_y + base + p) = ov;
            }
        }
    }
}

// ---------------------------------------------------------------------------
// gcnT = relu(bn_g(y) + bn_c(cres)) -> channel-last fp16 single
// ---------------------------------------------------------------------------
__global__ __launch_bounds__(256) void gcnT_kernel()
{
    int wBlk = blockIdx.x << 6;
    int h    = blockIdx.y;
    int n    = blockIdx.z;
    __shared__ float ts[64][129];
    int tid = threadIdx.x;
    int wl = tid & 63, cg = tid >> 6;
#pragma unroll 8
    for (int c = cg; c < 128; c += 4) {
        float sg = g_bnp[c], hg = g_bnp[128 + c];
        float sc = g_bnp[256 + c], hc = g_bnp[384 + c];
        float yv = g_y[(size_t)(n * 128 + c) * PP + h * 256 + wBlk + wl];
        float cv = g_crt[(size_t)(n * 256 + c) * PP + h * 256 + wBlk + wl];
        ts[wl][c] = fmaxf(yv * sg + hg + cv * sc + hc, 0.f);
    }
    __syncthreads();
    int c2 = (tid & 63) << 1;
    int w0 = tid >> 6;
#pragma unroll 8
    for (int w = w0; w < 64; w += 4) {
        __half2 ph;
        ph.x = __float2half_rn(ts[w][c2]);
        ph.y = __float2half_rn(ts[w][c2 + 1]);
        size_t base = ((size_t)(n * 256 + h) * 256 + wBlk + w) * 128 + c2;
        *(__half2*)(g_gT + base) = ph;
    }
}

// ---------------------------------------------------------------------------
// TCN via mma.sync fp16: A = W9 hi/lo (2 terms), B = gcn single fp16.
// cp.async double-buffered; B paired ldsm.x4.  Fused epilogue.
// ---------------------------------------------------------------------------
#define TSTAGE (3 * 128 * SMP)          // elems per stage (Ah | Al | B)
#define TBUF_B (128 * SMP * 2)          // bytes per operand buffer
__global__ __launch_bounds__(256) void tcn_mma_kernel(float* __restrict__ out)
{
    extern __shared__ __align__(16) __half sm[];

    int wBlk = blockIdx.x << 7;
    int h    = blockIdx.y;
    int n    = blockIdx.z;
    int tid  = threadIdx.x;
    int warp = tid >> 5, lane = tid & 31;
    int warpO = warp & 3, warpW = warp >> 2;

    float d[2][8][4];
#pragma unroll
    for (int i = 0; i < 2; i++)
#pragma unroll
        for (int j = 0; j < 8; j++)
#pragma unroll
            for (int k = 0; k < 4; k++) d[i][j][k] = 0.f;

    int k9L[9], nt = 0;
#pragma unroll
    for (int k9 = 0; k9 < 9; k9++) {
        int hs = h + k9 - 4;
        if ((unsigned)hs < 256u) k9L[nt++] = k9;
    }

    uint32_t uS0 = smem_u32(sm);
    uint32_t uS1 = uS0 + (uint32_t)(TSTAGE * 2);

    int fr = tid >> 4, fc8 = tid & 15;
#define TCN_FILL(base_u32, ti)                                                    \
    {                                                                             \
        int k9_ = k9L[ti];                                                        \
        int hs_ = h + k9_ - 4;                                                    \
        const __half* wh_ = g_W9h + k9_ * 16384;                                  \
        const __half* wl_ = g_W9l + k9_ * 16384;                                  \
        const __half* gb_ = g_gT + ((size_t)(n * 256 + hs_) * 256 + wBlk) * 128;  \
        _Pragma("unroll")                                                         \
        for (int t_ = 0; t_ < 8; t_++) {                                          \
            int r_ = fr + t_ * 16;                                                \
            uint32_t doff = (uint32_t)((r_ * SMP + (fc8 << 3)) << 1);             \
            int goff = r_ * 128 + (fc8 << 3);                                     \
            CP_ASYNC((base_u32) + doff, wh_ + goff);                              \
            CP_ASYNC((base_u32) + TBUF_B + doff, wl_ + goff);                     \
            CP_ASYNC((base_u32) + 2 * TBUF_B + doff, gb_ + goff);                 \
        }                                                                         \
        CP_COMMIT();                                                              \
    }

    TCN_FILL(uS0, 0)

    int aRow = warpO * 32 + (lane & 15);
    int aColSel = (lane >> 4) << 3;
    int bRowP = warpW * 64 + (lane & 7) + ((lane >> 4) << 3);
    int bColP = ((lane >> 3) & 1) << 3;

    uint32_t bases[2] = {uS0, uS1};
    int buf = 0;
    for (int it = 0; it < nt; it++) {
        if (it + 1 < nt) {
            TCN_FILL(bases[buf ^ 1], it + 1)
            CP_WAIT(1);
        } else {
            CP_WAIT(0);
        }
        __syncthreads();
        uint32_t uAh = bases[buf];
        uint32_t uAl = bases[buf] + TBUF_B;
        uint32_t uB  = bases[buf] + 2 * TBUF_B;
#pragma unroll
        for (int kc = 0; kc < 8; kc++) {
            int c0 = kc << 4;
            uint32_t ah[2][4], al[2][4];
#pragma unroll
            for (int mt = 0; mt < 2; mt++) {
                uint32_t off = (uint32_t)(((aRow + mt * 16) * SMP + c0 + aColSel) << 1);
                ldsm_x4(ah[mt], uAh + off);
                ldsm_x4(al[mt], uAl + off);
            }
            uint32_t b2[8][2];
#pragma unroll
            for (int ntp = 0; ntp < 4; ntp++) {
                uint32_t off = (uint32_t)(((bRowP + ntp * 16) * SMP + c0 + bColP) << 1);
                ldsm_x4(&b2[2 * ntp][0], uB + off);
            }
#pragma unroll
            for (int mt = 0; mt < 2; mt++)
#pragma unroll
                for (int ntt = 0; ntt < 8; ntt++) {
                    mma_f16(d[mt][ntt], ah[mt], b2[ntt]);
                    mma_f16(d[mt][ntt], al[mt], b2[ntt]);
                }
        }
        buf ^= 1;
        __syncthreads();
    }

    int oB = warpO * 32;
    int wB = wBlk + warpW * 64;
#pragma unroll
    for (int mt = 0; mt < 2; mt++) {
        int o0 = oB + mt * 16 + (lane >> 2);
#pragma unroll
        for (int half = 0; half < 2; half++) {
            int o = o0 + half * 8;
            float st = g_bnp[512 + o], ht = g_bnp[640 + o];
            float sr = g_bnp[768 + o], hr = g_bnp[896 + o];
            size_t ob = ((size_t)(n * 128 + o) * 256 + h) * 256;
            size_t rb = ((size_t)(n * 256 + 128 + o) * 256 + h) * 256;
#pragma unroll
            for (int ntt = 0; ntt < 8; ntt++) {
                int w = wB + ntt * 8 + ((lane & 3) << 1);
                float2 rv = *(const float2*)(g_crt + rb + w);
                float v0 = d[mt][ntt][half * 2 + 0];
                float v1 = d[mt][ntt][half * 2 + 1];
                float2 ov;
                ov.x = fmaxf(v0 * st + ht + rv.x * sr + hr, 0.f);
                ov.y = fmaxf(v1 * st + ht + rv.y * sr + hr, 0.f);
                *(float2*)(out + ob + w) = ov;
            }
        }
    }
}

// ---------------------------------------------------------------------------
extern "C" void kernel_launch(void* const* d_in, const int* in_sizes, int n_in,
                              void* d_out, int out_size)
{
    const float* x       = (const float*)d_in[0];
    const float* mat_adj = (const float*)d_in[1];
    const float* adj_w   = (const float*)d_in[2];
    const float* wa      = (const float*)d_in[3];
    const float* ba      = (const float*)d_in[4];
    const float* wb      = (const float*)d_in[5];
    const float* bb      = (const float*)d_in[6];
    const float* wd      = (const float*)d_in[7];
    const float* bd      = (const float*)d_in[8];
    const float* gcn_bn  = (const float*)d_in[9];
    const float* cres_w  = (const float*)d_in[10];
    const float* cres_b  = (const float*)d_in[11];
    const float* cres_bn = (const float*)d_in[12];
    const float* tcn_w   = (const float*)d_in[13];
    const float* tcn_b   = (const float*)d_in[14];
    const float* tcn_bn  = (const float*)d_in[15];
    const float* rt_w    = (const float*)d_in[16];
    const float* rt_b    = (const float*)d_in[17];
    const float* rt_bn   = (const float*)d_in[18];
    float* out = (float*)d_out;

    const int tcn_smem   = 2 * TSTAGE * 2;                    // 208896
    const int gem_smem   = 2 * 128 * SMP * 2;                 // 69632
    const int conv0_smem = (128 * APITCH + 64 * SMP) * 2;     // 35840
    const int conv1_smem = (2 * 128 * APITCH + 64 * SMP) * 2; // 54272
    const int ygemm_smem = (128 * YPITCH + 16 * SMP) * 2;     // 55552
    cudaFuncSetAttribute(tcn_mma_kernel,
                         cudaFuncAttributeMaxDynamicSharedMemorySize, tcn_smem);
    cudaFuncSetAttribute(scores_mma_kernel,
                         cudaFuncAttributeMaxDynamicSharedMemorySize, gem_smem);
    cudaFuncSetAttribute(xa_mma_kernel,
                         cudaFuncAttributeMaxDynamicSharedMemorySize, gem_smem);
    cudaFuncSetAttribute(conv_mma_kernel<0>,
                         cudaFuncAttributeMaxDynamicSharedMemorySize, conv0_smem);
    cudaFuncSetAttribute(conv_mma_kernel<1>,
                         cudaFuncAttributeMaxDynamicSharedMemorySize, conv1_smem);
    cudaFuncSetAttribute(ygemm_mma_kernel,
                         cudaFuncAttributeMaxDynamicSharedMemorySize, ygemm_smem);

    pack_kernel<<<128, 256>>>(wa, ba, wb, bb, wd, bd, cres_w, cres_b,
                              rt_w, rt_b, gcn_bn, cres_bn, tcn_bn, rt_bn,
                              tcn_w, tcn_b);
    xsplit_kernel<<<32768, 256>>>(x);
    conv_mma_kernel<0><<<dim3(512, 2, 8), 256, conv0_smem>>>();
    conv_mma_kernel<1><<<dim3(512, 2, 8), 256, conv1_smem>>>();
    scores_mma_kernel<<<dim3(2, 2, 48), 256, gem_smem>>>();
    softmax_kernel<<<24, 1024>>>(mat_adj, adj_w);
    xa_mma_kernel<<<dim3(2, 2, 1536), 256, gem_smem>>>();
    ygemm_mma_kernel<<<dim3(512, 1, 8), 256, ygemm_smem>>>();
    gcnT_kernel<<<dim3(4, 256, 8), 256>>>();
    tcn_mma_kernel<<<dim3(2, 256, 8), 256, tcn_smem>>>(out);
}

// round 12
// speedup vs baseline: 5.6911x; 1.1250x over previous
#include <cuda_runtime.h>
#include <cuda_fp16.h>
#include <math.h>
#include <stdint.h>

// ---------------------------------------------------------------------------
// Problem dims: N=8, C=64, COUT=128, T=V=256, S=3, IC=32, P=T*V=65536
// ---------------------------------------------------------------------------
#define PP 65536
#define SMP 136

__device__ __forceinline__ uint32_t smem_u32(const void* p) {
    uint32_t a;
    asm("{ .reg .u64 t; cvta.to.shared.u64 t, %1; cvt.u32.u64 %0, t; }"
        : "=r"(a) : "l"(p));
    return a;
}
__device__ __forceinline__ void ldsm_x4(uint32_t* r, uint32_t addr) {
    asm volatile("ldmatrix.sync.aligned.m8n8.x4.shared.b16 {%0,%1,%2,%3}, [%4];"
                 : "=r"(r[0]), "=r"(r[1]), "=r"(r[2]), "=r"(r[3]) : "r"(addr));
}
__device__ __forceinline__ void ldsm_x4_t(uint32_t* r, uint32_t addr) {
    asm volatile("ldmatrix.sync.aligned.m8n8.x4.trans.shared.b16 {%0,%1,%2,%3}, [%4];"
                 : "=r"(r[0]), "=r"(r[1]), "=r"(r[2]), "=r"(r[3]) : "r"(addr));
}
__device__ __forceinline__ void mma_f16(float* d, const uint32_t* a, const uint32_t* b) {
    asm volatile(
        "mma.sync.aligned.m16n8k16.row.col.f32.f16.f16.f32 "
        "{%0,%1,%2,%3}, {%4,%5,%6,%7}, {%8,%9}, {%0,%1,%2,%3};"
        : "+f"(d[0]), "+f"(d[1]), "+f"(d[2]), "+f"(d[3])
        : "r"(a[0]), "r"(a[1]), "r"(a[2]), "r"(a[3]), "r"(b[0]), "r"(b[1]));
}
__device__ __forceinline__ void hsplit(float v, __half& h, __half& l) {
    h = __float2half_rn(v);
    l = __float2half_rn(v - __half2float(h));
}
#define CP_ASYNC(dst, src) \
    asm volatile("cp.async.cg.shared.global [%0], [%1], 16;" :: "r"(dst), "l"(src))
#define CP_COMMIT() asm volatile("cp.async.commit_group;")
#define CP_WAIT(N)  asm volatile("cp.async.wait_group %0;" :: "n"(N))

// ------------------------- packed parameters -------------------------------
__device__ __half g_Wabh[256 * 64];        // single (y-path)
__device__ float g_Bab[256];
__device__ __half g_Wcrth[256 * 64];       // hi/lo (precision path)
__device__ __half g_Wcrtl[256 * 64];
__device__ float g_Bcrt[256];
__device__ __half g_Wdh[128 * 192];        // single
__device__ float g_Bd[128];
__device__ float g_bnp[1024];              // sg,hg, sc,hc, st,ht2, sr,hr
__device__ __half g_W9h[9 * 128 * 128];    // [k9][o][c] hi
__device__ __half g_W9l[9 * 128 * 128];    // lo

// ------------------------- scratch buffers ---------------------------------
__device__ __half g_abh[134217728];  // [n][256][PP] embeds (fp16 single)
__device__ __half g_xh[33554432];    // x fp16 single
__device__ __half g_adh[1572864];    // adapt fp16
__device__ float g_adapt[1572864];   // scores partial kh=0
__device__ float g_adapt2[1572864];  // scores partial kh=1
__device__ __half g_xab[100663296];  // xa out fp16
__device__ __half g_crt16[134217728]; // (cres | rt) fp16
__device__ __half g_gT[67108864];    // [n][h][w][c] gcn fp16 single

// ---------------------------------------------------------------------------
__global__ void pack_kernel(const float* __restrict__ wa, const float* __restrict__ ba,
                            const float* __restrict__ wb, const float* __restrict__ bb,
                            const float* __restrict__ wd, const float* __restrict__ bd,
                            const float* __restrict__ cres_w, const float* __restrict__ cres_b,
                            const float* __restrict__ rt_w, const float* __restrict__ rt_b,
                            const float* __restrict__ gcn_bn, const float* __restrict__ cres_bn,
                            const float* __restrict__ tcn_bn, const float* __restrict__ rt_bn,
                            const float* __restrict__ tcn_w, const float* __restrict__ tcn_b)
{
    int tid = blockIdx.x * blockDim.x + threadIdx.x;
    int nth = gridDim.x * blockDim.x;
    for (int idx = tid; idx < 256 * 64; idx += nth) {
        int o = idx >> 6, c = idx & 63;
        int i = o >> 6, sub = o & 63;
        float v = 0.f;
        if (o < 192) v = (sub < 32) ? wa[(i * 32 + sub) * 64 + c]
                                    : wb[(i * 32 + sub - 32) * 64 + c];
        g_Wabh[idx] = __float2half_rn(v);
    }
    for (int o = tid; o < 256; o += nth) {
        int i = o >> 6, sub = o & 63;
        float v = 0.f;
        if (o < 192) v = (sub < 32) ? ba[i * 32 + sub] : bb[i * 32 + sub - 32];
        g_Bab[o] = v;
    }
    for (int idx = tid; idx < 256 * 64; idx += nth) {
        int o = idx >> 6, c = idx & 63;
        float v = (o < 128) ? cres_w[o * 64 + c] : rt_w[(o - 128) * 64 + c];
        __half h, l;
        hsplit(v, h, l);
        g_Wcrth[idx] = h; g_Wcrtl[idx] = l;
    }
    for (int o = tid; o < 256; o += nth)
        g_Bcrt[o] = (o < 128) ? cres_b[o] : rt_b[o - 128];
    for (int idx = tid; idx < 128 * 192; idx += nth) {
        int o = idx / 192, k = idx - o * 192;
        int i = k >> 6, c = k & 63;
        g_Wdh[idx] = __float2half_rn(wd[(i * 128 + o) * 64 + c]);
    }
    for (int o = tid; o < 128; o += nth)
        g_Bd[o] = bd[o] + bd[128 + o] + bd[256 + o];
    for (int idx = tid; idx < 9 * 128 * 128; idx += nth) {
        int k9 = idx >> 14;
        int rem = idx & 16383;
        int o = rem >> 7, c = rem & 127;
        float v = tcn_w[o * 1152 + c * 9 + k9];
        __half h, l;
        hsplit(v, h, l);
        g_W9h[idx] = h; g_W9l[idx] = l;
    }
    for (int o = tid; o < 128; o += nth) {
        float g, b, m, v, s;
        g = gcn_bn[o]; b = gcn_bn[128 + o]; m = gcn_bn[256 + o]; v = gcn_bn[384 + o];
        s = g * rsqrtf(v + 1e-5f);
        g_bnp[o] = s; g_bnp[128 + o] = b - m * s;
        g = cres_bn[o]; b = cres_bn[128 + o]; m = cres_bn[256 + o]; v = cres_bn[384 + o];
        s = g * rsqrtf(v + 1e-5f);
        g_bnp[256 + o] = s; g_bnp[384 + o] = b - m * s;
        g = tcn_bn[o]; b = tcn_bn[128 + o]; m = tcn_bn[256 + o]; v = tcn_bn[384 + o];
        s = g * rsqrtf(v + 1e-5f);
        g_bnp[512 + o] = s; g_bnp[640 + o] = (tcn_b[o] - m) * s + b;
        g = rt_bn[o]; b = rt_bn[128 + o]; m = rt_bn[256 + o]; v = rt_bn[384 + o];
        s = g * rsqrtf(v + 1e-5f);
        g_bnp[768 + o] = s; g_bnp[896 + o] = b - m * s;
    }
}

// ---------------------------------------------------------------------------
__global__ __launch_bounds__(256) void xsplit_kernel(const float* __restrict__ x)
{
    size_t i = (size_t)blockIdx.x * 256 + threadIdx.x;   // 8388608 float4
    float4 v = ((const float4*)x)[i];
    __half2 ph0, ph1;
    ph0.x = __float2half_rn(v.x); ph0.y = __float2half_rn(v.y);
    ph1.x = __float2half_rn(v.z); ph1.y = __float2half_rn(v.w);
    *(__half2*)(g_xh + i * 4) = ph0;
    *(__half2*)(g_xh + i * 4 + 2) = ph1;
}

// ---------------------------------------------------------------------------
// conv1x1 via MMA. K=64.  MODE 0: 1-term, out fp16 embeds.
// MODE 1: 2-term (W hi/lo, x single), out fp16 crt.
// ---------------------------------------------------------------------------
#define APITCH 72
template <int MODE>
__global__ __launch_bounds__(256) void conv_mma_kernel()
{
    extern __shared__ __align__(16) __half sm[];
    __half* sAh = sm;                                  // 128 x 72
    __half* sAl = sm + 128 * APITCH;                   // MODE1 only
    __half* sBh = sm + (MODE ? 2 : 1) * 128 * APITCH;  // 64 x 136

    int pBlk = blockIdx.x << 7;
    int oBlk = blockIdx.y << 7;
    int n    = blockIdx.z;
    int tid  = threadIdx.x;
    int warp = tid >> 5, lane = tid & 31;
    int warpO = warp & 3, warpW = warp >> 2;

    const __half* Wh = MODE ? g_Wcrth : g_Wabh;

    float d[2][8][4];
#pragma unroll
    for (int a = 0; a < 2; a++)
#pragma unroll
        for (int bq = 0; bq < 8; bq++)
#pragma unroll
            for (int k = 0; k < 4; k++) d[a][bq][k] = 0.f;

#pragma unroll
    for (int t = 0; t < 4; t++) {
        int idx = tid + t * 256;
        int r = idx >> 3, c8 = idx & 7;
        int doff = r * APITCH + (c8 << 3);
        *(uint4*)(sAh + doff) = *(const uint4*)(Wh + (oBlk + r) * 64 + (c8 << 3));
        if (MODE)
            *(uint4*)(sAl + doff) = *(const uint4*)(g_Wcrtl + (oBlk + r) * 64 + (c8 << 3));
    }
#pragma unroll
    for (int t = 0; t < 4; t++) {
        int idx = tid + t * 256;
        int r = idx >> 4, c8 = idx & 15;
        int doff = r * SMP + (c8 << 3);
        *(uint4*)(sBh + doff) = *(const uint4*)(g_xh + ((size_t)n * 64 + r) * PP + pBlk + (c8 << 3));
    }
    __syncthreads();

    uint32_t uAh = smem_u32(sAh), uAl = smem_u32(sAl);
    uint32_t uBh = smem_u32(sBh);
    int aRow = warpO * 32 + (lane & 15);
    int aColSel = (lane >> 4) << 3;
    int bRowT = lane & 15;
    int bColT = (lane >> 4) << 3;

#pragma unroll
    for (int kc = 0; kc < 4; kc++) {
        int k16 = kc << 4;
        uint32_t ah[2][4], al[2][4];
#pragma unroll
        for (int mt = 0; mt < 2; mt++) {
            uint32_t off = (uint32_t)(((aRow + mt * 16) * APITCH + k16 + aColSel) << 1);
            ldsm_x4(ah[mt], uAh + off);
            if (MODE) ldsm_x4(al[mt], uAl + off);
        }
        uint32_t b2[8][2];
#pragma unroll
        for (int ntp = 0; ntp < 4; ntp++) {
            int sCol = warpW * 64 + ntp * 16 + bColT;
            uint32_t off = (uint32_t)(((k16 + bRowT) * SMP + sCol) << 1);
            ldsm_x4_t(&b2[2 * ntp][0], uBh + off);
        }
#pragma unroll
        for (int mt = 0; mt < 2; mt++)
#pragma unroll
            for (int nt = 0; nt < 8; nt++) {
                mma_f16(d[mt][nt], ah[mt], b2[nt]);
                if (MODE) mma_f16(d[mt][nt], al[mt], b2[nt]);
            }
    }

#pragma unroll
    for (int mt = 0; mt < 2; mt++) {
        int o0 = oBlk + warpO * 32 + mt * 16 + (lane >> 2);
#pragma unroll
        for (int half = 0; half < 2; half++) {
            int o = o0 + half * 8;
            float bi = MODE ? g_Bcrt[o] : g_Bab[o];
            size_t base = ((size_t)n * 256 + o) * PP + pBlk;
#pragma unroll
            for (int nt = 0; nt < 8; nt++) {
                int p = warpW * 64 + nt * 8 + ((lane & 3) << 1);
                float v0 = d[mt][nt][half * 2 + 0] + bi;
                float v1 = d[mt][nt][half * 2 + 1] + bi;
                __half2 pk;
                pk.x = __float2half_rn(v0);
                pk.y = __float2half_rn(v1);
                if (MODE) *(__half2*)(g_crt16 + base + p) = pk;
                else      *(__half2*)(g_abh + base + p) = pk;
            }
        }
    }
}

// ---------------------------------------------------------------------------
// scores via mma (1-term), split-K=2 over c. Block 128(t) x 128(s).
// ---------------------------------------------------------------------------
__global__ __launch_bounds__(256) void scores_mma_kernel()
{
    extern __shared__ __align__(16) __half sm[];
    __half* sA = sm;
    __half* sB = sm + 128 * SMP;

    int kh = blockIdx.z & 1, b = blockIdx.z >> 1;
    int i = b >> 3, n = b & 7;
    int sBlk = blockIdx.x << 7, tBlk = blockIdx.y << 7;
    size_t aOff = ((size_t)n * 256 + i * 64) * PP;
    size_t bOff = aOff + (size_t)32 * PP;

    int tid = threadIdx.x;
    int warp = tid >> 5, lane = tid & 31;
    int warpO = warp & 3, warpW = warp >> 2;

    float d[2][8][4];
#pragma unroll
    for (int a = 0; a < 2; a++)
#pragma unroll
        for (int bq = 0; bq < 8; bq++)
#pragma unroll
            for (int k = 0; k < 4; k++) d[a][bq][k] = 0.f;

    uint32_t uA = smem_u32(sA), uB = smem_u32(sB);
    int aRow = warpO * 32 + (lane & 15);
    int aColSel = (lane >> 4) << 3;
    int bRowP = warpW * 64 + (lane & 7) + ((lane >> 4) << 3);
    int bColP = ((lane >> 3) & 1) << 3;

    int c0 = kh << 4;
    for (int c = c0; c < c0 + 16; c++) {
        const __half* aH = g_abh + aOff + (size_t)c * PP;
        const __half* bH = g_abh + bOff + (size_t)c * PP;
#pragma unroll 1
        for (int vh = 0; vh < 2; vh++) {
            int v0 = vh << 7;
            __syncthreads();
#pragma unroll
            for (int t = 0; t < 8; t++) {
                int idx = tid + t * 256;
                int r = idx >> 4, c8 = idx & 15;
                int doff = r * SMP + (c8 << 3);
                *(uint4*)(sA + doff) = *(const uint4*)(aH + (size_t)(tBlk + r) * 256 + v0 + (c8 << 3));
                *(uint4*)(sB + doff) = *(const uint4*)(bH + (size_t)(sBlk + r) * 256 + v0 + (c8 << 3));
            }
            __syncthreads();
#pragma unroll
            for (int kc = 0; kc < 8; kc++) {
                int k16 = kc << 4;
                uint32_t a4[2][4];
#pragma unroll
                for (int mt = 0; mt < 2; mt++) {
                    uint32_t off = (uint32_t)(((aRow + mt * 16) * SMP + k16 + aColSel) << 1);
                    ldsm_x4(a4[mt], uA + off);
                }
                uint32_t b2[8][2];
#pragma unroll
                for (int ntp = 0; ntp < 4; ntp++) {
                    uint32_t off = (uint32_t)(((bRowP + ntp * 16) * SMP + k16 + bColP) << 1);
                    ldsm_x4(&b2[2 * ntp][0], uB + off);
                }
#pragma unroll
                for (int mt = 0; mt < 2; mt++)
#pragma unroll
                    for (int nt = 0; nt < 8; nt++)
                        mma_f16(d[mt][nt], a4[mt], b2[nt]);
            }
        }
    }

    float* dst = (kh ? g_adapt2 : g_adapt) + (size_t)b * PP;
    const float sc = 1.0f / 256.0f;
#pragma unroll
    for (int mt = 0; mt < 2; mt++) {
        int t0 = tBlk + warpO * 32 + mt * 16 + (lane >> 2);
#pragma unroll
        for (int half = 0; half < 2; half++) {
            int t = t0 + half * 8;
#pragma unroll
            for (int nt = 0; nt < 8; nt++) {
                int s = sBlk + warpW * 64 + nt * 8 + ((lane & 3) << 1);
                float2 ov;
                ov.x = d[mt][nt][half * 2 + 0] * sc;
                ov.y = d[mt][nt][half * 2 + 1] * sc;
                *(float2*)(dst + (size_t)t * 256 + s) = ov;
            }
        }
    }
}

// ---------------------------------------------------------------------------
__global__ __launch_bounds__(1024) void softmax_kernel(const float* __restrict__ mat_adj,
                                                       const float* __restrict__ adj_w)
{
    int b = blockIdx.x;
    int i = b >> 3;
    const float* p1 = g_adapt + (size_t)b * PP;
    const float* p2 = g_adapt2 + (size_t)b * PP;
    int s = threadIdx.x & 255, tq = threadIdx.x >> 8;
    __shared__ float red[4][256];
    int t0 = tq << 6, t1 = t0 + 64;
    float m = -1e30f;
    for (int t = t0; t < t1; t++) {
        int idx = t * 256 + s;
        m = fmaxf(m, p1[idx] + p2[idx]);
    }
    red[tq][s] = m;
    __syncthreads();
    m = fmaxf(fmaxf(red[0][s], red[1][s]), fmaxf(red[2][s], red[3][s]));
    __syncthreads();
    float sum = 0.f;
    for (int t = t0; t < t1; t++) {
        int idx = t * 256 + s;
        sum += expf(p1[idx] + p2[idx] - m);
    }
    red[tq][s] = sum;
    __syncthreads();
    sum = red[0][s] + red[1][s] + red[2][s] + red[3][s];
    float inv = 1.f / sum;
    const float* A1 = mat_adj + (size_t)i * PP;
    const float* A2 = adj_w + (size_t)i * PP;
    __half* dh = g_adh + (size_t)b * PP;
    for (int t = t0; t < t1; t++) {
        int idx = t * 256 + s;
        float e = expf(p1[idx] + p2[idx] - m) * inv;
        dh[idx] = __float2half_rn(A1[idx] + A2[idx] + e);
    }
}

// ---------------------------------------------------------------------------
// xa via mma (1-term), trans ldsm both operands; B paired; output fp16.
// ---------------------------------------------------------------------------
__global__ __launch_bounds__(256) void xa_mma_kernel()
{
    extern __shared__ __align__(16) __half sm[];
    __half* sA = sm;
    __half* sB = sm + 128 * SMP;

    int b2i = blockIdx.z;
    int c = b2i & 63, bn = b2i >> 6;
    int n = bn & 7;
    int sBlk = blockIdx.x << 7, vBlk = blockIdx.y << 7;
    const __half* xH = g_xh + ((size_t)n * 64 + c) * PP;
    const __half* aH = g_adh + (size_t)bn * PP;

    int tid = threadIdx.x;
    int warp = tid >> 5, lane = tid & 31;
    int warpV = warp & 3, warpS = warp >> 2;

    float d[2][8][4];
#pragma unroll
    for (int a = 0; a < 2; a++)
#pragma unroll
        for (int bq = 0; bq < 8; bq++)
#pragma unroll
            for (int k = 0; k < 4; k++) d[a][bq][k] = 0.f;

    uint32_t uA = smem_u32(sA), uB = smem_u32(sB);
    int tRowA = (lane & 7) + ((lane & 16) >> 1);
    int vColA = ((lane >> 3) & 1) << 3;
    int bRowT = lane & 15;
    int bColT = (lane >> 4) << 3;

#pragma unroll 1
    for (int th = 0; th < 2; th++) {
        int t0 = th << 7;
        __syncthreads();
#pragma unroll
        for (int t = 0; t < 8; t++) {
            int idx = tid + t * 256;
            int r = idx >> 4, c8 = idx & 15;
            int doff = r * SMP + (c8 << 3);
            *(uint4*)(sA + doff) = *(const uint4*)(xH + (size_t)(t0 + r) * 256 + vBlk + (c8 << 3));
            *(uint4*)(sB + doff) = *(const uint4*)(aH + (size_t)(t0 + r) * 256 + sBlk + (c8 << 3));
        }
        __syncthreads();
#pragma unroll
        for (int kc = 0; kc < 8; kc++) {
            int k16 = kc << 4;
            uint32_t a4[2][4];
#pragma unroll
            for (int mt = 0; mt < 2; mt++) {
                int vCol = warpV * 32 + mt * 16 + vColA;
                uint32_t off = (uint32_t)(((k16 + tRowA) * SMP + vCol) << 1);
                ldsm_x4_t(a4[mt], uA + off);
            }
            uint32_t b2[8][2];
#pragma unroll
            for (int ntp = 0; ntp < 4; ntp++) {
                int sCol = warpS * 64 + ntp * 16 + bColT;
                uint32_t off = (uint32_t)(((k16 + bRowT) * SMP + sCol) << 1);
                ldsm_x4_t(&b2[2 * ntp][0], uB + off);
            }
#pragma unroll
            for (int mt = 0; mt < 2; mt++)
#pragma unroll
                for (int nt = 0; nt < 8; nt++)
                    mma_f16(d[mt][nt], a4[mt], b2[nt]);
        }
    }

    __half* op = g_xab + (size_t)b2i * PP;
#pragma unroll
    for (int mt = 0; mt < 2; mt++) {
        int v0 = vBlk + warpV * 32 + mt * 16 + (lane >> 2);
#pragma unroll
        for (int half = 0; half < 2; half++) {
            int v = v0 + half * 8;
#pragma unroll
            for (int nt = 0; nt < 8; nt++) {
                int s = sBlk + warpS * 64 + nt * 8 + ((lane & 3) << 1);
                __half2 pk;
                pk.x = __float2half_rn(d[mt][nt][half * 2 + 0]);
                pk.y = __float2half_rn(d[mt][nt][half * 2 + 1]);
                *(__half2*)(op + (size_t)v * 256 + s) = pk;
            }
        }
    }
}

// ---------------------------------------------------------------------------
// y GEMM via mma (1-term) with FUSED gcn epilogue:
// gT[n][p][c] = relu(bn_g(y + Bd) + bn_c(cres)), fp16 channel-last.
// M=128(o), K=192, p-tile 128.  Eliminates g_y and the gcnT kernel.
// ---------------------------------------------------------------------------
#define YPITCH 200
__global__ __launch_bounds__(256) void ygemm_mma_kernel()
{
    extern __shared__ __align__(16) __half sm[];
    __half* sA = sm;                   // 128 x 200 (mainloop)
    __half* sB = sm + 128 * YPITCH;    // 16 x 136 (mainloop)
    __half* sC = sm;                   // 128(o) x 136(p)  (epilogue, aliases sA)
    __half* sT = sm + 128 * SMP;       // 128(p) x 136(c)  (epilogue)

    int pBlk = blockIdx.x << 7;
    int n    = blockIdx.z;
    int tid  = threadIdx.x;
    int warp = tid >> 5, lane = tid & 31;
    int warpO = warp & 3, warpW = warp >> 2;

    float d[2][8][4];
#pragma unroll
    for (int a = 0; a < 2; a++)
#pragma unroll
        for (int bq = 0; bq < 8; bq++)
#pragma unroll
            for (int k = 0; k < 4; k++) d[a][bq][k] = 0.f;

#pragma unroll
    for (int t = 0; t < 12; t++) {
        int idx = tid + t * 256;
        int r = idx / 24, c8 = idx - r * 24;
        *(uint4*)(sA + r * YPITCH + (c8 << 3)) = *(const uint4*)(g_Wdh + r * 192 + (c8 << 3));
    }

    uint32_t uA = smem_u32(sA), uB = smem_u32(sB);
    int aRow = warpO * 32 + (lane & 15);
    int aColSel = (lane >> 4) << 3;
    int bRowT = lane & 15;
    int bColT = (lane >> 4) << 3;

    for (int kc = 0; kc < 12; kc++) {
        if (kc) __syncthreads();
        {
            int r = tid >> 4, c8 = tid & 15;
            int k = (kc << 4) + r;
            int i = k >> 6, cc = k & 63;
            *(uint4*)(sB + r * SMP + (c8 << 3)) =
                *(const uint4*)(g_xab + (size_t)((i << 9) + (n << 6) + cc) * PP + pBlk + (c8 << 3));
        }
        __syncthreads();
        int k16 = kc << 4;
        uint32_t a4[2][4];
#pragma unroll
        for (int mt = 0; mt < 2; mt++) {
            uint32_t off = (uint32_t)(((aRow + mt * 16) * YPITCH + k16 + aColSel) << 1);
            ldsm_x4(a4[mt], uA + off);
        }
        uint32_t b2[8][2];
#pragma unroll
        for (int ntp = 0; ntp < 4; ntp++) {
            int sCol = warpW * 64 + ntp * 16 + bColT;
            uint32_t off = (uint32_t)((bRowT * SMP + sCol) << 1);
            ldsm_x4_t(&b2[2 * ntp][0], uB + off);
        }
#pragma unroll
        for (int mt = 0; mt < 2; mt++)
#pragma unroll
            for (int nt = 0; nt < 8; nt++)
                mma_f16(d[mt][nt], a4[mt], b2[nt]);
    }

    // ---- fused gcn epilogue ----
    __syncthreads();
    // cooperative load of cres tile (128 o x 128 p) into sC
#pragma unroll
    for (int t = 0; t < 8; t++) {
        int idx = tid + t * 256;
        int r = idx >> 4, c8 = idx & 15;
        *(uint4*)(sC + r * SMP + (c8 << 3)) =
            *(const uint4*)(g_crt16 + ((size_t)(n * 256) + r) * PP + pBlk + (c8 << 3));
    }
    __syncthreads();
    // compute gcn, write transposed into sT[p][c]
#pragma unroll
    for (int mt = 0; mt < 2; mt++) {
        int o0 = warpO * 32 + mt * 16 + (lane >> 2);
#pragma unroll
        for (int half = 0; half < 2; half++) {
            int o = o0 + half * 8;
            float bi = g_Bd[o];
            float sg = g_bnp[o], hg = g_bnp[128 + o];
            float sc = g_bnp[256 + o], hc = g_bnp[384 + o];
#pragma unroll
            for (int nt = 0; nt < 8; nt++) {
                int p = warpW * 64 + nt * 8 + ((lane & 3) << 1);
                __half2 cv = *(const __half2*)(sC + o * SMP + p);
                float y0 = d[mt][nt][half * 2 + 0] + bi;
                float y1 = d[mt][nt][half * 2 + 1] + bi;
                float g0 = fmaxf(y0 * sg + hg + __half2float(cv.x) * sc + hc, 0.f);
                float g1 = fmaxf(y1 * sg + hg + __half2float(cv.y) * sc + hc, 0.f);
                sT[p * SMP + o] = __float2half_rn(g0);
                sT[(p + 1) * SMP + o] = __float2half_rn(g1);
            }
        }
    }
    __syncthreads();
    // write channel-last gT
#pragma unroll
    for (int t = 0; t < 8; t++) {
        int idx = tid + t * 256;
        int r = idx >> 4, c8 = idx & 15;
        *(uint4*)(g_gT + ((size_t)n * PP + pBlk + r) * 128 + (c8 << 3)) =
            *(const uint4*)(sT + r * SMP + (c8 << 3));
    }
}

// ---------------------------------------------------------------------------
// TCN via mma.sync fp16: A = W9 hi/lo (2 terms), B = gcn single fp16.
// cp.async double-buffered; B paired ldsm.x4.  Fused epilogue (rt fp16).
// ---------------------------------------------------------------------------
#define TSTAGE (3 * 128 * SMP)          // elems per stage (Ah | Al | B)
#define TBUF_B (128 * SMP * 2)          // bytes per operand buffer
__global__ __launch_bounds__(256) void tcn_mma_kernel(float* __restrict__ out)
{
    extern __shared__ __align__(16) __half sm[];

    int wBlk = blockIdx.x << 7;
    int h    = blockIdx.y;
    int n    = blockIdx.z;
    int tid  = threadIdx.x;
    int warp = tid >> 5, lane = tid & 31;
    int warpO = warp & 3, warpW = warp >> 2;

    float d[2][8][4];
#pragma unroll
    for (int i = 0; i < 2; i++)
#pragma unroll
        for (int j = 0; j < 8; j++)
#pragma unroll
            for (int k = 0; k < 4; k++) d[i][j][k] = 0.f;

    int k9L[9], nt = 0;
#pragma unroll
    for (int k9 = 0; k9 < 9; k9++) {
        int hs = h + k9 - 4;
        if ((unsigned)hs < 256u) k9L[nt++] = k9;
    }

    uint32_t uS0 = smem_u32(sm);
    uint32_t uS1 = uS0 + (uint32_t)(TSTAGE * 2);

    int fr = tid >> 4, fc8 = tid & 15;
#define TCN_FILL(base_u32, ti)                                                    \
    {                                                                             \
        int k9_ = k9L[ti];                                                        \
        int hs_ = h + k9_ - 4;                                                    \
        const __half* wh_ = g_W9h + k9_ * 16384;                                  \
        const __half* wl_ = g_W9l + k9_ * 16384;                                  \
        const __half* gb_ = g_gT + ((size_t)(n * 256 + hs_) * 256 + wBlk) * 128;  \
        _Pragma("unroll")                                                         \
        for (int t_ = 0; t_ < 8; t_++) {                                          \
            int r_ = fr + t_ * 16;                                                \
            uint32_t doff = (uint32_t)((r_ * SMP + (fc8 << 3)) << 1);             \
            int goff = r_ * 128 + (fc8 << 3);                                     \
            CP_ASYNC((base_u32) + doff, wh_ + goff);                              \
            CP_ASYNC((base_u32) + TBUF_B + doff, wl_ + goff);                     \
            CP_ASYNC((base_u32) + 2 * TBUF_B + doff, gb_ + goff);                 \
        }                                                                         \
        CP_COMMIT();                                                              \
    }

    TCN_FILL(uS0, 0)

    int aRow = warpO * 32 + (lane & 15);
    int aColSel = (lane >> 4) << 3;
    int bRowP = warpW * 64 + (lane & 7) + ((lane >> 4) << 3);
    int bColP = ((lane >> 3) & 1) << 3;

    uint32_t bases[2] = {uS0, uS1};
    int buf = 0;
    for (int it = 0; it < nt; it++) {
        if (it + 1 < nt) {
            TCN_FILL(bases[buf ^ 1], it + 1)
            CP_WAIT(1);
        } else {
            CP_WAIT(0);
        }
        __syncthreads();
        uint32_t uAh = bases[buf];
        uint32_t uAl = bases[buf] + TBUF_B;
        uint32_t uB  = bases[buf] + 2 * TBUF_B;
#pragma unroll
        for (int kc = 0; kc < 8; kc++) {
            int c0 = kc << 4;
            uint32_t ah[2][4], al[2][4];
#pragma unroll
            for (int mt = 0; mt < 2; mt++) {
                uint32_t off = (uint32_t)(((aRow + mt * 16) * SMP + c0 + aColSel) << 1);
                ldsm_x4(ah[mt], uAh + off);
                ldsm_x4(al[mt], uAl + off);
            }
            uint32_t b2[8][2];
#pragma unroll
            for (int ntp = 0; ntp < 4; ntp++) {
                uint32_t off = (uint32_t)(((bRowP + ntp * 16) * SMP + c0 + bColP) << 1);
                ldsm_x4(&b2[2 * ntp][0], uB + off);
            }
#pragma unroll
            for (int mt = 0; mt < 2; mt++)
#pragma unroll
                for (int ntt = 0; ntt < 8; ntt++) {
                    mma_f16(d[mt][ntt], ah[mt], b2[ntt]);
                    mma_f16(d[mt][ntt], al[mt], b2[ntt]);
                }
        }
        buf ^= 1;
        __syncthreads();
    }

    int oB = warpO * 32;
    int wB = wBlk + warpW * 64;
#pragma unroll
    for (int mt = 0; mt < 2; mt++) {
        int o0 = oB + mt * 16 + (lane >> 2);
#pragma unroll
        for (int half = 0; half < 2; half++) {
            int o = o0 + half * 8;
            float st = g_bnp[512 + o], ht = g_bnp[640 + o];
            float sr = g_bnp[768 + o], hr = g_bnp[896 + o];
            size_t ob = ((size_t)(n * 128 + o) * 256 + h) * 256;
            size_t rb = ((size_t)(n * 256 + 128 + o) * 256 + h) * 256;
#pragma unroll
            for (int ntt = 0; ntt < 8; ntt++) {
                int w = wB + ntt * 8 + ((lane & 3) << 1);
                __half2 rh = *(const __half2*)(g_crt16 + rb + w);
                float v0 = d[mt][ntt][half * 2 + 0];
                float v1 = d[mt][ntt][half * 2 + 1];
                float2 ov;
                ov.x = fmaxf(v0 * st + ht + __half2float(rh.x) * sr + hr, 0.f);
                ov.y = fmaxf(v1 * st + ht + __half2float(rh.y) * sr + hr, 0.f);
                *(float2*)(out + ob + w) = ov;
            }
        }
    }
}

// ---------------------------------------------------------------------------
extern "C" void kernel_launch(void* const* d_in, const int* in_sizes, int n_in,
                              void* d_out, int out_size)
{
    const float* x       = (const float*)d_in[0];
    const float* mat_adj = (const float*)d_in[1];
    const float* adj_w   = (const float*)d_in[2];
    const float* wa      = (const float*)d_in[3];
    const float* ba      = (const float*)d_in[4];
    const float* wb      = (const float*)d_in[5];
    const float* bb      = (const float*)d_in[6];
    const float* wd      = (const float*)d_in[7];
    const float* bd      = (const float*)d_in[8];
    const float* gcn_bn  = (const float*)d_in[9];
    const float* cres_w  = (const float*)d_in[10];
    const float* cres_b  = (const float*)d_in[11];
    const float* cres_bn = (const float*)d_in[12];
    const float* tcn_w   = (const float*)d_in[13];
    const float* tcn_b   = (const float*)d_in[14];
    const float* tcn_bn  = (const float*)d_in[15];
    const float* rt_w    = (const float*)d_in[16];
    const float* rt_b    = (const float*)d_in[17];
    const float* rt_bn   = (const float*)d_in[18];
    float* out = (float*)d_out;

    const int tcn_smem   = 2 * TSTAGE * 2;                    // 208896
    const int gem_smem   = 2 * 128 * SMP * 2;                 // 69632
    const int conv0_smem = (128 * APITCH + 64 * SMP) * 2;     // 35840
    const int conv1_smem = (2 * 128 * APITCH + 64 * SMP) * 2; // 54272
    const int ygemm_smem = 2 * 128 * SMP * 2;                 // 69632 (max of phases)
    cudaFuncSetAttribute(tcn_mma_kernel,
                         cudaFuncAttributeMaxDynamicSharedMemorySize, tcn_smem);
    cudaFuncSetAttribute(scores_mma_kernel,
                         cudaFuncAttributeMaxDynamicSharedMemorySize, gem_smem);
    cudaFuncSetAttribute(xa_mma_kernel,
                         cudaFuncAttributeMaxDynamicSharedMemorySize, gem_smem);
    cudaFuncSetAttribute(conv_mma_kernel<0>,
                         cudaFuncAttributeMaxDynamicSharedMemorySize, conv0_smem);
    cudaFuncSetAttribute(conv_mma_kernel<1>,
                         cudaFuncAttributeMaxDynamicSharedMemorySize, conv1_smem);
    cudaFuncSetAttribute(ygemm_mma_kernel,
                         cudaFuncAttributeMaxDynamicSharedMemorySize, ygemm_smem);

    pack_kernel<<<128, 256>>>(wa, ba, wb, bb, wd, bd, cres_w, cres_b,
                              rt_w, rt_b, gcn_bn, cres_bn, tcn_bn, rt_bn,
                              tcn_w, tcn_b);
    xsplit_kernel<<<32768, 256>>>(x);
    conv_mma_kernel<0><<<dim3(512, 2, 8), 256, conv0_smem>>>();
    conv_mma_kernel<1><<<dim3(512, 2, 8), 256, conv1_smem>>>();
    scores_mma_kernel<<<dim3(2, 2, 48), 256, gem_smem>>>();
    softmax_kernel<<<24, 1024>>>(mat_adj, adj_w);
    xa_mma_kernel<<<dim3(2, 2, 1536), 256, gem_smem>>>();
    ygemm_mma_kernel<<<dim3(512, 1, 8), 256, ygemm_smem>>>();
    tcn_mma_kernel<<<dim3(2, 256, 8), 256, tcn_smem>>>(out);
}

// round 13
// speedup vs baseline: 7.4205x; 1.3039x over previous
#include <cuda_runtime.h>
#include <cuda_fp16.h>
#include <math.h>
#include <stdint.h>

// ---------------------------------------------------------------------------
// Problem dims: N=8, C=64, COUT=128, T=V=256, S=3, IC=32, P=T*V=65536
// ---------------------------------------------------------------------------
#define PP 65536
#define SMP 136

__device__ __forceinline__ uint32_t smem_u32(const void* p) {
    uint32_t a;
    asm("{ .reg .u64 t; cvta.to.shared.u64 t, %1; cvt.u32.u64 %0, t; }"
        : "=r"(a) : "l"(p));
    return a;
}
__device__ __forceinline__ void ldsm_x4(uint32_t* r, uint32_t addr) {
    asm volatile("ldmatrix.sync.aligned.m8n8.x4.shared.b16 {%0,%1,%2,%3}, [%4];"
                 : "=r"(r[0]), "=r"(r[1]), "=r"(r[2]), "=r"(r[3]) : "r"(addr));
}
__device__ __forceinline__ void ldsm_x4_t(uint32_t* r, uint32_t addr) {
    asm volatile("ldmatrix.sync.aligned.m8n8.x4.trans.shared.b16 {%0,%1,%2,%3}, [%4];"
                 : "=r"(r[0]), "=r"(r[1]), "=r"(r[2]), "=r"(r[3]) : "r"(addr));
}
__device__ __forceinline__ void mma_f16(float* d, const uint32_t* a, const uint32_t* b) {
    asm volatile(
        "mma.sync.aligned.m16n8k16.row.col.f32.f16.f16.f32 "
        "{%0,%1,%2,%3}, {%4,%5,%6,%7}, {%8,%9}, {%0,%1,%2,%3};"
        : "+f"(d[0]), "+f"(d[1]), "+f"(d[2]), "+f"(d[3])
        : "r"(a[0]), "r"(a[1]), "r"(a[2]), "r"(a[3]), "r"(b[0]), "r"(b[1]));
}
__device__ __forceinline__ void hsplit(float v, __half& h, __half& l) {
    h = __float2half_rn(v);
    l = __float2half_rn(v - __half2float(h));
}
#define CP_ASYNC(dst, src) \
    asm volatile("cp.async.cg.shared.global [%0], [%1], 16;" :: "r"(dst), "l"(src))
#define CP_COMMIT() asm volatile("cp.async.commit_group;")
#define CP_WAIT(N)  asm volatile("cp.async.wait_group %0;" :: "n"(N))

// ------------------------- packed parameters -------------------------------
__device__ __half g_Wabh[256 * 64];        // single (y-path)
__device__ float g_Bab[256];
__device__ __half g_Wcrth[256 * 64];       // hi/lo (precision path)
__device__ __half g_Wcrtl[256 * 64];
__device__ float g_Bcrt[256];
__device__ __half g_Wdh[128 * 192];        // single
__device__ float g_Bd[128];
__device__ float g_bnp[1024];              // sg,hg, sc,hc, st,ht2, sr,hr
__device__ __half g_W9h[9 * 128 * 128];    // [k9][o][c] fp16 single

// ------------------------- scratch buffers ---------------------------------
__device__ __half g_abh[134217728];  // [n][256][PP] embeds (fp16 single)
__device__ __half g_xh[33554432];    // x fp16 single
__device__ __half g_adh[1572864];    // adapt fp16
__device__ float g_adapt[1572864];   // scores partial kh=0
__device__ float g_adapt2[1572864];  // scores partial kh=1
__device__ __half g_xab[100663296];  // xa out fp16
__device__ __half g_crt16[134217728]; // (cres | rt) fp16
__device__ __half g_gT[67108864];    // [n][h][w][c] gcn fp16 single

// ---------------------------------------------------------------------------
__global__ void pack_kernel(const float* __restrict__ wa, const float* __restrict__ ba,
                            const float* __restrict__ wb, const float* __restrict__ bb,
                            const float* __restrict__ wd, const float* __restrict__ bd,
                            const float* __restrict__ cres_w, const float* __restrict__ cres_b,
                            const float* __restrict__ rt_w, const float* __restrict__ rt_b,
                            const float* __restrict__ gcn_bn, const float* __restrict__ cres_bn,
                            const float* __restrict__ tcn_bn, const float* __restrict__ rt_bn,
                            const float* __restrict__ tcn_w, const float* __restrict__ tcn_b)
{
    int tid = blockIdx.x * blockDim.x + threadIdx.x;
    int nth = gridDim.x * blockDim.x;
    for (int idx = tid; idx < 256 * 64; idx += nth) {
        int o = idx >> 6, c = idx & 63;
        int i = o >> 6, sub = o & 63;
        float v = 0.f;
        if (o < 192) v = (sub < 32) ? wa[(i * 32 + sub) * 64 + c]
                                    : wb[(i * 32 + sub - 32) * 64 + c];
        g_Wabh[idx] = __float2half_rn(v);
    }
    for (int o = tid; o < 256; o += nth) {
        int i = o >> 6, sub = o & 63;
        float v = 0.f;
        if (o < 192) v = (sub < 32) ? ba[i * 32 + sub] : bb[i * 32 + sub - 32];
        g_Bab[o] = v;
    }
    for (int idx = tid; idx < 256 * 64; idx += nth) {
        int o = idx >> 6, c = idx & 63;
        float v = (o < 128) ? cres_w[o * 64 + c] : rt_w[(o - 128) * 64 + c];
        __half h, l;
        hsplit(v, h, l);
        g_Wcrth[idx] = h; g_Wcrtl[idx] = l;
    }
    for (int o = tid; o < 256; o += nth)
        g_Bcrt[o] = (o < 128) ? cres_b[o] : rt_b[o - 128];
    for (int idx = tid; idx < 128 * 192; idx += nth) {
        int o = idx / 192, k = idx - o * 192;
        int i = k >> 6, c = k & 63;
        g_Wdh[idx] = __float2half_rn(wd[(i * 128 + o) * 64 + c]);
    }
    for (int o = tid; o < 128; o += nth)
        g_Bd[o] = bd[o] + bd[128 + o] + bd[256 + o];
    for (int idx = tid; idx < 9 * 128 * 128; idx += nth) {
        int k9 = idx >> 14;
        int rem = idx & 16383;
        int o = rem >> 7, c = rem & 127;
        g_W9h[idx] = __float2half_rn(tcn_w[o * 1152 + c * 9 + k9]);
    }
    for (int o = tid; o < 128; o += nth) {
        float g, b, m, v, s;
        g = gcn_bn[o]; b = gcn_bn[128 + o]; m = gcn_bn[256 + o]; v = gcn_bn[384 + o];
        s = g * rsqrtf(v + 1e-5f);
        g_bnp[o] = s; g_bnp[128 + o] = b - m * s;
        g = cres_bn[o]; b = cres_bn[128 + o]; m = cres_bn[256 + o]; v = cres_bn[384 + o];
        s = g * rsqrtf(v + 1e-5f);
        g_bnp[256 + o] = s; g_bnp[384 + o] = b - m * s;
        g = tcn_bn[o]; b = tcn_bn[128 + o]; m = tcn_bn[256 + o]; v = tcn_bn[384 + o];
        s = g * rsqrtf(v + 1e-5f);
        g_bnp[512 + o] = s; g_bnp[640 + o] = (tcn_b[o] - m) * s + b;
        g = rt_bn[o]; b = rt_bn[128 + o]; m = rt_bn[256 + o]; v = rt_bn[384 + o];
        s = g * rsqrtf(v + 1e-5f);
        g_bnp[768 + o] = s; g_bnp[896 + o] = b - m * s;
    }
}

// ---------------------------------------------------------------------------
__global__ __launch_bounds__(256) void xsplit_kernel(const float* __restrict__ x)
{
    size_t i = (size_t)blockIdx.x * 256 + threadIdx.x;   // 8388608 float4
    float4 v = ((const float4*)x)[i];
    __half2 ph0, ph1;
    ph0.x = __float2half_rn(v.x); ph0.y = __float2half_rn(v.y);
    ph1.x = __float2half_rn(v.z); ph1.y = __float2half_rn(v.w);
    *(__half2*)(g_xh + i * 4) = ph0;
    *(__half2*)(g_xh + i * 4 + 2) = ph1;
}

// ---------------------------------------------------------------------------
// conv1x1 via MMA. K=64.  MODE 0: 1-term, out fp16 embeds.
// MODE 1: 2-term (W hi/lo, x single), out fp16 crt.
// ---------------------------------------------------------------------------
#define APITCH 72
template <int MODE>
__global__ __launch_bounds__(256) void conv_mma_kernel()
{
    extern __shared__ __align__(16) __half sm[];
    __half* sAh = sm;                                  // 128 x 72
    __half* sAl = sm + 128 * APITCH;                   // MODE1 only
    __half* sBh = sm + (MODE ? 2 : 1) * 128 * APITCH;  // 64 x 136

    int pBlk = blockIdx.x << 7;
    int oBlk = blockIdx.y << 7;
    int n    = blockIdx.z;
    int tid  = threadIdx.x;
    int warp = tid >> 5, lane = tid & 31;
    int warpO = warp & 3, warpW = warp >> 2;

    const __half* Wh = MODE ? g_Wcrth : g_Wabh;

    float d[2][8][4];
#pragma unroll
    for (int a = 0; a < 2; a++)
#pragma unroll
        for (int bq = 0; bq < 8; bq++)
#pragma unroll
            for (int k = 0; k < 4; k++) d[a][bq][k] = 0.f;

#pragma unroll
    for (int t = 0; t < 4; t++) {
        int idx = tid + t * 256;
        int r = idx >> 3, c8 = idx & 7;
        int doff = r * APITCH + (c8 << 3);
        *(uint4*)(sAh + doff) = *(const uint4*)(Wh + (oBlk + r) * 64 + (c8 << 3));
        if (MODE)
            *(uint4*)(sAl + doff) = *(const uint4*)(g_Wcrtl + (oBlk + r) * 64 + (c8 << 3));
    }
#pragma unroll
    for (int t = 0; t < 4; t++) {
        int idx = tid + t * 256;
        int r = idx >> 4, c8 = idx & 15;
        int doff = r * SMP + (c8 << 3);
        *(uint4*)(sBh + doff) = *(const uint4*)(g_xh + ((size_t)n * 64 + r) * PP + pBlk + (c8 << 3));
    }
    __syncthreads();

    uint32_t uAh = smem_u32(sAh), uAl = smem_u32(sAl);
    uint32_t uBh = smem_u32(sBh);
    int aRow = warpO * 32 + (lane & 15);
    int aColSel = (lane >> 4) << 3;
    int bRowT = lane & 15;
    int bColT = (lane >> 4) << 3;

#pragma unroll
    for (int kc = 0; kc < 4; kc++) {
        int k16 = kc << 4;
        uint32_t ah[2][4], al[2][4];
#pragma unroll
        for (int mt = 0; mt < 2; mt++) {
            uint32_t off = (uint32_t)(((aRow + mt * 16) * APITCH + k16 + aColSel) << 1);
            ldsm_x4(ah[mt], uAh + off);
            if (MODE) ldsm_x4(al[mt], uAl + off);
        }
        uint32_t b2[8][2];
#pragma unroll
        for (int ntp = 0; ntp < 4; ntp++) {
            int sCol = warpW * 64 + ntp * 16 + bColT;
            uint32_t off = (uint32_t)(((k16 + bRowT) * SMP + sCol) << 1);
            ldsm_x4_t(&b2[2 * ntp][0], uBh + off);
        }
#pragma unroll
        for (int mt = 0; mt < 2; mt++)
#pragma unroll
            for (int nt = 0; nt < 8; nt++) {
                mma_f16(d[mt][nt], ah[mt], b2[nt]);
                if (MODE) mma_f16(d[mt][nt], al[mt], b2[nt]);
            }
    }

#pragma unroll
    for (int mt = 0; mt < 2; mt++) {
        int o0 = oBlk + warpO * 32 + mt * 16 + (lane >> 2);
#pragma unroll
        for (int half = 0; half < 2; half++) {
            int o = o0 + half * 8;
            float bi = MODE ? g_Bcrt[o] : g_Bab[o];
            size_t base = ((size_t)n * 256 + o) * PP + pBlk;
#pragma unroll
            for (int nt = 0; nt < 8; nt++) {
                int p = warpW * 64 + nt * 8 + ((lane & 3) << 1);
                float v0 = d[mt][nt][half * 2 + 0] + bi;
                float v1 = d[mt][nt][half * 2 + 1] + bi;
                __half2 pk;
                pk.x = __float2half_rn(v0);
                pk.y = __float2half_rn(v1);
                if (MODE) *(__half2*)(g_crt16 + base + p) = pk;
                else      *(__half2*)(g_abh + base + p) = pk;
            }
        }
    }
}

// ---------------------------------------------------------------------------
// scores via mma (1-term), split-K=2 over c. Block 128(t) x 128(s).
// ---------------------------------------------------------------------------
__global__ __launch_bounds__(256) void scores_mma_kernel()
{
    extern __shared__ __align__(16) __half sm[];
    __half* sA = sm;
    __half* sB = sm + 128 * SMP;

    int kh = blockIdx.z & 1, b = blockIdx.z >> 1;
    int i = b >> 3, n = b & 7;
    int sBlk = blockIdx.x << 7, tBlk = blockIdx.y << 7;
    size_t aOff = ((size_t)n * 256 + i * 64) * PP;
    size_t bOff = aOff + (size_t)32 * PP;

    int tid = threadIdx.x;
    int warp = tid >> 5, lane = tid & 31;
    int warpO = warp & 3, warpW = warp >> 2;

    float d[2][8][4];
#pragma unroll
    for (int a = 0; a < 2; a++)
#pragma unroll
        for (int bq = 0; bq < 8; bq++)
#pragma unroll
            for (int k = 0; k < 4; k++) d[a][bq][k] = 0.f;

    uint32_t uA = smem_u32(sA), uB = smem_u32(sB);
    int aRow = warpO * 32 + (lane & 15);
    int aColSel = (lane >> 4) << 3;
    int bRowP = warpW * 64 + (lane & 7) + ((lane >> 4) << 3);
    int bColP = ((lane >> 3) & 1) << 3;

    int c0 = kh << 4;
    for (int c = c0; c < c0 + 16; c++) {
        const __half* aH = g_abh + aOff + (size_t)c * PP;
        const __half* bH = g_abh + bOff + (size_t)c * PP;
#pragma unroll 1
        for (int vh = 0; vh < 2; vh++) {
            int v0 = vh << 7;
            __syncthreads();
#pragma unroll
            for (int t = 0; t < 8; t++) {
                int idx = tid + t * 256;
                int r = idx >> 4, c8 = idx & 15;
                int doff = r * SMP + (c8 << 3);
                *(uint4*)(sA + doff) = *(const uint4*)(aH + (size_t)(tBlk + r) * 256 + v0 + (c8 << 3));
                *(uint4*)(sB + doff) = *(const uint4*)(bH + (size_t)(sBlk + r) * 256 + v0 + (c8 << 3));
            }
            __syncthreads();
#pragma unroll
            for (int kc = 0; kc < 8; kc++) {
                int k16 = kc << 4;
                uint32_t a4[2][4];
#pragma unroll
                for (int mt = 0; mt < 2; mt++) {
                    uint32_t off = (uint32_t)(((aRow + mt * 16) * SMP + k16 + aColSel) << 1);
                    ldsm_x4(a4[mt], uA + off);
                }
                uint32_t b2[8][2];
#pragma unroll
                for (int ntp = 0; ntp < 4; ntp++) {
                    uint32_t off = (uint32_t)(((bRowP + ntp * 16) * SMP + k16 + bColP) << 1);
                    ldsm_x4(&b2[2 * ntp][0], uB + off);
                }
#pragma unroll
                for (int mt = 0; mt < 2; mt++)
#pragma unroll
                    for (int nt = 0; nt < 8; nt++)
                        mma_f16(d[mt][nt], a4[mt], b2[nt]);
            }
        }
    }

    float* dst = (kh ? g_adapt2 : g_adapt) + (size_t)b * PP;
    const float sc = 1.0f / 256.0f;
#pragma unroll
    for (int mt = 0; mt < 2; mt++) {
        int t0 = tBlk + warpO * 32 + mt * 16 + (lane >> 2);
#pragma unroll
        for (int half = 0; half < 2; half++) {
            int t = t0 + half * 8;
#pragma unroll
            for (int nt = 0; nt < 8; nt++) {
                int s = sBlk + warpW * 64 + nt * 8 + ((lane & 3) << 1);
                float2 ov;
                ov.x = d[mt][nt][half * 2 + 0] * sc;
                ov.y = d[mt][nt][half * 2 + 1] * sc;
                *(float2*)(dst + (size_t)t * 256 + s) = ov;
            }
        }
    }
}

// ---------------------------------------------------------------------------
// softmax over t per column s; grid (24, 4): each block owns 64 s-columns.
// 1024 threads = 64 s x 16 t-quarters of 16.
// ---------------------------------------------------------------------------
__global__ __launch_bounds__(1024) void softmax_kernel(const float* __restrict__ mat_adj,
                                                       const float* __restrict__ adj_w)
{
    int b = blockIdx.x;
    int i = b >> 3;
    int sq = blockIdx.y;
    const float* p1 = g_adapt + (size_t)b * PP;
    const float* p2 = g_adapt2 + (size_t)b * PP;
    int sl = threadIdx.x & 63, tq = threadIdx.x >> 6;   // 16 t-quarters
    int s = (sq << 6) + sl;
    __shared__ float red[16][64];
    int t0 = tq << 4, t1 = t0 + 16;
    float m = -1e30f;
    for (int t = t0; t < t1; t++) {
        int idx = t * 256 + s;
        m = fmaxf(m, p1[idx] + p2[idx]);
    }
    red[tq][sl] = m;
    __syncthreads();
    m = -1e30f;
#pragma unroll
    for (int j = 0; j < 16; j++) m = fmaxf(m, red[j][sl]);
    __syncthreads();
    float sum = 0.f;
    for (int t = t0; t < t1; t++) {
        int idx = t * 256 + s;
        sum += expf(p1[idx] + p2[idx] - m);
    }
    red[tq][sl] = sum;
    __syncthreads();
    sum = 0.f;
#pragma unroll
    for (int j = 0; j < 16; j++) sum += red[j][sl];
    float inv = 1.f / sum;
    const float* A1 = mat_adj + (size_t)i * PP;
    const float* A2 = adj_w + (size_t)i * PP;
    __half* dh = g_adh + (size_t)b * PP;
    for (int t = t0; t < t1; t++) {
        int idx = t * 256 + s;
        float e = expf(p1[idx] + p2[idx] - m) * inv;
        dh[idx] = __float2half_rn(A1[idx] + A2[idx] + e);
    }
}

// ---------------------------------------------------------------------------
// xa via mma (1-term), c-chunked: one block does 4 channels at (bn,vBlk,sBlk),
// caching both adapt t-halves in smem.  Output fp16.
// ---------------------------------------------------------------------------
__global__ __launch_bounds__(256) void xa_mma_kernel()
{
    extern __shared__ __align__(16) __half sm[];
    __half* sAd = sm;                     // [2][128 x 136] adapt panels
    __half* sX  = sm + 2 * 128 * SMP;     // 128 x 136 x panel (reused)

    int z = blockIdx.z;
    int bn = z >> 4;
    int c0 = (z & 15) << 2;
    int n = bn & 7;
    int sBlk = blockIdx.x << 7, vBlk = blockIdx.y << 7;
    const __half* aH = g_adh + (size_t)bn * PP;

    int tid = threadIdx.x;
    int warp = tid >> 5, lane = tid & 31;
    int warpV = warp & 3, warpS = warp >> 2;

    // load adapt panels (both t-halves) once
#pragma unroll
    for (int th = 0; th < 2; th++)
#pragma unroll
        for (int t = 0; t < 8; t++) {
            int idx = tid + t * 256;
            int r = idx >> 4, c8 = idx & 15;
            *(uint4*)(sAd + th * 128 * SMP + r * SMP + (c8 << 3)) =
                *(const uint4*)(aH + (size_t)((th << 7) + r) * 256 + sBlk + (c8 << 3));
        }

    uint32_t uAd = smem_u32(sAd), uX = smem_u32(sX);
    int tRowA = (lane & 7) + ((lane & 16) >> 1);
    int vColA = ((lane >> 3) & 1) << 3;
    int bRowT = lane & 15;
    int bColT = (lane >> 4) << 3;

    for (int cc = 0; cc < 4; cc++) {
        int c = c0 + cc;
        const __half* xH = g_xh + ((size_t)n * 64 + c) * PP;
        float d[2][8][4];
#pragma unroll
        for (int a = 0; a < 2; a++)
#pragma unroll
            for (int bq = 0; bq < 8; bq++)
#pragma unroll
                for (int k = 0; k < 4; k++) d[a][bq][k] = 0.f;

#pragma unroll 1
        for (int th = 0; th < 2; th++) {
            __syncthreads();   // protects sX overwrite & (cc=0,th=0) adapt readiness
#pragma unroll
            for (int t = 0; t < 8; t++) {
                int idx = tid + t * 256;
                int r = idx >> 4, c8 = idx & 15;
                *(uint4*)(sX + r * SMP + (c8 << 3)) =
                    *(const uint4*)(xH + (size_t)((th << 7) + r) * 256 + vBlk + (c8 << 3));
            }
            __syncthreads();
            uint32_t uB = uAd + (uint32_t)(th * 128 * SMP * 2);
#pragma unroll
            for (int kc = 0; kc < 8; kc++) {
                int k16 = kc << 4;
                uint32_t a4[2][4];
#pragma unroll
                for (int mt = 0; mt < 2; mt++) {
                    int vCol = warpV * 32 + mt * 16 + vColA;
                    uint32_t off = (uint32_t)(((k16 + tRowA) * SMP + vCol) << 1);
                    ldsm_x4_t(a4[mt], uX + off);
                }
                uint32_t b2[8][2];
#pragma unroll
                for (int ntp = 0; ntp < 4; ntp++) {
                    int sCol = warpS * 64 + ntp * 16 + bColT;
                    uint32_t off = (uint32_t)(((k16 + bRowT) * SMP + sCol) << 1);
                    ldsm_x4_t(&b2[2 * ntp][0], uB + off);
                }
#pragma unroll
                for (int mt = 0; mt < 2; mt++)
#pragma unroll
                    for (int nt = 0; nt < 8; nt++)
                        mma_f16(d[mt][nt], a4[mt], b2[nt]);
            }
        }

        __half* op = g_xab + (size_t)(bn * 64 + c) * PP;
#pragma unroll
        for (int mt = 0; mt < 2; mt++) {
            int v0 = vBlk + warpV * 32 + mt * 16 + (lane >> 2);
#pragma unroll
            for (int half = 0; half < 2; half++) {
                int v = v0 + half * 8;
#pragma unroll
                for (int nt = 0; nt < 8; nt++) {
                    int s = sBlk + warpS * 64 + nt * 8 + ((lane & 3) << 1);
                    __half2 pk;
                    pk.x = __float2half_rn(d[mt][nt][half * 2 + 0]);
                    pk.y = __float2half_rn(d[mt][nt][half * 2 + 1]);
                    *(__half2*)(op + (size_t)v * 256 + s) = pk;
                }
            }
        }
    }
}

// ---------------------------------------------------------------------------
// y GEMM via mma (1-term) with FUSED gcn epilogue -> gT fp16 channel-last.
// ---------------------------------------------------------------------------
#define YPITCH 200
__global__ __launch_bounds__(256) void ygemm_mma_kernel()
{
    extern __shared__ __align__(16) __half sm[];
    __half* sA = sm;                   // 128 x 200 (mainloop)
    __half* sB = sm + 128 * YPITCH;    // 16 x 136 (mainloop)
    __half* sC = sm;                   // 128(o) x 136(p)  (epilogue, aliases sA)
    __half* sT = sm + 128 * SMP;       // 128(p) x 136(c)  (epilogue)

    int pBlk = blockIdx.x << 7;
    int n    = blockIdx.z;
    int tid  = threadIdx.x;
    int warp = tid >> 5, lane = tid & 31;
    int warpO = warp & 3, warpW = warp >> 2;

    float d[2][8][4];
#pragma unroll
    for (int a = 0; a < 2; a++)
#pragma unroll
        for (int bq = 0; bq < 8; bq++)
#pragma unroll
            for (int k = 0; k < 4; k++) d[a][bq][k] = 0.f;

#pragma unroll
    for (int t = 0; t < 12; t++) {
        int idx = tid + t * 256;
        int r = idx / 24, c8 = idx - r * 24;
        *(uint4*)(sA + r * YPITCH + (c8 << 3)) = *(const uint4*)(g_Wdh + r * 192 + (c8 << 3));
    }

    uint32_t uA = smem_u32(sA), uB = smem_u32(sB);
    int aRow = warpO * 32 + (lane & 15);
    int aColSel = (lane >> 4) << 3;
    int bRowT = lane & 15;
    int bColT = (lane >> 4) << 3;

    for (int kc = 0; kc < 12; kc++) {
        if (kc) __syncthreads();
        {
            int r = tid >> 4, c8 = tid & 15;
            int k = (kc << 4) + r;
            int i = k >> 6, cc = k & 63;
            *(uint4*)(sB + r * SMP + (c8 << 3)) =
                *(const uint4*)(g_xab + (size_t)((i << 9) + (n << 6) + cc) * PP + pBlk + (c8 << 3));
        }
        __syncthreads();
        int k16 = kc << 4;
        uint32_t a4[2][4];
#pragma unroll
        for (int mt = 0; mt < 2; mt++) {
            uint32_t off = (uint32_t)(((aRow + mt * 16) * YPITCH + k16 + aColSel) << 1);
            ldsm_x4(a4[mt], uA + off);
        }
        uint32_t b2[8][2];
#pragma unroll
        for (int ntp = 0; ntp < 4; ntp++) {
            int sCol = warpW * 64 + ntp * 16 + bColT;
            uint32_t off = (uint32_t)((bRowT * SMP + sCol) << 1);
            ldsm_x4_t(&b2[2 * ntp][0], uB + off);
        }
#pragma unroll
        for (int mt = 0; mt < 2; mt++)
#pragma unroll
            for (int nt = 0; nt < 8; nt++)
                mma_f16(d[mt][nt], a4[mt], b2[nt]);
    }

    // ---- fused gcn epilogue ----
    __syncthreads();
#pragma unroll
    for (int t = 0; t < 8; t++) {
        int idx = tid + t * 256;
        int r = idx >> 4, c8 = idx & 15;
        *(uint4*)(sC + r * SMP + (c8 << 3)) =
            *(const uint4*)(g_crt16 + ((size_t)(n * 256) + r) * PP + pBlk + (c8 << 3));
    }
    __syncthreads();
#pragma unroll
    for (int mt = 0; mt < 2; mt++) {
        int o0 = warpO * 32 + mt * 16 + (lane >> 2);
#pragma unroll
        for (int half = 0; half < 2; half++) {
            int o = o0 + half * 8;
            float bi = g_Bd[o];
            float sg = g_bnp[o], hg = g_bnp[128 + o];
            float sc = g_bnp[256 + o], hc = g_bnp[384 + o];
#pragma unroll
            for (int nt = 0; nt < 8; nt++) {
                int p = warpW * 64 + nt * 8 + ((lane & 3) << 1);
                __half2 cv = *(const __half2*)(sC + o * SMP + p);
                float y0 = d[mt][nt][half * 2 + 0] + bi;
                float y1 = d[mt][nt][half * 2 + 1] + bi;
                float g0 = fmaxf(y0 * sg + hg + __half2float(cv.x) * sc + hc, 0.f);
                float g1 = fmaxf(y1 * sg + hg + __half2float(cv.y) * sc + hc, 0.f);
                sT[p * SMP + o] = __float2half_rn(g0);
                sT[(p + 1) * SMP + o] = __float2half_rn(g1);
            }
        }
    }
    __syncthreads();
#pragma unroll
    for (int t = 0; t < 8; t++) {
        int idx = tid + t * 256;
        int r = idx >> 4, c8 = idx & 15;
        *(uint4*)(g_gT + ((size_t)n * PP + pBlk + r) * 128 + (c8 << 3)) =
            *(const uint4*)(sT + r * SMP + (c8 << 3));
    }
}

// ---------------------------------------------------------------------------
// TCN via mma.sync fp16 single-term: A = W9 fp16, B = gcn fp16.
// cp.async double-buffered; B paired ldsm.x4.  Fused epilogue (rt fp16).
// ---------------------------------------------------------------------------
#define TSTAGE (2 * 128 * SMP)          // elems per stage (A | B)
#define TBUF_B (128 * SMP * 2)          // bytes per operand buffer
__global__ __launch_bounds__(256) void tcn_mma_kernel(float* __restrict__ out)
{
    extern __shared__ __align__(16) __half sm[];

    int wBlk = blockIdx.x << 7;
    int h    = blockIdx.y;
    int n    = blockIdx.z;
    int tid  = threadIdx.x;
    int warp = tid >> 5, lane = tid & 31;
    int warpO = warp & 3, warpW = warp >> 2;

    float d[2][8][4];
#pragma unroll
    for (int i = 0; i < 2; i++)
#pragma unroll
        for (int j = 0; j < 8; j++)
#pragma unroll
            for (int k = 0; k < 4; k++) d[i][j][k] = 0.f;

    int k9L[9], nt = 0;
#pragma unroll
    for (int k9 = 0; k9 < 9; k9++) {
        int hs = h + k9 - 4;
        if ((unsigned)hs < 256u) k9L[nt++] = k9;
    }

    uint32_t uS0 = smem_u32(sm);
    uint32_t uS1 = uS0 + (uint32_t)(TSTAGE * 2);

    int fr = tid >> 4, fc8 = tid & 15;
#define TCN_FILL(base_u32, ti)                                                    \
    {                                                                             \
        int k9_ = k9L[ti];                                                        \
        int hs_ = h + k9_ - 4;                                                    \
        const __half* wh_ = g_W9h + k9_ * 16384;                                  \
        const __half* gb_ = g_gT + ((size_t)(n * 256 + hs_) * 256 + wBlk) * 128;  \
        _Pragma("unroll")                                                         \
        for (int t_ = 0; t_ < 8; t_++) {                                          \
            int r_ = fr + t_ * 16;                                                \
            uint32_t doff = (uint32_t)((r_ * SMP + (fc8 << 3)) << 1);             \
            int goff = r_ * 128 + (fc8 << 3);                                     \
            CP_ASYNC((base_u32) + doff, wh_ + goff);                              \
            CP_ASYNC((base_u32) + TBUF_B + doff, gb_ + goff);                     \
        }                                                                         \
        CP_COMMIT();                                                              \
    }

    TCN_FILL(uS0, 0)

    int aRow = warpO * 32 + (lane & 15);
    int aColSel = (lane >> 4) << 3;
    int bRowP = warpW * 64 + (lane & 7) + ((lane >> 4) << 3);
    int bColP = ((lane >> 3) & 1) << 3;

    uint32_t bases[2] = {uS0, uS1};
    int buf = 0;
    for (int it = 0; it < nt; it++) {
        if (it + 1 < nt) {
            TCN_FILL(bases[buf ^ 1], it + 1)
            CP_WAIT(1);
        } else {
            CP_WAIT(0);
        }
        __syncthreads();
        uint32_t uA = bases[buf];
        uint32_t uB = bases[buf] + TBUF_B;
#pragma unroll
        for (int kc = 0; kc < 8; kc++) {
            int c0 = kc << 4;
            uint32_t ah[2][4];
#pragma unroll
            for (int mt = 0; mt < 2; mt++) {
                uint32_t off = (uint32_t)(((aRow + mt * 16) * SMP + c0 + aColSel) << 1);
                ldsm_x4(ah[mt], uA + off);
            }
            uint32_t b2[8][2];
#pragma unroll
            for (int ntp = 0; ntp < 4; ntp++) {
                uint32_t off = (uint32_t)(((bRowP + ntp * 16) * SMP + c0 + bColP) << 1);
                ldsm_x4(&b2[2 * ntp][0], uB + off);
            }
#pragma unroll
            for (int mt = 0; mt < 2; mt++)
#pragma unroll
                for (int ntt = 0; ntt < 8; ntt++)
                    mma_f16(d[mt][ntt], ah[mt], b2[ntt]);
        }
        buf ^= 1;
        __syncthreads();
    }

    int oB = warpO * 32;
    int wB = wBlk + warpW * 64;
#pragma unroll
    for (int mt = 0; mt < 2; mt++) {
        int o0 = oB + mt * 16 + (lane >> 2);
#pragma unroll
        for (int half = 0; half < 2; half++) {
            int o = o0 + half * 8;
            float st = g_bnp[512 + o], ht = g_bnp[640 + o];
            float sr = g_bnp[768 + o], hr = g_bnp[896 + o];
            size_t ob = ((size_t)(n * 128 + o) * 256 + h) * 256;
            size_t rb = ((size_t)(n * 256 + 128 + o) * 256 + h) * 256;
#pragma unroll
            for (int ntt = 0; ntt < 8; ntt++) {
                int w = wB + ntt * 8 + ((lane & 3) << 1);
                __half2 rh = *(const __half2*)(g_crt16 + rb + w);
                float v0 = d[mt][ntt][half * 2 + 0];
                float v1 = d[mt][ntt][half * 2 + 1];
                float2 ov;
                ov.x = fmaxf(v0 * st + ht + __half2float(rh.x) * sr + hr, 0.f);
                ov.y = fmaxf(v1 * st + ht + __half2float(rh.y) * sr + hr, 0.f);
                *(float2*)(out + ob + w) = ov;
            }
        }
    }
}

// ---------------------------------------------------------------------------
extern "C" void kernel_launch(void* const* d_in, const int* in_sizes, int n_in,
                              void* d_out, int out_size)
{
    const float* x       = (const float*)d_in[0];
    const float* mat_adj = (const float*)d_in[1];
    const float* adj_w   = (const float*)d_in[2];
    const float* wa      = (const float*)d_in[3];
    const float* ba      = (const float*)d_in[4];
    const float* wb      = (const float*)d_in[5];
    const float* bb      = (const float*)d_in[6];
    const float* wd      = (const float*)d_in[7];
    const float* bd      = (const float*)d_in[8];
    const float* gcn_bn  = (const float*)d_in[9];
    const float* cres_w  = (const float*)d_in[10];
    const float* cres_b  = (const float*)d_in[11];
    const float* cres_bn = (const float*)d_in[12];
    const float* tcn_w   = (const float*)d_in[13];
    const float* tcn_b   = (const float*)d_in[14];
    const float* tcn_bn  = (const float*)d_in[15];
    const float* rt_w    = (const float*)d_in[16];
    const float* rt_b    = (const float*)d_in[17];
    const float* rt_bn   = (const float*)d_in[18];
    float* out = (float*)d_out;

    const int tcn_smem   = 2 * TSTAGE * 2;                    // 139264
    const int gem_smem   = 2 * 128 * SMP * 2;                 // 69632
    const int xa_smem    = 3 * 128 * SMP * 2;                 // 104448
    const int conv0_smem = (128 * APITCH + 64 * SMP) * 2;     // 35840
    const int conv1_smem = (2 * 128 * APITCH + 64 * SMP) * 2; // 54272
    const int ygemm_smem = 2 * 128 * SMP * 2;                 // 69632
    cudaFuncSetAttribute(tcn_mma_kernel,
                         cudaFuncAttributeMaxDynamicSharedMemorySize, tcn_smem);
    cudaFuncSetAttribute(scores_mma_kernel,
                         cudaFuncAttributeMaxDynamicSharedMemorySize, gem_smem);
    cudaFuncSetAttribute(xa_mma_kernel,
                         cudaFuncAttributeMaxDynamicSharedMemorySize, xa_smem);
    cudaFuncSetAttribute(conv_mma_kernel<0>,
                         cudaFuncAttributeMaxDynamicSharedMemorySize, conv0_smem);
    cudaFuncSetAttribute(conv_mma_kernel<1>,
                         cudaFuncAttributeMaxDynamicSharedMemorySize, conv1_smem);
    cudaFuncSetAttribute(ygemm_mma_kernel,
                         cudaFuncAttributeMaxDynamicSharedMemorySize, ygemm_smem);

    pack_kernel<<<128, 256>>>(wa, ba, wb, bb, wd, bd, cres_w, cres_b,
                              rt_w, rt_b, gcn_bn, cres_bn, tcn_bn, rt_bn,
                              tcn_w, tcn_b);
    xsplit_kernel<<<32768, 256>>>(x);
    conv_mma_kernel<0><<<dim3(512, 2, 8), 256, conv0_smem>>>();
    conv_mma_kernel<1><<<dim3(512, 2, 8), 256, conv1_smem>>>();
    scores_mma_kernel<<<dim3(2, 2, 48), 256, gem_smem>>>();
    softmax_kernel<<<dim3(24, 4), 1024>>>(mat_adj, adj_w);
    xa_mma_kernel<<<dim3(2, 2, 384), 256, xa_smem>>>();
    ygemm_mma_kernel<<<dim3(512, 1, 8), 256, ygemm_smem>>>();
    tcn_mma_kernel<<<dim3(2, 256, 8), 256, tcn_smem>>>(out);
}